// round 8
// baseline (speedup 1.0000x reference)
#include <cuda_runtime.h>
#include <math.h>

typedef unsigned long long ull;

#define BDIM 2
#define NTOT 1024
#define PLEN 768
#define LLEN 256
#define KDIM 128
#define HDIM 32

constexpr int PP = 132;                          // pair-major row pitch (floats)
constexpr int NT_LP = BDIM * PLEN * 4;           // 6144
constexpr int NT_LL_SLOW = BDIM * LLEN * 4;      // 2048
constexpr int NTILES_SLOW = NT_LL_SLOW + NT_LP;  // 8192
constexpr int NT_LL_FAST = BDIM * 640;           // 1280 (256 diag + 384 upper per b)
constexpr int NTILES_FAST = NT_LL_FAST + NT_LP;  // 7424

// shared memory layout (float offsets)
constexpr int OFF_OW1  = 0;                      // 16384: OW1P[kp][2c+{0,1}]
constexpr int OFF_OW2  = 16384;                  // 4096:  OW2P[kp][2h+{0,1}]
constexpr int OFF_VW2  = 20480;                  // 4096
constexpr int OFF_TVV  = 24576;                  // 96: T[d][h] = vw1@vw2
constexpr int OFF_VW1  = 24672;                  // 384
constexpr int OFF_VB1  = 25056;                  // 128
constexpr int OFF_OB1  = 25184;                  // 128
constexpr int OFF_MEAN = 25312;                  // 128
constexpr int OFF_ISTD = 25440;                  // 128
constexpr int OFF_COEF = 25568;                  // 128
constexpr int OFF_B2   = 25696;                  // 32
constexpr int OFF_FLAG = 25728;                  // 4 ints: [0] vbzero, [1] sym
constexpr int OFF_DLM4 = 25732;                  // 256: {d0,d1,d2,x0} per m
constexpr int OFF_GP   = 25988;                  // 8448: G / H1 pair-major [kp][2m]
constexpr int OFF_VP1  = OFF_GP + 64 * PP;       // 34436
// scratch: pitch 36 floats (144B) -> m*36 + h0 (h0 multiple of 8) is 16B-aligned
constexpr int SCP = 36;
constexpr int SCSTRIDE = 64 * SCP;               // 2304
constexpr int OFF_SCR  = OFF_VP1 + 64 * PP;      // 42884 (16B-aligned: 171536B)
constexpr int SMEM_FLOATS = OFF_SCR + 3 * SCSTRIDE;  // 49796
constexpr int SMEM_BYTES  = SMEM_FLOATS * 4;         // 199184

__device__ __forceinline__ ull ffma2(ull a, ull b, ull c) {
    ull d; asm("fma.rn.f32x2 %0,%1,%2,%3;" : "=l"(d) : "l"(a), "l"(b), "l"(c)); return d;
}
__device__ __forceinline__ float2 u2f2(ull v) {
    float2 f; asm("mov.b64 {%0,%1},%2;" : "=f"(f.x), "=f"(f.y) : "l"(v)); return f;
}
__device__ __forceinline__ ull f2pack(float x, float y) {
    ull r; asm("mov.b64 %0,{%1,%2};" : "=l"(r) : "f"(x), "f"(y)); return r;
}
__device__ __forceinline__ float hadd2(ull v) { float2 f = u2f2(v); return f.x + f.y; }

// exact-form gelu via Abramowitz-Stegun 7.1.26 erf (|abs err| <= 1.5e-7), branchless
__device__ __forceinline__ float fast_gelu(float x) {
    float y  = x * 0.70710678118654752f;
    float ax = fabsf(y);
    float t  = __fdividef(1.0f, fmaf(0.3275911f, ax, 1.0f));
    float p  = fmaf(t, 1.061405429f, -1.453152027f);
    p = fmaf(t, p, 1.421413741f);
    p = fmaf(t, p, -0.284496736f);
    p = fmaf(t, p, 0.254829592f);
    p *= t;
    float e = __expf(-ax * ax);
    float erfv = copysignf(fmaf(-p, e, 1.0f), y);
    return 0.5f * x * (1.0f + erfv);
}

__global__ void zero_pp_kernel(float* __restrict__ out) {
    const int q = PLEN / 4;
    size_t idx = (size_t)blockIdx.x * blockDim.x + threadIdx.x;
    size_t total = (size_t)BDIM * HDIM * PLEN * q;
    if (idx >= total) return;
    int jq = (int)(idx % q);
    size_t r = idx / q;
    int ip = (int)(r % PLEN);
    size_t bh = r / PLEN;
    size_t addr = (bh * NTOT + (LLEN + ip)) * NTOT + LLEN + 4 * jq;
    *reinterpret_cast<float4*>(out + addr) = make_float4(0.f, 0.f, 0.f, 0.f);
}

__global__ __launch_bounds__(1024, 1)
void fused_distbias_kernel(
    const float* __restrict__ pos,
    const int*   __restrict__ etype,
    const float* __restrict__ mw,
    const float* __restrict__ bw,
    const float* __restrict__ means,
    const float* __restrict__ stds,
    const float* __restrict__ ow1,
    const float* __restrict__ ob1,
    const float* __restrict__ ow2,
    const float* __restrict__ ob2,
    const float* __restrict__ vw1,
    const float* __restrict__ vb1,
    const float* __restrict__ vw2,
    const float* __restrict__ vb2,
    float* __restrict__ out,
    int nE)
{
    extern __shared__ float sm[];
    const int tid = threadIdx.x;
    int* iflags = reinterpret_cast<int*>(sm + OFF_FLAG);

    // ---- Stage weights (pair-major), once per block ----
    for (int i = tid; i < 64 * 128; i += 1024) {
        int kp = i >> 7, c = i & 127;
        sm[OFF_OW1 + kp * 256 + 2 * c]     = ow1[(2 * kp) * KDIM + c];
        sm[OFF_OW1 + kp * 256 + 2 * c + 1] = ow1[(2 * kp + 1) * KDIM + c];
    }
    for (int i = tid; i < 64 * 32; i += 1024) {
        int kp = i >> 5, h = i & 31;
        sm[OFF_OW2 + kp * 64 + 2 * h]     = ow2[(2 * kp) * HDIM + h];
        sm[OFF_OW2 + kp * 64 + 2 * h + 1] = ow2[(2 * kp + 1) * HDIM + h];
        sm[OFF_VW2 + kp * 64 + 2 * h]     = vw2[(2 * kp) * HDIM + h];
        sm[OFF_VW2 + kp * 64 + 2 * h + 1] = vw2[(2 * kp + 1) * HDIM + h];
    }
    if (tid < 3 * KDIM) sm[OFF_VW1 + tid] = vw1[tid];
    if (tid < KDIM) {
        sm[OFF_VB1 + tid] = vb1[tid];
        sm[OFF_OB1 + tid] = ob1[tid];
        float s  = fabsf(stds[tid]) + 1e-5f;
        float is = 1.0f / s;
        sm[OFF_MEAN + tid] = means[tid];
        sm[OFF_ISTD + tid] = is;
        sm[OFF_COEF + tid] = is * (1.0f / sqrtf(2.0f * 3.14159f));
    }
    if (tid < HDIM) sm[OFF_B2 + tid] = ob2[tid] + vb2[tid];
    if (tid == 0) { iflags[0] = 1; iflags[1] = 1; }
    __syncthreads();
    // flag checks
    if (tid < KDIM && vb1[tid] != 0.0f) atomicAnd(&iflags[0], 0);
    {
        float m0v = mw[0], b0v = bw[0];
        for (int i = tid; i < nE; i += 1024)
            if (mw[i] != m0v || bw[i] != b0v) atomicAnd(&iflags[1], 0);
    }
    __syncthreads();
    // T[d][h] = vw1 @ vw2
    if (tid < 96) {
        int d = tid >> 5, h = tid & 31;
        float s = 0.0f;
        for (int kp = 0; kp < 64; kp++) {
            float2 a = *reinterpret_cast<float2*>(sm + OFF_VW1 + d * 128 + 2 * kp);
            float2 w = *reinterpret_cast<float2*>(sm + OFF_VW2 + kp * 64 + 2 * h);
            s += a.x * w.x + a.y * w.y;
        }
        sm[OFF_TVV + d * 32 + h] = s;
    }
    __syncthreads();
    const int vbzero = iflags[0];
    const int fastmode = iflags[0] & iflags[1];
    const int ntiles = fastmode ? NTILES_FAST : NTILES_SLOW;

    // ---- per-thread decompositions ----
    // gaussian: m per lane (64), kp-chunk of 4 per tid>>6
    const int gm  = tid & 63;
    const int gkc = tid >> 6;
    // stage 1: warp = wm(8) x wn(4); lane = mg(4) x ng(8); thread 2m x 4c
    const int s1_lane = tid & 31, s1_w = tid >> 5;
    const int s1_wm = s1_w & 7, s1_wn = s1_w >> 3;
    const int s1_mg = s1_lane >> 3, s1_ng = s1_lane & 7;
    const int s1_m0 = s1_wm * 8 + s1_mg * 2;
    const int s1_np0 = s1_wn * 16 + s1_ng;     // col pairs np0, np0+8
    // stage 2: warp = mq(4) x hq(2) x kh(4); lane = ml(16) x hh(2); thread 1m x 8h x 16kp
    const int s2_lane = tid & 31, s2_w = tid >> 5;
    const int s2_ml = s2_lane >> 1, s2_hh = s2_lane & 1;
    const int s2_mq = s2_w & 3, s2_hq = (s2_w >> 2) & 1, s2_kh = s2_w >> 3;
    const int s2_m  = s2_mq * 16 + s2_ml;
    const int s2_h0 = s2_hq * 16 + s2_hh * 8;

    for (int t = blockIdx.x; t < ntiles; t += gridDim.x) {
        int b, rowi, j0, wrM;
        if (fastmode) {
            if (t < NT_LL_FAST) {
                b = t / 640; int r = t - b * 640;
                if (r < 256) { rowi = r; j0 = r & 192; wrM = 0; }
                else {
                    int r2 = r - 256; int pr = r2 >> 6;
                    int br = (pr < 3) ? 0 : ((pr < 5) ? 1 : 2);
                    int bc = (pr == 0) ? 1 : ((pr == 1 || pr == 3) ? 2 : 3);
                    rowi = br * 64 + (r2 & 63); j0 = bc * 64; wrM = 1;
                }
            } else {
                int u = t - NT_LL_FAST; b = u / 3072; int r = u - b * 3072;
                rowi = LLEN + (r >> 2); j0 = (r & 3) << 6; wrM = 1;
            }
        } else {
            if (t < NT_LL_SLOW) {
                b = t >> 10; int r = t & 1023;
                rowi = r >> 2; j0 = (r & 3) << 6; wrM = 0;
            } else {
                int u = t - NT_LL_SLOW; b = u / 3072; int r = u - b * 3072;
                rowi = LLEN + (r >> 2); j0 = (r & 3) << 6; wrM = 1;
            }
        }

        // ---- (M) metadata ----
        if (tid < 64) {
            int j = j0 + tid;
            const float* pj = pos + ((size_t)b * NTOT + j) * 3;
            const float* pi = pos + ((size_t)b * NTOT + rowi) * 3;
            float d0 = pj[0] - pi[0];
            float d1 = pj[1] - pi[1];
            float d2 = pj[2] - pi[2];
            float d = 1.0f / (d0 * d0 + d1 * d1 + d2 * d2 + 1.0f);
            int e = etype[((size_t)b * NTOT + rowi) * NTOT + j];
            float x0 = mw[e] * d + bw[e];
            *reinterpret_cast<float4*>(sm + OFF_DLM4 + tid * 4) =
                make_float4(d0, d1, d2, x0);
        }
        __syncthreads();   // (1)

        // ---- (G) gaussian + vector-MLP hidden ----
        {
            float4 dm = *reinterpret_cast<float4*>(sm + OFF_DLM4 + gm * 4);
            #pragma unroll
            for (int i = 0; i < 4; i++) {
                int kp = gkc * 4 + i;
                float2 mn = *reinterpret_cast<float2*>(sm + OFF_MEAN + 2 * kp);
                float2 is = *reinterpret_cast<float2*>(sm + OFF_ISTD + 2 * kp);
                float2 cf = *reinterpret_cast<float2*>(sm + OFF_COEF + 2 * kp);
                float2 w0 = *reinterpret_cast<float2*>(sm + OFF_VW1 + 2 * kp);
                float2 w1 = *reinterpret_cast<float2*>(sm + OFF_VW1 + 128 + 2 * kp);
                float2 w2 = *reinterpret_cast<float2*>(sm + OFF_VW1 + 256 + 2 * kp);
                float2 vb = *reinterpret_cast<float2*>(sm + OFF_VB1 + 2 * kp);
                float tx = (dm.w - mn.x) * is.x;
                float ty = (dm.w - mn.y) * is.y;
                float2 g = make_float2(__expf(-0.5f * tx * tx) * cf.x,
                                       __expf(-0.5f * ty * ty) * cf.y);
                float sx = dm.x * w0.x + dm.y * w1.x + dm.z * w2.x + vb.x;
                float sy = dm.x * w0.y + dm.y * w1.y + dm.z * w2.y + vb.y;
                float2 v1 = make_float2(fast_gelu(sx), fast_gelu(sy));
                *reinterpret_cast<float2*>(sm + OFF_GP  + kp * PP + 2 * gm) = g;
                *reinterpret_cast<float2*>(sm + OFF_VP1 + kp * PP + 2 * gm) = v1;
            }
        }
        __syncthreads();   // (2)

        // ---- (S1) H1 = gelu(G @ ow1 + ob1) ----
        {
            ull a00 = 0, a01 = 0, a02 = 0, a03 = 0;
            ull a10 = 0, a11 = 0, a12 = 0, a13 = 0;
            const float* gB = sm + OFF_GP + 2 * s1_m0;
            const float* wB = sm + OFF_OW1 + s1_wn * 64 + 4 * s1_ng;
            #pragma unroll 4
            for (int kp = 0; kp < 64; kp++) {
                ulonglong2 g  = *reinterpret_cast<const ulonglong2*>(gB + kp * PP);
                ulonglong2 wA = *reinterpret_cast<const ulonglong2*>(wB + kp * 256);
                ulonglong2 wC = *reinterpret_cast<const ulonglong2*>(wB + kp * 256 + 32);
                a00 = ffma2(g.x, wA.x, a00); a01 = ffma2(g.x, wA.y, a01);
                a02 = ffma2(g.x, wC.x, a02); a03 = ffma2(g.x, wC.y, a03);
                a10 = ffma2(g.y, wA.x, a10); a11 = ffma2(g.y, wA.y, a11);
                a12 = ffma2(g.y, wC.x, a12); a13 = ffma2(g.y, wC.y, a13);
            }
            __syncthreads();   // (3)
            float2 obA = *reinterpret_cast<float2*>(sm + OFF_OB1 + s1_wn * 32 + 2 * s1_ng);
            float2 obB = *reinterpret_cast<float2*>(sm + OFF_OB1 + s1_wn * 32 + 2 * s1_ng + 16);
            float2 hA0 = make_float2(fast_gelu(hadd2(a00) + obA.x),
                                     fast_gelu(hadd2(a01) + obA.y));
            float2 hB0 = make_float2(fast_gelu(hadd2(a02) + obB.x),
                                     fast_gelu(hadd2(a03) + obB.y));
            float2 hA1 = make_float2(fast_gelu(hadd2(a10) + obA.x),
                                     fast_gelu(hadd2(a11) + obA.y));
            float2 hB1 = make_float2(fast_gelu(hadd2(a12) + obB.x),
                                     fast_gelu(hadd2(a13) + obB.y));
            *reinterpret_cast<float2*>(sm + OFF_GP + s1_np0 * PP + 2 * s1_m0) = hA0;
            *reinterpret_cast<float2*>(sm + OFF_GP + (s1_np0 + 8) * PP + 2 * s1_m0) = hB0;
            *reinterpret_cast<float2*>(sm + OFF_GP + s1_np0 * PP + 2 * (s1_m0 + 1)) = hA1;
            *reinterpret_cast<float2*>(sm + OFF_GP + (s1_np0 + 8) * PP + 2 * (s1_m0 + 1)) = hB1;
        }
        __syncthreads();   // (4)

        // ---- (S2) combined contraction: R = H1@ow2 + V1@vw2 ----
        float rowv[8];
        {
            const float* hB = sm + OFF_GP  + s2_kh * 16 * PP + 2 * s2_m;
            const float* vB = sm + OFF_VP1 + s2_kh * 16 * PP + 2 * s2_m;
            const float* oB = sm + OFF_OW2 + s2_kh * 1024 + 2 * s2_h0;
            const float* wB = sm + OFF_VW2 + s2_kh * 1024 + 2 * s2_h0;
            ull R[8];
            #pragma unroll
            for (int j = 0; j < 8; j++) R[j] = 0ull;
            #pragma unroll 4
            for (int i = 0; i < 16; i++) {
                ull hp = *reinterpret_cast<const ull*>(hB + i * PP);
                ull vp = *reinterpret_cast<const ull*>(vB + i * PP);
                ulonglong2 o01 = *reinterpret_cast<const ulonglong2*>(oB + i * 64);
                ulonglong2 o23 = *reinterpret_cast<const ulonglong2*>(oB + i * 64 + 4);
                ulonglong2 o45 = *reinterpret_cast<const ulonglong2*>(oB + i * 64 + 8);
                ulonglong2 o67 = *reinterpret_cast<const ulonglong2*>(oB + i * 64 + 12);
                R[0] = ffma2(hp, o01.x, R[0]); R[1] = ffma2(hp, o01.y, R[1]);
                R[2] = ffma2(hp, o23.x, R[2]); R[3] = ffma2(hp, o23.y, R[3]);
                R[4] = ffma2(hp, o45.x, R[4]); R[5] = ffma2(hp, o45.y, R[5]);
                R[6] = ffma2(hp, o67.x, R[6]); R[7] = ffma2(hp, o67.y, R[7]);
                ulonglong2 v01 = *reinterpret_cast<const ulonglong2*>(wB + i * 64);
                ulonglong2 v23 = *reinterpret_cast<const ulonglong2*>(wB + i * 64 + 4);
                ulonglong2 v45 = *reinterpret_cast<const ulonglong2*>(wB + i * 64 + 8);
                ulonglong2 v67 = *reinterpret_cast<const ulonglong2*>(wB + i * 64 + 12);
                R[0] = ffma2(vp, v01.x, R[0]); R[1] = ffma2(vp, v01.y, R[1]);
                R[2] = ffma2(vp, v23.x, R[2]); R[3] = ffma2(vp, v23.y, R[3]);
                R[4] = ffma2(vp, v45.x, R[4]); R[5] = ffma2(vp, v45.y, R[5]);
                R[6] = ffma2(vp, v67.x, R[6]); R[7] = ffma2(vp, v67.y, R[7]);
            }
            #pragma unroll
            for (int j = 0; j < 8; j++) rowv[j] = hadd2(R[j]);
        }
        // mirror correction (identity path), computed before barrier (DLM4 still valid)
        float corr[8];
        if (wrM && vbzero && s2_kh == 0) {
            float4 dmv = *reinterpret_cast<float4*>(sm + OFF_DLM4 + s2_m * 4);
            #pragma unroll
            for (int j = 0; j < 8; j++) {
                int h = s2_h0 + j;
                corr[j] = dmv.x * sm[OFF_TVV + h]
                        + dmv.y * sm[OFF_TVV + 32 + h]
                        + dmv.z * sm[OFF_TVV + 64 + h];
            }
        }
        if (s2_kh) {
            float* sc = sm + OFF_SCR + (s2_kh - 1) * SCSTRIDE + s2_m * SCP + s2_h0;
            *reinterpret_cast<float4*>(sc)     = make_float4(rowv[0], rowv[1], rowv[2], rowv[3]);
            *reinterpret_cast<float4*>(sc + 4) = make_float4(rowv[4], rowv[5], rowv[6], rowv[7]);
        }
        __syncthreads();   // (5)
        if (s2_kh == 0) {
            #pragma unroll
            for (int p = 0; p < 3; p++) {
                const float* sc = sm + OFF_SCR + p * SCSTRIDE + s2_m * SCP + s2_h0;
                float4 r0 = *reinterpret_cast<const float4*>(sc);
                float4 r1 = *reinterpret_cast<const float4*>(sc + 4);
                rowv[0] += r0.x; rowv[1] += r0.y; rowv[2] += r0.z; rowv[3] += r0.w;
                rowv[4] += r1.x; rowv[5] += r1.y; rowv[6] += r1.z; rowv[7] += r1.w;
            }
            const size_t bh = (size_t)b * HDIM;
            #pragma unroll
            for (int j = 0; j < 8; j++) {
                int h = s2_h0 + j;
                float v = rowv[j] + sm[OFF_B2 + h];
                out[((bh + h) * NTOT + rowi) * NTOT + j0 + s2_m] = v;
                if (wrM && vbzero)
                    out[((bh + h) * NTOT + (j0 + s2_m)) * NTOT + rowi] = v - corr[j];
            }
        }

        // ---- fallback mirror path (vb1 != 0): delta = sum (gelu(-s)-v1) * vw2 ----
        if (wrM && !vbzero) {
            float dp[8];
            {
                float4 dmv = *reinterpret_cast<float4*>(sm + OFF_DLM4 + s2_m * 4);
                const float* vB = sm + OFF_VP1 + s2_kh * 16 * PP + 2 * s2_m;
                const float* wB = sm + OFF_VW2 + s2_kh * 1024 + 2 * s2_h0;
                ull D[8];
                #pragma unroll
                for (int j = 0; j < 8; j++) D[j] = 0ull;
                for (int i = 0; i < 16; i++) {
                    int kp = s2_kh * 16 + i;
                    float2 w0 = *reinterpret_cast<float2*>(sm + OFF_VW1 + 2 * kp);
                    float2 w1 = *reinterpret_cast<float2*>(sm + OFF_VW1 + 128 + 2 * kp);
                    float2 w2 = *reinterpret_cast<float2*>(sm + OFF_VW1 + 256 + 2 * kp);
                    float2 vb = *reinterpret_cast<float2*>(sm + OFF_VB1 + 2 * kp);
                    float sx = dmv.x * w0.x + dmv.y * w1.x + dmv.z * w2.x + vb.x;
                    float sy = dmv.x * w0.y + dmv.y * w1.y + dmv.z * w2.y + vb.y;
                    float2 pv = u2f2(*reinterpret_cast<const ull*>(vB + i * PP));
                    ull dq = f2pack(fast_gelu(2.0f * vb.x - sx) - pv.x,
                                    fast_gelu(2.0f * vb.y - sy) - pv.y);
                    ulonglong2 v01 = *reinterpret_cast<const ulonglong2*>(wB + i * 64);
                    ulonglong2 v23 = *reinterpret_cast<const ulonglong2*>(wB + i * 64 + 4);
                    ulonglong2 v45 = *reinterpret_cast<const ulonglong2*>(wB + i * 64 + 8);
                    ulonglong2 v67 = *reinterpret_cast<const ulonglong2*>(wB + i * 64 + 12);
                    D[0] = ffma2(dq, v01.x, D[0]); D[1] = ffma2(dq, v01.y, D[1]);
                    D[2] = ffma2(dq, v23.x, D[2]); D[3] = ffma2(dq, v23.y, D[3]);
                    D[4] = ffma2(dq, v45.x, D[4]); D[5] = ffma2(dq, v45.y, D[5]);
                    D[6] = ffma2(dq, v67.x, D[6]); D[7] = ffma2(dq, v67.y, D[7]);
                }
                #pragma unroll
                for (int j = 0; j < 8; j++) dp[j] = hadd2(D[j]);
            }
            __syncthreads();   // (6) scratch free (kh0 finished reading R partials)
            if (s2_kh) {
                float* sc = sm + OFF_SCR + (s2_kh - 1) * SCSTRIDE + s2_m * SCP + s2_h0;
                *reinterpret_cast<float4*>(sc)     = make_float4(dp[0], dp[1], dp[2], dp[3]);
                *reinterpret_cast<float4*>(sc + 4) = make_float4(dp[4], dp[5], dp[6], dp[7]);
            }
            __syncthreads();   // (7)
            if (s2_kh == 0) {
                #pragma unroll
                for (int p = 0; p < 3; p++) {
                    const float* sc = sm + OFF_SCR + p * SCSTRIDE + s2_m * SCP + s2_h0;
                    float4 r0 = *reinterpret_cast<const float4*>(sc);
                    float4 r1 = *reinterpret_cast<const float4*>(sc + 4);
                    dp[0] += r0.x; dp[1] += r0.y; dp[2] += r0.z; dp[3] += r0.w;
                    dp[4] += r1.x; dp[5] += r1.y; dp[6] += r1.z; dp[7] += r1.w;
                }
                const size_t bh = (size_t)b * HDIM;
                #pragma unroll
                for (int j = 0; j < 8; j++) {
                    int h = s2_h0 + j;
                    float v = rowv[j] + dp[j] + sm[OFF_B2 + h];
                    out[((bh + h) * NTOT + (j0 + s2_m)) * NTOT + rowi] = v;
                }
            }
        }
        // loop-around ordering: DLM4 rewritten only after barrier (1) of next tile;
        // GP/VP1 rewritten after (2); scratch rewritten after (4)/(6).
    }
}

extern "C" void kernel_launch(void* const* d_in, const int* in_sizes, int n_in,
                              void* d_out, int out_size) {
    const float* pos    = (const float*)d_in[0];
    const int*   etype  = (const int*)d_in[1];
    const float* means  = (const float*)d_in[3];
    const float* stds   = (const float*)d_in[4];
    const float* mul_w  = (const float*)d_in[5];
    const float* bias_w = (const float*)d_in[6];
    const float* ow1    = (const float*)d_in[7];
    const float* ob1    = (const float*)d_in[8];
    const float* ow2    = (const float*)d_in[9];
    const float* ob2    = (const float*)d_in[10];
    const float* vw1    = (const float*)d_in[11];
    const float* vb1    = (const float*)d_in[12];
    const float* vw2    = (const float*)d_in[13];
    const float* vb2    = (const float*)d_in[14];
    float* out = (float*)d_out;
    int nE = in_sizes[5];   // mul_w element count (E)

    cudaFuncSetAttribute(fused_distbias_kernel,
                         cudaFuncAttributeMaxDynamicSharedMemorySize, SMEM_BYTES);

    {
        size_t total = (size_t)BDIM * HDIM * PLEN * (PLEN / 4);
        int grid = (int)((total + 255) / 256);
        zero_pp_kernel<<<grid, 256>>>(out);
    }

    fused_distbias_kernel<<<148, 1024, SMEM_BYTES>>>(
        pos, etype, mul_w, bias_w, means, stds,
        ow1, ob1, ow2, ob2, vw1, vb1, vw2, vb2, out, nE);
}

// round 10
// speedup vs baseline: 1.0002x; 1.0002x over previous
#include <cuda_runtime.h>
#include <math.h>

typedef unsigned long long ull;

#define BDIM 2
#define NTOT 1024
#define PLEN 768
#define LLEN 256
#define KDIM 128
#define HDIM 32

constexpr int PP = 132;                          // pair-major row pitch (floats)
constexpr int NT_LP = BDIM * PLEN * 4;           // 6144
constexpr int NT_LL_SLOW = BDIM * LLEN * 4;      // 2048
constexpr int NTILES_SLOW = NT_LL_SLOW + NT_LP;  // 8192
constexpr int NT_LL_FAST = BDIM * 640;           // 1280 (256 diag + 384 upper per b)
constexpr int NTILES_FAST = NT_LL_FAST + NT_LP;  // 7424

// shared memory layout (float offsets)
constexpr int OFF_OW1  = 0;                      // 16384: OW1P[kp][2c+{0,1}]
constexpr int OFF_OW2  = 16384;                  // 4096:  OW2P[kp][2h+{0,1}]
constexpr int OFF_VW2  = 20480;                  // 4096
constexpr int OFF_TVV  = 24576;                  // 96: T[d][h] = vw1@vw2
constexpr int OFF_VW1  = 24672;                  // 384
constexpr int OFF_VB1  = 25056;                  // 128
constexpr int OFF_OB1  = 25184;                  // 128
constexpr int OFF_MEAN = 25312;                  // 128
constexpr int OFF_ISTD = 25440;                  // 128
constexpr int OFF_COEF = 25568;                  // 128
constexpr int OFF_B2   = 25696;                  // 32
constexpr int OFF_FLAG = 25728;                  // 4 ints: [0] vbzero, [1] sym
constexpr int OFF_DLM4 = 25732;                  // 256: {d0,d1,d2,x0} per m
constexpr int OFF_GP   = 25988;                  // 8448: G / H1 pair-major [kp][2m]
constexpr int OFF_VP1  = OFF_GP + 64 * PP;       // 34436
// scratch: pitch 36 floats (144B) -> m*36 + h0 (h0 multiple of 8) is 16B-aligned
constexpr int SCP = 36;
constexpr int SCSTRIDE = 64 * SCP;               // 2304
constexpr int OFF_SCR  = OFF_VP1 + 64 * PP;      // 42884 (16B-aligned: 171536B)
constexpr int SMEM_FLOATS = OFF_SCR + 3 * SCSTRIDE;  // 49796
constexpr int SMEM_BYTES  = SMEM_FLOATS * 4;         // 199184

__device__ __forceinline__ ull ffma2(ull a, ull b, ull c) {
    ull d; asm("fma.rn.f32x2 %0,%1,%2,%3;" : "=l"(d) : "l"(a), "l"(b), "l"(c)); return d;
}
__device__ __forceinline__ float2 u2f2(ull v) {
    float2 f; asm("mov.b64 {%0,%1},%2;" : "=f"(f.x), "=f"(f.y) : "l"(v)); return f;
}
__device__ __forceinline__ ull f2pack(float x, float y) {
    ull r; asm("mov.b64 %0,{%1,%2};" : "=l"(r) : "f"(x), "f"(y)); return r;
}
__device__ __forceinline__ float hadd2(ull v) { float2 f = u2f2(v); return f.x + f.y; }

// exact-form gelu via Abramowitz-Stegun 7.1.26 erf (|abs err| <= 1.5e-7), branchless
__device__ __forceinline__ float fast_gelu(float x) {
    float y  = x * 0.70710678118654752f;
    float ax = fabsf(y);
    float t  = __fdividef(1.0f, fmaf(0.3275911f, ax, 1.0f));
    float p  = fmaf(t, 1.061405429f, -1.453152027f);
    p = fmaf(t, p, 1.421413741f);
    p = fmaf(t, p, -0.284496736f);
    p = fmaf(t, p, 0.254829592f);
    p *= t;
    float e = __expf(-ax * ax);
    float erfv = copysignf(fmaf(-p, e, 1.0f), y);
    return 0.5f * x * (1.0f + erfv);
}

__global__ void zero_pp_kernel(float* __restrict__ out) {
    const int q = PLEN / 4;
    size_t idx = (size_t)blockIdx.x * blockDim.x + threadIdx.x;
    size_t total = (size_t)BDIM * HDIM * PLEN * q;
    if (idx >= total) return;
    int jq = (int)(idx % q);
    size_t r = idx / q;
    int ip = (int)(r % PLEN);
    size_t bh = r / PLEN;
    size_t addr = (bh * NTOT + (LLEN + ip)) * NTOT + LLEN + 4 * jq;
    *reinterpret_cast<float4*>(out + addr) = make_float4(0.f, 0.f, 0.f, 0.f);
}

__global__ __launch_bounds__(1024, 1)
void fused_distbias_kernel(
    const float* __restrict__ pos,
    const int*   __restrict__ etype,
    const float* __restrict__ mw,
    const float* __restrict__ bw,
    const float* __restrict__ means,
    const float* __restrict__ stds,
    const float* __restrict__ ow1,
    const float* __restrict__ ob1,
    const float* __restrict__ ow2,
    const float* __restrict__ ob2,
    const float* __restrict__ vw1,
    const float* __restrict__ vb1,
    const float* __restrict__ vw2,
    const float* __restrict__ vb2,
    float* __restrict__ out,
    int nE)
{
    extern __shared__ float sm[];
    const int tid = threadIdx.x;
    int* iflags = reinterpret_cast<int*>(sm + OFF_FLAG);

    // ---- Stage weights (pair-major), once per block ----
    for (int i = tid; i < 64 * 128; i += 1024) {
        int kp = i >> 7, c = i & 127;
        sm[OFF_OW1 + kp * 256 + 2 * c]     = ow1[(2 * kp) * KDIM + c];
        sm[OFF_OW1 + kp * 256 + 2 * c + 1] = ow1[(2 * kp + 1) * KDIM + c];
    }
    for (int i = tid; i < 64 * 32; i += 1024) {
        int kp = i >> 5, h = i & 31;
        sm[OFF_OW2 + kp * 64 + 2 * h]     = ow2[(2 * kp) * HDIM + h];
        sm[OFF_OW2 + kp * 64 + 2 * h + 1] = ow2[(2 * kp + 1) * HDIM + h];
        sm[OFF_VW2 + kp * 64 + 2 * h]     = vw2[(2 * kp) * HDIM + h];
        sm[OFF_VW2 + kp * 64 + 2 * h + 1] = vw2[(2 * kp + 1) * HDIM + h];
    }
    if (tid < 3 * KDIM) sm[OFF_VW1 + tid] = vw1[tid];
    if (tid < KDIM) {
        sm[OFF_VB1 + tid] = vb1[tid];
        sm[OFF_OB1 + tid] = ob1[tid];
        float s  = fabsf(stds[tid]) + 1e-5f;
        float is = 1.0f / s;
        sm[OFF_MEAN + tid] = means[tid];
        sm[OFF_ISTD + tid] = is;
        sm[OFF_COEF + tid] = is * (1.0f / sqrtf(2.0f * 3.14159f));
    }
    if (tid < HDIM) sm[OFF_B2 + tid] = ob2[tid] + vb2[tid];
    if (tid == 0) { iflags[0] = 1; iflags[1] = 1; }
    __syncthreads();
    // flag checks
    if (tid < KDIM && vb1[tid] != 0.0f) atomicAnd(&iflags[0], 0);
    {
        float m0v = mw[0], b0v = bw[0];
        for (int i = tid; i < nE; i += 1024)
            if (mw[i] != m0v || bw[i] != b0v) atomicAnd(&iflags[1], 0);
    }
    __syncthreads();
    // T[d][h] = vw1 @ vw2
    if (tid < 96) {
        int d = tid >> 5, h = tid & 31;
        float s = 0.0f;
        for (int kp = 0; kp < 64; kp++) {
            float2 a = *reinterpret_cast<float2*>(sm + OFF_VW1 + d * 128 + 2 * kp);
            float2 w = *reinterpret_cast<float2*>(sm + OFF_VW2 + kp * 64 + 2 * h);
            s += a.x * w.x + a.y * w.y;
        }
        sm[OFF_TVV + d * 32 + h] = s;
    }
    __syncthreads();
    const int vbzero = iflags[0];
    const int fastmode = iflags[0] & iflags[1];
    const int ntiles = fastmode ? NTILES_FAST : NTILES_SLOW;

    // ---- per-thread decompositions ----
    // gaussian: m per lane (64), kp-chunk of 4 per tid>>6
    const int gm  = tid & 63;
    const int gkc = tid >> 6;
    // stage 1: warp = wm(8) x wn(4); lane = mg(4) x ng(8); thread 2m x 4c
    const int s1_lane = tid & 31, s1_w = tid >> 5;
    const int s1_wm = s1_w & 7, s1_wn = s1_w >> 3;
    const int s1_mg = s1_lane >> 3, s1_ng = s1_lane & 7;
    const int s1_m0 = s1_wm * 8 + s1_mg * 2;
    const int s1_np0 = s1_wn * 16 + s1_ng;     // col pairs np0, np0+8
    // stage 2: warp = mq(4) x hq(2) x kh(4); lane = ml(16) x hh(2); thread 1m x 8h x 16kp
    const int s2_lane = tid & 31, s2_w = tid >> 5;
    const int s2_ml = s2_lane >> 1, s2_hh = s2_lane & 1;
    const int s2_mq = s2_w & 3, s2_hq = (s2_w >> 2) & 1, s2_kh = s2_w >> 3;
    const int s2_m  = s2_mq * 16 + s2_ml;
    const int s2_h0 = s2_hq * 16 + s2_hh * 8;

    for (int t = blockIdx.x; t < ntiles; t += gridDim.x) {
        int b, rowi, j0, wrM;
        if (fastmode) {
            if (t < NT_LL_FAST) {
                b = t / 640; int r = t - b * 640;
                if (r < 256) { rowi = r; j0 = r & 192; wrM = 0; }
                else {
                    int r2 = r - 256; int pr = r2 >> 6;
                    int br = (pr < 3) ? 0 : ((pr < 5) ? 1 : 2);
                    int bc = (pr == 0) ? 1 : ((pr == 1 || pr == 3) ? 2 : 3);
                    rowi = br * 64 + (r2 & 63); j0 = bc * 64; wrM = 1;
                }
            } else {
                int u = t - NT_LL_FAST; b = u / 3072; int r = u - b * 3072;
                rowi = LLEN + (r >> 2); j0 = (r & 3) << 6; wrM = 1;
            }
        } else {
            if (t < NT_LL_SLOW) {
                b = t >> 10; int r = t & 1023;
                rowi = r >> 2; j0 = (r & 3) << 6; wrM = 0;
            } else {
                int u = t - NT_LL_SLOW; b = u / 3072; int r = u - b * 3072;
                rowi = LLEN + (r >> 2); j0 = (r & 3) << 6; wrM = 1;
            }
        }

        // ---- (M) metadata ----
        if (tid < 64) {
            int j = j0 + tid;
            const float* pj = pos + ((size_t)b * NTOT + j) * 3;
            const float* pi = pos + ((size_t)b * NTOT + rowi) * 3;
            float d0 = pj[0] - pi[0];
            float d1 = pj[1] - pi[1];
            float d2 = pj[2] - pi[2];
            float d = 1.0f / (d0 * d0 + d1 * d1 + d2 * d2 + 1.0f);
            int e = etype[((size_t)b * NTOT + rowi) * NTOT + j];
            float x0 = mw[e] * d + bw[e];
            *reinterpret_cast<float4*>(sm + OFF_DLM4 + tid * 4) =
                make_float4(d0, d1, d2, x0);
        }
        __syncthreads();   // (1)

        // ---- (G) gaussian + vector-MLP hidden ----
        {
            float4 dm = *reinterpret_cast<float4*>(sm + OFF_DLM4 + gm * 4);
            #pragma unroll
            for (int i = 0; i < 4; i++) {
                int kp = gkc * 4 + i;
                float2 mn = *reinterpret_cast<float2*>(sm + OFF_MEAN + 2 * kp);
                float2 is = *reinterpret_cast<float2*>(sm + OFF_ISTD + 2 * kp);
                float2 cf = *reinterpret_cast<float2*>(sm + OFF_COEF + 2 * kp);
                float2 w0 = *reinterpret_cast<float2*>(sm + OFF_VW1 + 2 * kp);
                float2 w1 = *reinterpret_cast<float2*>(sm + OFF_VW1 + 128 + 2 * kp);
                float2 w2 = *reinterpret_cast<float2*>(sm + OFF_VW1 + 256 + 2 * kp);
                float2 vb = *reinterpret_cast<float2*>(sm + OFF_VB1 + 2 * kp);
                float tx = (dm.w - mn.x) * is.x;
                float ty = (dm.w - mn.y) * is.y;
                float2 g = make_float2(__expf(-0.5f * tx * tx) * cf.x,
                                       __expf(-0.5f * ty * ty) * cf.y);
                float sx = dm.x * w0.x + dm.y * w1.x + dm.z * w2.x + vb.x;
                float sy = dm.x * w0.y + dm.y * w1.y + dm.z * w2.y + vb.y;
                float2 v1 = make_float2(fast_gelu(sx), fast_gelu(sy));
                *reinterpret_cast<float2*>(sm + OFF_GP  + kp * PP + 2 * gm) = g;
                *reinterpret_cast<float2*>(sm + OFF_VP1 + kp * PP + 2 * gm) = v1;
            }
        }
        __syncthreads();   // (2)

        // ---- (S1) H1 = gelu(G @ ow1 + ob1) ----
        {
            ull a00 = 0, a01 = 0, a02 = 0, a03 = 0;
            ull a10 = 0, a11 = 0, a12 = 0, a13 = 0;
            const float* gB = sm + OFF_GP + 2 * s1_m0;
            const float* wB = sm + OFF_OW1 + s1_wn * 64 + 4 * s1_ng;
            #pragma unroll 4
            for (int kp = 0; kp < 64; kp++) {
                ulonglong2 g  = *reinterpret_cast<const ulonglong2*>(gB + kp * PP);
                ulonglong2 wA = *reinterpret_cast<const ulonglong2*>(wB + kp * 256);
                ulonglong2 wC = *reinterpret_cast<const ulonglong2*>(wB + kp * 256 + 32);
                a00 = ffma2(g.x, wA.x, a00); a01 = ffma2(g.x, wA.y, a01);
                a02 = ffma2(g.x, wC.x, a02); a03 = ffma2(g.x, wC.y, a03);
                a10 = ffma2(g.y, wA.x, a10); a11 = ffma2(g.y, wA.y, a11);
                a12 = ffma2(g.y, wC.x, a12); a13 = ffma2(g.y, wC.y, a13);
            }
            __syncthreads();   // (3)
            float2 obA = *reinterpret_cast<float2*>(sm + OFF_OB1 + s1_wn * 32 + 2 * s1_ng);
            float2 obB = *reinterpret_cast<float2*>(sm + OFF_OB1 + s1_wn * 32 + 2 * s1_ng + 16);
            float2 hA0 = make_float2(fast_gelu(hadd2(a00) + obA.x),
                                     fast_gelu(hadd2(a01) + obA.y));
            float2 hB0 = make_float2(fast_gelu(hadd2(a02) + obB.x),
                                     fast_gelu(hadd2(a03) + obB.y));
            float2 hA1 = make_float2(fast_gelu(hadd2(a10) + obA.x),
                                     fast_gelu(hadd2(a11) + obA.y));
            float2 hB1 = make_float2(fast_gelu(hadd2(a12) + obB.x),
                                     fast_gelu(hadd2(a13) + obB.y));
            *reinterpret_cast<float2*>(sm + OFF_GP + s1_np0 * PP + 2 * s1_m0) = hA0;
            *reinterpret_cast<float2*>(sm + OFF_GP + (s1_np0 + 8) * PP + 2 * s1_m0) = hB0;
            *reinterpret_cast<float2*>(sm + OFF_GP + s1_np0 * PP + 2 * (s1_m0 + 1)) = hA1;
            *reinterpret_cast<float2*>(sm + OFF_GP + (s1_np0 + 8) * PP + 2 * (s1_m0 + 1)) = hB1;
        }
        __syncthreads();   // (4)

        // ---- (S2) combined contraction: R = H1@ow2 + V1@vw2 ----
        float rowv[8];
        {
            const float* hB = sm + OFF_GP  + s2_kh * 16 * PP + 2 * s2_m;
            const float* vB = sm + OFF_VP1 + s2_kh * 16 * PP + 2 * s2_m;
            const float* oB = sm + OFF_OW2 + s2_kh * 1024 + 2 * s2_h0;
            const float* wB = sm + OFF_VW2 + s2_kh * 1024 + 2 * s2_h0;
            ull R[8];
            #pragma unroll
            for (int j = 0; j < 8; j++) R[j] = 0ull;
            #pragma unroll 4
            for (int i = 0; i < 16; i++) {
                ull hp = *reinterpret_cast<const ull*>(hB + i * PP);
                ull vp = *reinterpret_cast<const ull*>(vB + i * PP);
                ulonglong2 o01 = *reinterpret_cast<const ulonglong2*>(oB + i * 64);
                ulonglong2 o23 = *reinterpret_cast<const ulonglong2*>(oB + i * 64 + 4);
                ulonglong2 o45 = *reinterpret_cast<const ulonglong2*>(oB + i * 64 + 8);
                ulonglong2 o67 = *reinterpret_cast<const ulonglong2*>(oB + i * 64 + 12);
                R[0] = ffma2(hp, o01.x, R[0]); R[1] = ffma2(hp, o01.y, R[1]);
                R[2] = ffma2(hp, o23.x, R[2]); R[3] = ffma2(hp, o23.y, R[3]);
                R[4] = ffma2(hp, o45.x, R[4]); R[5] = ffma2(hp, o45.y, R[5]);
                R[6] = ffma2(hp, o67.x, R[6]); R[7] = ffma2(hp, o67.y, R[7]);
                ulonglong2 v01 = *reinterpret_cast<const ulonglong2*>(wB + i * 64);
                ulonglong2 v23 = *reinterpret_cast<const ulonglong2*>(wB + i * 64 + 4);
                ulonglong2 v45 = *reinterpret_cast<const ulonglong2*>(wB + i * 64 + 8);
                ulonglong2 v67 = *reinterpret_cast<const ulonglong2*>(wB + i * 64 + 12);
                R[0] = ffma2(vp, v01.x, R[0]); R[1] = ffma2(vp, v01.y, R[1]);
                R[2] = ffma2(vp, v23.x, R[2]); R[3] = ffma2(vp, v23.y, R[3]);
                R[4] = ffma2(vp, v45.x, R[4]); R[5] = ffma2(vp, v45.y, R[5]);
                R[6] = ffma2(vp, v67.x, R[6]); R[7] = ffma2(vp, v67.y, R[7]);
            }
            #pragma unroll
            for (int j = 0; j < 8; j++) rowv[j] = hadd2(R[j]);
        }
        // mirror correction (identity path), computed before barrier (DLM4 still valid)
        float corr[8];
        if (wrM && vbzero && s2_kh == 0) {
            float4 dmv = *reinterpret_cast<float4*>(sm + OFF_DLM4 + s2_m * 4);
            #pragma unroll
            for (int j = 0; j < 8; j++) {
                int h = s2_h0 + j;
                corr[j] = dmv.x * sm[OFF_TVV + h]
                        + dmv.y * sm[OFF_TVV + 32 + h]
                        + dmv.z * sm[OFF_TVV + 64 + h];
            }
        }
        if (s2_kh) {
            float* sc = sm + OFF_SCR + (s2_kh - 1) * SCSTRIDE + s2_m * SCP + s2_h0;
            *reinterpret_cast<float4*>(sc)     = make_float4(rowv[0], rowv[1], rowv[2], rowv[3]);
            *reinterpret_cast<float4*>(sc + 4) = make_float4(rowv[4], rowv[5], rowv[6], rowv[7]);
        }
        __syncthreads();   // (5)
        if (s2_kh == 0) {
            #pragma unroll
            for (int p = 0; p < 3; p++) {
                const float* sc = sm + OFF_SCR + p * SCSTRIDE + s2_m * SCP + s2_h0;
                float4 r0 = *reinterpret_cast<const float4*>(sc);
                float4 r1 = *reinterpret_cast<const float4*>(sc + 4);
                rowv[0] += r0.x; rowv[1] += r0.y; rowv[2] += r0.z; rowv[3] += r0.w;
                rowv[4] += r1.x; rowv[5] += r1.y; rowv[6] += r1.z; rowv[7] += r1.w;
            }
            const size_t bh = (size_t)b * HDIM;
            #pragma unroll
            for (int j = 0; j < 8; j++) {
                int h = s2_h0 + j;
                float v = rowv[j] + sm[OFF_B2 + h];
                out[((bh + h) * NTOT + rowi) * NTOT + j0 + s2_m] = v;
                if (wrM && vbzero)
                    out[((bh + h) * NTOT + (j0 + s2_m)) * NTOT + rowi] = v - corr[j];
            }
        }

        // ---- fallback mirror path (vb1 != 0): delta = sum (gelu(-s)-v1) * vw2 ----
        if (wrM && !vbzero) {
            float dp[8];
            {
                float4 dmv = *reinterpret_cast<float4*>(sm + OFF_DLM4 + s2_m * 4);
                const float* vB = sm + OFF_VP1 + s2_kh * 16 * PP + 2 * s2_m;
                const float* wB = sm + OFF_VW2 + s2_kh * 1024 + 2 * s2_h0;
                ull D[8];
                #pragma unroll
                for (int j = 0; j < 8; j++) D[j] = 0ull;
                for (int i = 0; i < 16; i++) {
                    int kp = s2_kh * 16 + i;
                    float2 w0 = *reinterpret_cast<float2*>(sm + OFF_VW1 + 2 * kp);
                    float2 w1 = *reinterpret_cast<float2*>(sm + OFF_VW1 + 128 + 2 * kp);
                    float2 w2 = *reinterpret_cast<float2*>(sm + OFF_VW1 + 256 + 2 * kp);
                    float2 vb = *reinterpret_cast<float2*>(sm + OFF_VB1 + 2 * kp);
                    float sx = dmv.x * w0.x + dmv.y * w1.x + dmv.z * w2.x + vb.x;
                    float sy = dmv.x * w0.y + dmv.y * w1.y + dmv.z * w2.y + vb.y;
                    float2 pv = u2f2(*reinterpret_cast<const ull*>(vB + i * PP));
                    ull dq = f2pack(fast_gelu(2.0f * vb.x - sx) - pv.x,
                                    fast_gelu(2.0f * vb.y - sy) - pv.y);
                    ulonglong2 v01 = *reinterpret_cast<const ulonglong2*>(wB + i * 64);
                    ulonglong2 v23 = *reinterpret_cast<const ulonglong2*>(wB + i * 64 + 4);
                    ulonglong2 v45 = *reinterpret_cast<const ulonglong2*>(wB + i * 64 + 8);
                    ulonglong2 v67 = *reinterpret_cast<const ulonglong2*>(wB + i * 64 + 12);
                    D[0] = ffma2(dq, v01.x, D[0]); D[1] = ffma2(dq, v01.y, D[1]);
                    D[2] = ffma2(dq, v23.x, D[2]); D[3] = ffma2(dq, v23.y, D[3]);
                    D[4] = ffma2(dq, v45.x, D[4]); D[5] = ffma2(dq, v45.y, D[5]);
                    D[6] = ffma2(dq, v67.x, D[6]); D[7] = ffma2(dq, v67.y, D[7]);
                }
                #pragma unroll
                for (int j = 0; j < 8; j++) dp[j] = hadd2(D[j]);
            }
            __syncthreads();   // (6) scratch free (kh0 finished reading R partials)
            if (s2_kh) {
                float* sc = sm + OFF_SCR + (s2_kh - 1) * SCSTRIDE + s2_m * SCP + s2_h0;
                *reinterpret_cast<float4*>(sc)     = make_float4(dp[0], dp[1], dp[2], dp[3]);
                *reinterpret_cast<float4*>(sc + 4) = make_float4(dp[4], dp[5], dp[6], dp[7]);
            }
            __syncthreads();   // (7)
            if (s2_kh == 0) {
                #pragma unroll
                for (int p = 0; p < 3; p++) {
                    const float* sc = sm + OFF_SCR + p * SCSTRIDE + s2_m * SCP + s2_h0;
                    float4 r0 = *reinterpret_cast<const float4*>(sc);
                    float4 r1 = *reinterpret_cast<const float4*>(sc + 4);
                    dp[0] += r0.x; dp[1] += r0.y; dp[2] += r0.z; dp[3] += r0.w;
                    dp[4] += r1.x; dp[5] += r1.y; dp[6] += r1.z; dp[7] += r1.w;
                }
                const size_t bh = (size_t)b * HDIM;
                #pragma unroll
                for (int j = 0; j < 8; j++) {
                    int h = s2_h0 + j;
                    float v = rowv[j] + dp[j] + sm[OFF_B2 + h];
                    out[((bh + h) * NTOT + (j0 + s2_m)) * NTOT + rowi] = v;
                }
            }
        }
        // loop-around ordering: DLM4 rewritten only after barrier (1) of next tile;
        // GP/VP1 rewritten after (2); scratch rewritten after (4)/(6).
    }
}

extern "C" void kernel_launch(void* const* d_in, const int* in_sizes, int n_in,
                              void* d_out, int out_size) {
    const float* pos    = (const float*)d_in[0];
    const int*   etype  = (const int*)d_in[1];
    const float* means  = (const float*)d_in[3];
    const float* stds   = (const float*)d_in[4];
    const float* mul_w  = (const float*)d_in[5];
    const float* bias_w = (const float*)d_in[6];
    const float* ow1    = (const float*)d_in[7];
    const float* ob1    = (const float*)d_in[8];
    const float* ow2    = (const float*)d_in[9];
    const float* ob2    = (const float*)d_in[10];
    const float* vw1    = (const float*)d_in[11];
    const float* vb1    = (const float*)d_in[12];
    const float* vw2    = (const float*)d_in[13];
    const float* vb2    = (const float*)d_in[14];
    float* out = (float*)d_out;
    int nE = in_sizes[5];   // mul_w element count (E)

    cudaFuncSetAttribute(fused_distbias_kernel,
                         cudaFuncAttributeMaxDynamicSharedMemorySize, SMEM_BYTES);

    {
        size_t total = (size_t)BDIM * HDIM * PLEN * (PLEN / 4);
        int grid = (int)((total + 255) / 256);
        zero_pp_kernel<<<grid, 256>>>(out);
    }

    fused_distbias_kernel<<<148, 1024, SMEM_BYTES>>>(
        pos, etype, mul_w, bias_w, means, stds,
        ow1, ob1, ow2, ob2, vw1, vb1, vw2, vb2, out, nE);
}

// round 11
// speedup vs baseline: 1.1742x; 1.1739x over previous
#include <cuda_runtime.h>
#include <math.h>

typedef unsigned long long ull;

#define BDIM 2
#define NTOT 1024
#define PLEN 768
#define LLEN 256
#define KDIM 128
#define HDIM 32

constexpr int PP = 132;                          // pair-major row pitch (floats)
constexpr int NT_LP = BDIM * PLEN * 4;           // 6144
constexpr int NT_LL_SLOW = BDIM * LLEN * 4;      // 2048
constexpr int NTILES_SLOW = NT_LL_SLOW + NT_LP;  // 8192
constexpr int NT_LL_FAST = BDIM * 640;           // 1280 (256 diag + 384 upper per b)
constexpr int NTILES_FAST = NT_LL_FAST + NT_LP;  // 7424

// shared memory layout (float offsets)
constexpr int OFF_OW1  = 0;                      // 16384: OW1P[kp][2c+{0,1}]
constexpr int OFF_OW2  = 16384;                  // 4096:  OW2P[kp][2h+{0,1}]
constexpr int OFF_VW2  = 20480;                  // 4096
constexpr int OFF_TVV  = 24576;                  // 96: T[d][h] = vw1@vw2
constexpr int OFF_VW1  = 24672;                  // 384
constexpr int OFF_VB1  = 25056;                  // 128
constexpr int OFF_OB1  = 25184;                  // 128
constexpr int OFF_MEAN = 25312;                  // 128
constexpr int OFF_ISTD = 25440;                  // 128
constexpr int OFF_COEF = 25568;                  // 128
constexpr int OFF_B2   = 25696;                  // 32
constexpr int OFF_FLAG = 25728;                  // ints: [0] vbzero, [1] sym
constexpr int OFF_DLM4 = 25732;                  // 256: {d0,d1,d2,x0} per m
constexpr int OFF_GP   = 25988;                  // 8448: G / H1 pair-major [kp][2m]
constexpr int OFF_VP1  = OFF_GP + 64 * PP;       // 34436
// scratch: pitch 36 floats (144B) -> m*36 + h0 (h0 mult of 8) is 16B-aligned
constexpr int SCP = 36;
constexpr int SCSTRIDE = 64 * SCP;               // 2304
constexpr int OFF_SCR  = OFF_VP1 + 64 * PP;      // 42884 (byte 171536, 16B-aligned)
constexpr int SMEM_FLOATS = OFF_SCR + SCSTRIDE;  // 45188
constexpr int SMEM_BYTES  = SMEM_FLOATS * 4;     // 180752

__device__ __forceinline__ ull ffma2(ull a, ull b, ull c) {
    ull d; asm("fma.rn.f32x2 %0,%1,%2,%3;" : "=l"(d) : "l"(a), "l"(b), "l"(c)); return d;
}
__device__ __forceinline__ float2 u2f2(ull v) {
    float2 f; asm("mov.b64 {%0,%1},%2;" : "=f"(f.x), "=f"(f.y) : "l"(v)); return f;
}
__device__ __forceinline__ ull f2pack(float x, float y) {
    ull r; asm("mov.b64 %0,{%1,%2};" : "=l"(r) : "f"(x), "f"(y)); return r;
}
__device__ __forceinline__ float hadd2(ull v) { float2 f = u2f2(v); return f.x + f.y; }

// exact-form gelu via Abramowitz-Stegun 7.1.26 erf (|abs err| <= 1.5e-7), branchless
__device__ __forceinline__ float fast_gelu(float x) {
    float y  = x * 0.70710678118654752f;
    float ax = fabsf(y);
    float t  = __fdividef(1.0f, fmaf(0.3275911f, ax, 1.0f));
    float p  = fmaf(t, 1.061405429f, -1.453152027f);
    p = fmaf(t, p, 1.421413741f);
    p = fmaf(t, p, -0.284496736f);
    p = fmaf(t, p, 0.254829592f);
    p *= t;
    float e = __expf(-ax * ax);
    float erfv = copysignf(fmaf(-p, e, 1.0f), y);
    return 0.5f * x * (1.0f + erfv);
}

__global__ void zero_pp_kernel(float* __restrict__ out) {
    const int q = PLEN / 4;
    size_t idx = (size_t)blockIdx.x * blockDim.x + threadIdx.x;
    size_t total = (size_t)BDIM * HDIM * PLEN * q;
    if (idx >= total) return;
    int jq = (int)(idx % q);
    size_t r = idx / q;
    int ip = (int)(r % PLEN);
    size_t bh = r / PLEN;
    size_t addr = (bh * NTOT + (LLEN + ip)) * NTOT + LLEN + 4 * jq;
    *reinterpret_cast<float4*>(out + addr) = make_float4(0.f, 0.f, 0.f, 0.f);
}

__global__ __launch_bounds__(512, 1)
void fused_distbias_kernel(
    const float* __restrict__ pos,
    const int*   __restrict__ etype,
    const float* __restrict__ mw,
    const float* __restrict__ bw,
    const float* __restrict__ means,
    const float* __restrict__ stds,
    const float* __restrict__ ow1,
    const float* __restrict__ ob1,
    const float* __restrict__ ow2,
    const float* __restrict__ ob2,
    const float* __restrict__ vw1,
    const float* __restrict__ vb1,
    const float* __restrict__ vw2,
    const float* __restrict__ vb2,
    float* __restrict__ out,
    int nE)
{
    extern __shared__ float sm[];
    const int tid = threadIdx.x;
    int* iflags = reinterpret_cast<int*>(sm + OFF_FLAG);

    // ---- Stage weights (pair-major), once per block ----
    for (int i = tid; i < 64 * 128; i += 512) {
        int kp = i >> 7, c = i & 127;
        sm[OFF_OW1 + kp * 256 + 2 * c]     = ow1[(2 * kp) * KDIM + c];
        sm[OFF_OW1 + kp * 256 + 2 * c + 1] = ow1[(2 * kp + 1) * KDIM + c];
    }
    for (int i = tid; i < 64 * 32; i += 512) {
        int kp = i >> 5, h = i & 31;
        sm[OFF_OW2 + kp * 64 + 2 * h]     = ow2[(2 * kp) * HDIM + h];
        sm[OFF_OW2 + kp * 64 + 2 * h + 1] = ow2[(2 * kp + 1) * HDIM + h];
        sm[OFF_VW2 + kp * 64 + 2 * h]     = vw2[(2 * kp) * HDIM + h];
        sm[OFF_VW2 + kp * 64 + 2 * h + 1] = vw2[(2 * kp + 1) * HDIM + h];
    }
    if (tid < 3 * KDIM) sm[OFF_VW1 + tid] = vw1[tid];
    if (tid < KDIM) {
        sm[OFF_VB1 + tid] = vb1[tid];
        sm[OFF_OB1 + tid] = ob1[tid];
        float s  = fabsf(stds[tid]) + 1e-5f;
        float is = 1.0f / s;
        sm[OFF_MEAN + tid] = means[tid];
        sm[OFF_ISTD + tid] = is;
        sm[OFF_COEF + tid] = is * (1.0f / sqrtf(2.0f * 3.14159f));
    }
    if (tid < HDIM) sm[OFF_B2 + tid] = ob2[tid] + vb2[tid];
    if (tid == 0) { iflags[0] = 1; iflags[1] = 1; }
    __syncthreads();
    if (tid < KDIM && vb1[tid] != 0.0f) atomicAnd(&iflags[0], 0);
    {
        float m0v = mw[0], b0v = bw[0];
        for (int i = tid; i < nE; i += 512)
            if (mw[i] != m0v || bw[i] != b0v) atomicAnd(&iflags[1], 0);
    }
    __syncthreads();
    // T[d][h] = vw1 @ vw2
    if (tid < 96) {
        int d = tid >> 5, h = tid & 31;
        float s = 0.0f;
        for (int kp = 0; kp < 64; kp++) {
            float2 a = *reinterpret_cast<float2*>(sm + OFF_VW1 + d * 128 + 2 * kp);
            float2 w = *reinterpret_cast<float2*>(sm + OFF_VW2 + kp * 64 + 2 * h);
            s += a.x * w.x + a.y * w.y;
        }
        sm[OFF_TVV + d * 32 + h] = s;
    }
    __syncthreads();
    const int vbzero = iflags[0];
    const int fastmode = iflags[0] & iflags[1];
    const int ntiles = fastmode ? NTILES_FAST : NTILES_SLOW;

    // ---- per-thread decompositions (512 threads, 16 warps) ----
    // gaussian: m per lane (64), 8 kp per chunk
    const int gm  = tid & 63;
    const int gkc = tid >> 6;
    // stage 1: warp (wm4, wn4); lane (mg4, ng8); thread: 4m x 4 col-pairs
    const int s1_wid = tid >> 5, s1_lane = tid & 31;
    const int s1_wm = s1_wid & 3, s1_wn = s1_wid >> 2;
    const int s1_mg = s1_lane >> 3, s1_ng = s1_lane & 7;
    const int s1_mbase = s1_wm * 16 + s1_mg * 4;
    const int s1_cbase = s1_wn * 32;
    const int s1_npA   = s1_wn * 16 + s1_ng;       // col pairs npA, npA+8
    // stage 2: warp = hg(4) x kh(2) x mh(2); thread: 1m, 8h, 32kp
    const int s2_hg = (tid >> 5) & 3;
    const int s2_kh = (tid >> 7) & 1;
    const int s2_mh = tid >> 8;
    const int s2_h0 = s2_hg * 8;
    const int s2_m  = s2_mh * 32 + (tid & 31);

    for (int t = blockIdx.x; t < ntiles; t += gridDim.x) {
        int b, rowi, j0, wrM;
        if (fastmode) {
            if (t < NT_LL_FAST) {
                b = t / 640; int r = t - b * 640;
                if (r < 256) { rowi = r; j0 = r & 192; wrM = 0; }
                else {
                    int r2 = r - 256; int pr = r2 >> 6;
                    int br = (pr < 3) ? 0 : ((pr < 5) ? 1 : 2);
                    int bc = (pr == 0) ? 1 : ((pr == 1 || pr == 3) ? 2 : 3);
                    rowi = br * 64 + (r2 & 63); j0 = bc * 64; wrM = 1;
                }
            } else {
                int u = t - NT_LL_FAST; b = u / 3072; int r = u - b * 3072;
                rowi = LLEN + (r >> 2); j0 = (r & 3) << 6; wrM = 1;
            }
        } else {
            if (t < NT_LL_SLOW) {
                b = t >> 10; int r = t & 1023;
                rowi = r >> 2; j0 = (r & 3) << 6; wrM = 0;
            } else {
                int u = t - NT_LL_SLOW; b = u / 3072; int r = u - b * 3072;
                rowi = LLEN + (r >> 2); j0 = (r & 3) << 6; wrM = 1;
            }
        }

        // ---- (M) metadata: DLM4[m] = {d0,d1,d2,x0} ----
        if (tid < 64) {
            int j = j0 + tid;
            const float* pj = pos + ((size_t)b * NTOT + j) * 3;
            const float* pi = pos + ((size_t)b * NTOT + rowi) * 3;
            float d0 = pj[0] - pi[0];
            float d1 = pj[1] - pi[1];
            float d2 = pj[2] - pi[2];
            float d = 1.0f / (d0 * d0 + d1 * d1 + d2 * d2 + 1.0f);
            int e = etype[((size_t)b * NTOT + rowi) * NTOT + j];
            float x0 = mw[e] * d + bw[e];
            *reinterpret_cast<float4*>(sm + OFF_DLM4 + tid * 4) =
                make_float4(d0, d1, d2, x0);
        }
        __syncthreads();   // (1)

        // ---- (G) gaussian + vector-MLP hidden (pair-major stores) ----
        {
            float4 dm = *reinterpret_cast<float4*>(sm + OFF_DLM4 + gm * 4);
            #pragma unroll
            for (int i = 0; i < 8; i++) {
                int kp = gkc * 8 + i;
                float2 mn = *reinterpret_cast<float2*>(sm + OFF_MEAN + 2 * kp);
                float2 is = *reinterpret_cast<float2*>(sm + OFF_ISTD + 2 * kp);
                float2 cf = *reinterpret_cast<float2*>(sm + OFF_COEF + 2 * kp);
                float2 w0 = *reinterpret_cast<float2*>(sm + OFF_VW1 + 2 * kp);
                float2 w1 = *reinterpret_cast<float2*>(sm + OFF_VW1 + 128 + 2 * kp);
                float2 w2 = *reinterpret_cast<float2*>(sm + OFF_VW1 + 256 + 2 * kp);
                float2 vb = *reinterpret_cast<float2*>(sm + OFF_VB1 + 2 * kp);
                float tx = (dm.w - mn.x) * is.x;
                float ty = (dm.w - mn.y) * is.y;
                float2 g = make_float2(__expf(-0.5f * tx * tx) * cf.x,
                                       __expf(-0.5f * ty * ty) * cf.y);
                float sx = dm.x * w0.x + dm.y * w1.x + dm.z * w2.x + vb.x;
                float sy = dm.x * w0.y + dm.y * w1.y + dm.z * w2.y + vb.y;
                float2 v1 = make_float2(fast_gelu(sx), fast_gelu(sy));
                *reinterpret_cast<float2*>(sm + OFF_GP  + kp * PP + 2 * gm) = g;
                *reinterpret_cast<float2*>(sm + OFF_VP1 + kp * PP + 2 * gm) = v1;
            }
        }
        __syncthreads();   // (2)

        // ---- (S1) H1 = gelu(G @ ow1 + ob1); 4m x 4 col-pairs, FFMA2 ----
        {
            ull acc[4][4];
            #pragma unroll
            for (int r = 0; r < 4; r++)
                #pragma unroll
                for (int j = 0; j < 4; j++) acc[r][j] = 0ull;
            const float* gpB = sm + OFF_GP + 2 * s1_mbase;
            const float* w1B = sm + OFF_OW1 + 2 * s1_cbase + 4 * s1_ng;
            #pragma unroll 4
            for (int kp = 0; kp < 64; kp++) {
                ulonglong2 g01 = *reinterpret_cast<const ulonglong2*>(gpB + kp * PP);
                ulonglong2 g23 = *reinterpret_cast<const ulonglong2*>(gpB + kp * PP + 4);
                ulonglong2 wA  = *reinterpret_cast<const ulonglong2*>(w1B + kp * 256);
                ulonglong2 wB  = *reinterpret_cast<const ulonglong2*>(w1B + kp * 256 + 32);
                acc[0][0] = ffma2(g01.x, wA.x, acc[0][0]);
                acc[0][1] = ffma2(g01.x, wA.y, acc[0][1]);
                acc[0][2] = ffma2(g01.x, wB.x, acc[0][2]);
                acc[0][3] = ffma2(g01.x, wB.y, acc[0][3]);
                acc[1][0] = ffma2(g01.y, wA.x, acc[1][0]);
                acc[1][1] = ffma2(g01.y, wA.y, acc[1][1]);
                acc[1][2] = ffma2(g01.y, wB.x, acc[1][2]);
                acc[1][3] = ffma2(g01.y, wB.y, acc[1][3]);
                acc[2][0] = ffma2(g23.x, wA.x, acc[2][0]);
                acc[2][1] = ffma2(g23.x, wA.y, acc[2][1]);
                acc[2][2] = ffma2(g23.x, wB.x, acc[2][2]);
                acc[2][3] = ffma2(g23.x, wB.y, acc[2][3]);
                acc[3][0] = ffma2(g23.y, wA.x, acc[3][0]);
                acc[3][1] = ffma2(g23.y, wA.y, acc[3][1]);
                acc[3][2] = ffma2(g23.y, wB.x, acc[3][2]);
                acc[3][3] = ffma2(g23.y, wB.y, acc[3][3]);
            }
            __syncthreads();   // (3) all GP reads done before H1 overwrite
            float2 obA = *reinterpret_cast<float2*>(sm + OFF_OB1 + s1_cbase + 2 * s1_ng);
            float2 obB = *reinterpret_cast<float2*>(sm + OFF_OB1 + s1_cbase + 2 * s1_ng + 16);
            #pragma unroll
            for (int r = 0; r < 4; r++) {
                int m = s1_mbase + r;
                float2 hA = make_float2(fast_gelu(hadd2(acc[r][0]) + obA.x),
                                        fast_gelu(hadd2(acc[r][1]) + obA.y));
                float2 hB = make_float2(fast_gelu(hadd2(acc[r][2]) + obB.x),
                                        fast_gelu(hadd2(acc[r][3]) + obB.y));
                *reinterpret_cast<float2*>(sm + OFF_GP + s1_npA * PP + 2 * m) = hA;
                *reinterpret_cast<float2*>(sm + OFF_GP + (s1_npA + 8) * PP + 2 * m) = hB;
            }
        }
        __syncthreads();   // (4)

        // ---- (S2) merged contraction R = H1@ow2 + V1@vw2; k-split 2 ----
        float rowv[8];
        {
            const float* hB = sm + OFF_GP  + s2_kh * 32 * PP + 2 * s2_m;
            const float* vB = sm + OFF_VP1 + s2_kh * 32 * PP + 2 * s2_m;
            const float* oB = sm + OFF_OW2 + s2_kh * 2048 + 2 * s2_h0;
            const float* wB = sm + OFF_VW2 + s2_kh * 2048 + 2 * s2_h0;
            ull R[8];
            #pragma unroll
            for (int j = 0; j < 8; j++) R[j] = 0ull;
            #pragma unroll 4
            for (int i = 0; i < 32; i++) {
                ull hp = *reinterpret_cast<const ull*>(hB + i * PP);
                ull vp = *reinterpret_cast<const ull*>(vB + i * PP);
                ulonglong2 o01 = *reinterpret_cast<const ulonglong2*>(oB + i * 64);
                ulonglong2 o23 = *reinterpret_cast<const ulonglong2*>(oB + i * 64 + 4);
                ulonglong2 o45 = *reinterpret_cast<const ulonglong2*>(oB + i * 64 + 8);
                ulonglong2 o67 = *reinterpret_cast<const ulonglong2*>(oB + i * 64 + 12);
                R[0] = ffma2(hp, o01.x, R[0]); R[1] = ffma2(hp, o01.y, R[1]);
                R[2] = ffma2(hp, o23.x, R[2]); R[3] = ffma2(hp, o23.y, R[3]);
                R[4] = ffma2(hp, o45.x, R[4]); R[5] = ffma2(hp, o45.y, R[5]);
                R[6] = ffma2(hp, o67.x, R[6]); R[7] = ffma2(hp, o67.y, R[7]);
                ulonglong2 v01 = *reinterpret_cast<const ulonglong2*>(wB + i * 64);
                ulonglong2 v23 = *reinterpret_cast<const ulonglong2*>(wB + i * 64 + 4);
                ulonglong2 v45 = *reinterpret_cast<const ulonglong2*>(wB + i * 64 + 8);
                ulonglong2 v67 = *reinterpret_cast<const ulonglong2*>(wB + i * 64 + 12);
                R[0] = ffma2(vp, v01.x, R[0]); R[1] = ffma2(vp, v01.y, R[1]);
                R[2] = ffma2(vp, v23.x, R[2]); R[3] = ffma2(vp, v23.y, R[3]);
                R[4] = ffma2(vp, v45.x, R[4]); R[5] = ffma2(vp, v45.y, R[5]);
                R[6] = ffma2(vp, v67.x, R[6]); R[7] = ffma2(vp, v67.y, R[7]);
            }
            #pragma unroll
            for (int j = 0; j < 8; j++) rowv[j] = hadd2(R[j]);
        }
        // mirror correction (identity path) — DLM4 still valid here
        float corr[8];
        if (wrM && vbzero && s2_kh == 0) {
            float4 dmv = *reinterpret_cast<float4*>(sm + OFF_DLM4 + s2_m * 4);
            #pragma unroll
            for (int j = 0; j < 8; j++) {
                int h = s2_h0 + j;
                corr[j] = dmv.x * sm[OFF_TVV + h]
                        + dmv.y * sm[OFF_TVV + 32 + h]
                        + dmv.z * sm[OFF_TVV + 64 + h];
            }
        }
        if (s2_kh) {
            float* sc = sm + OFF_SCR + s2_m * SCP + s2_h0;
            *reinterpret_cast<float4*>(sc)     = make_float4(rowv[0], rowv[1], rowv[2], rowv[3]);
            *reinterpret_cast<float4*>(sc + 4) = make_float4(rowv[4], rowv[5], rowv[6], rowv[7]);
        }
        __syncthreads();   // (5)
        if (s2_kh == 0) {
            const float* sc = sm + OFF_SCR + s2_m * SCP + s2_h0;
            float4 r0 = *reinterpret_cast<const float4*>(sc);
            float4 r1 = *reinterpret_cast<const float4*>(sc + 4);
            rowv[0] += r0.x; rowv[1] += r0.y; rowv[2] += r0.z; rowv[3] += r0.w;
            rowv[4] += r1.x; rowv[5] += r1.y; rowv[6] += r1.z; rowv[7] += r1.w;
            const size_t bh = (size_t)b * HDIM;
            #pragma unroll
            for (int j = 0; j < 8; j++) {
                int h = s2_h0 + j;
                float v = rowv[j] + sm[OFF_B2 + h];
                out[((bh + h) * NTOT + rowi) * NTOT + j0 + s2_m] = v;
                if (wrM && vbzero)
                    out[((bh + h) * NTOT + (j0 + s2_m)) * NTOT + rowi] = v - corr[j];
            }
        }

        // ---- fallback mirror path (vb1 != 0): delta = sum (gelu(-s)-v1)*vw2 ----
        if (wrM && !vbzero) {
            float dp[8];
            {
                float4 dmv = *reinterpret_cast<float4*>(sm + OFF_DLM4 + s2_m * 4);
                const float* vB = sm + OFF_VP1 + s2_kh * 32 * PP + 2 * s2_m;
                const float* wB = sm + OFF_VW2 + s2_kh * 2048 + 2 * s2_h0;
                ull D[8];
                #pragma unroll
                for (int j = 0; j < 8; j++) D[j] = 0ull;
                for (int i = 0; i < 32; i++) {
                    int kp = s2_kh * 32 + i;
                    float2 w0 = *reinterpret_cast<float2*>(sm + OFF_VW1 + 2 * kp);
                    float2 w1 = *reinterpret_cast<float2*>(sm + OFF_VW1 + 128 + 2 * kp);
                    float2 w2 = *reinterpret_cast<float2*>(sm + OFF_VW1 + 256 + 2 * kp);
                    float2 vb = *reinterpret_cast<float2*>(sm + OFF_VB1 + 2 * kp);
                    float sx = dmv.x * w0.x + dmv.y * w1.x + dmv.z * w2.x + vb.x;
                    float sy = dmv.x * w0.y + dmv.y * w1.y + dmv.z * w2.y + vb.y;
                    float2 pv = u2f2(*reinterpret_cast<const ull*>(vB + i * PP));
                    ull dq = f2pack(fast_gelu(2.0f * vb.x - sx) - pv.x,
                                    fast_gelu(2.0f * vb.y - sy) - pv.y);
                    ulonglong2 v01 = *reinterpret_cast<const ulonglong2*>(wB + i * 64);
                    ulonglong2 v23 = *reinterpret_cast<const ulonglong2*>(wB + i * 64 + 4);
                    ulonglong2 v45 = *reinterpret_cast<const ulonglong2*>(wB + i * 64 + 8);
                    ulonglong2 v67 = *reinterpret_cast<const ulonglong2*>(wB + i * 64 + 12);
                    D[0] = ffma2(dq, v01.x, D[0]); D[1] = ffma2(dq, v01.y, D[1]);
                    D[2] = ffma2(dq, v23.x, D[2]); D[3] = ffma2(dq, v23.y, D[3]);
                    D[4] = ffma2(dq, v45.x, D[4]); D[5] = ffma2(dq, v45.y, D[5]);
                    D[6] = ffma2(dq, v67.x, D[6]); D[7] = ffma2(dq, v67.y, D[7]);
                }
                #pragma unroll
                for (int j = 0; j < 8; j++) dp[j] = hadd2(D[j]);
            }
            __syncthreads();   // (6) scratch free
            if (s2_kh) {
                float* sc = sm + OFF_SCR + s2_m * SCP + s2_h0;
                *reinterpret_cast<float4*>(sc)     = make_float4(dp[0], dp[1], dp[2], dp[3]);
                *reinterpret_cast<float4*>(sc + 4) = make_float4(dp[4], dp[5], dp[6], dp[7]);
            }
            __syncthreads();   // (7)
            if (s2_kh == 0) {
                const float* sc = sm + OFF_SCR + s2_m * SCP + s2_h0;
                float4 r0 = *reinterpret_cast<const float4*>(sc);
                float4 r1 = *reinterpret_cast<const float4*>(sc + 4);
                dp[0] += r0.x; dp[1] += r0.y; dp[2] += r0.z; dp[3] += r0.w;
                dp[4] += r1.x; dp[5] += r1.y; dp[6] += r1.z; dp[7] += r1.w;
                const size_t bh = (size_t)b * HDIM;
                #pragma unroll
                for (int j = 0; j < 8; j++) {
                    int h = s2_h0 + j;
                    float v = rowv[j] + dp[j] + sm[OFF_B2 + h];
                    out[((bh + h) * NTOT + (j0 + s2_m)) * NTOT + rowi] = v;
                }
            }
        }
        // loop-around ordering: DLM4 rewritten only after next tile's barrier (1);
        // GP/VP1 after (2); scratch after (5)/(7).
    }
}

extern "C" void kernel_launch(void* const* d_in, const int* in_sizes, int n_in,
                              void* d_out, int out_size) {
    const float* pos    = (const float*)d_in[0];
    const int*   etype  = (const int*)d_in[1];
    const float* means  = (const float*)d_in[3];
    const float* stds   = (const float*)d_in[4];
    const float* mul_w  = (const float*)d_in[5];
    const float* bias_w = (const float*)d_in[6];
    const float* ow1    = (const float*)d_in[7];
    const float* ob1    = (const float*)d_in[8];
    const float* ow2    = (const float*)d_in[9];
    const float* ob2    = (const float*)d_in[10];
    const float* vw1    = (const float*)d_in[11];
    const float* vb1    = (const float*)d_in[12];
    const float* vw2    = (const float*)d_in[13];
    const float* vb2    = (const float*)d_in[14];
    float* out = (float*)d_out;
    int nE = in_sizes[5];   // mul_w element count (E)

    cudaFuncSetAttribute(fused_distbias_kernel,
                         cudaFuncAttributeMaxDynamicSharedMemorySize, SMEM_BYTES);

    {
        size_t total = (size_t)BDIM * HDIM * PLEN * (PLEN / 4);
        int grid = (int)((total + 255) / 256);
        zero_pp_kernel<<<grid, 256>>>(out);
    }

    fused_distbias_kernel<<<148, 512, SMEM_BYTES>>>(
        pos, etype, mul_w, bias_w, means, stds,
        ow1, ob1, ow2, ob2, vw1, vb1, vw2, vb2, out, nE);
}

// round 12
// speedup vs baseline: 1.2407x; 1.0567x over previous
#include <cuda_runtime.h>
#include <math.h>

typedef unsigned long long ull;

#define BDIM 2
#define NTOT 1024
#define PLEN 768
#define LLEN 256
#define KDIM 128
#define HDIM 32

constexpr int PP = 132;                          // pair-major row pitch (floats)
constexpr int NT_LP = BDIM * PLEN * 4;           // 6144
constexpr int NT_LL_SLOW = BDIM * LLEN * 4;      // 2048
constexpr int NTILES_SLOW = NT_LL_SLOW + NT_LP;  // 8192
constexpr int NT_LL_FAST = BDIM * 640;           // 1280
constexpr int NTILES_FAST = NT_LL_FAST + NT_LP;  // 7424

constexpr int GRIDX = 148;
constexpr int ZTOT_F4 = BDIM * HDIM * PLEN * (PLEN / 4);   // 9437184
constexpr int NZI = (ZTOT_F4 + 3 * GRIDX * 512 - 1) / (3 * GRIDX * 512);  // 42

// shared memory layout (float offsets)
constexpr int OFF_OW1  = 0;                      // 16384
constexpr int OFF_OW2  = 16384;                  // 4096
constexpr int OFF_VW2  = 20480;                  // 4096
constexpr int OFF_TVV  = 24576;                  // 96
constexpr int OFF_VW1  = 24672;                  // 384
constexpr int OFF_VB1  = 25056;                  // 128
constexpr int OFF_OB1  = 25184;                  // 128
constexpr int OFF_MEAN = 25312;                  // 128
constexpr int OFF_ISTD = 25440;                  // 128
constexpr int OFF_COEF = 25568;                  // 128
constexpr int OFF_B2   = 25696;                  // 32
constexpr int OFF_FLAG = 25728;                  // 4
constexpr int OFF_DLM4 = 25732;                  // 512 (two buffers of 256)
constexpr int OFF_GP   = 26244;                  // 8448 (byte 104976? 26244*4=104976, %16==0)
constexpr int OFF_VP1  = OFF_GP + 64 * PP;       // 34692
constexpr int OFF_H1P  = OFF_VP1 + 64 * PP;      // 43140
constexpr int SCP = 36;
constexpr int SCSTRIDE = 64 * SCP;               // 2304
constexpr int OFF_SCR  = OFF_H1P + 64 * PP;      // 51588
constexpr int SMEM_FLOATS = OFF_SCR + SCSTRIDE;  // 53892
constexpr int SMEM_BYTES  = SMEM_FLOATS * 4;     // 215568

__device__ __forceinline__ ull ffma2(ull a, ull b, ull c) {
    ull d; asm("fma.rn.f32x2 %0,%1,%2,%3;" : "=l"(d) : "l"(a), "l"(b), "l"(c)); return d;
}
__device__ __forceinline__ float2 u2f2(ull v) {
    float2 f; asm("mov.b64 {%0,%1},%2;" : "=f"(f.x), "=f"(f.y) : "l"(v)); return f;
}
__device__ __forceinline__ ull f2pack(float x, float y) {
    ull r; asm("mov.b64 %0,{%1,%2};" : "=l"(r) : "f"(x), "f"(y)); return r;
}
__device__ __forceinline__ float hadd2(ull v) { float2 f = u2f2(v); return f.x + f.y; }

// exact-form gelu via A&S 7.1.26 erf (|abs err| <= 1.5e-7), branchless
__device__ __forceinline__ float fast_gelu(float x) {
    float y  = x * 0.70710678118654752f;
    float ax = fabsf(y);
    float t  = __fdividef(1.0f, fmaf(0.3275911f, ax, 1.0f));
    float p  = fmaf(t, 1.061405429f, -1.453152027f);
    p = fmaf(t, p, 1.421413741f);
    p = fmaf(t, p, -0.284496736f);
    p = fmaf(t, p, 0.254829592f);
    p *= t;
    float e = __expf(-ax * ax);
    float erfv = copysignf(fmaf(-p, e, 1.0f), y);
    return 0.5f * x * (1.0f + erfv);
}

__device__ __forceinline__ void decode_tile(int t, int fastmode,
                                            int& b, int& rowi, int& j0, int& wrM) {
    if (fastmode) {
        if (t < NT_LL_FAST) {
            b = t / 640; int r = t - b * 640;
            if (r < 256) { rowi = r; j0 = r & 192; wrM = 0; }
            else {
                int r2 = r - 256; int pr = r2 >> 6;
                int br = (pr < 3) ? 0 : ((pr < 5) ? 1 : 2);
                int bc = (pr == 0) ? 1 : ((pr == 1 || pr == 3) ? 2 : 3);
                rowi = br * 64 + (r2 & 63); j0 = bc * 64; wrM = 1;
            }
        } else {
            int u = t - NT_LL_FAST; b = u / 3072; int r = u - b * 3072;
            rowi = LLEN + (r >> 2); j0 = (r & 3) << 6; wrM = 1;
        }
    } else {
        if (t < NT_LL_SLOW) {
            b = t >> 10; int r = t & 1023;
            rowi = r >> 2; j0 = (r & 3) << 6; wrM = 0;
        } else {
            int u = t - NT_LL_SLOW; b = u / 3072; int r = u - b * 3072;
            rowi = LLEN + (r >> 2); j0 = (r & 3) << 6; wrM = 1;
        }
    }
}

__device__ __forceinline__ float4 load_meta(const float* pos, const int* etype,
                                            const float* mw, const float* bw,
                                            int b, int rowi, int j) {
    const float* pj = pos + ((size_t)b * NTOT + j) * 3;
    const float* pi = pos + ((size_t)b * NTOT + rowi) * 3;
    float d0 = pj[0] - pi[0];
    float d1 = pj[1] - pi[1];
    float d2 = pj[2] - pi[2];
    float d = 1.0f / (d0 * d0 + d1 * d1 + d2 * d2 + 1.0f);
    int e = etype[((size_t)b * NTOT + rowi) * NTOT + j];
    return make_float4(d0, d1, d2, mw[e] * d + bw[e]);
}

__global__ __launch_bounds__(512, 1)
void fused_distbias_kernel(
    const float* __restrict__ pos,
    const int*   __restrict__ etype,
    const float* __restrict__ mw,
    const float* __restrict__ bw,
    const float* __restrict__ means,
    const float* __restrict__ stds,
    const float* __restrict__ ow1,
    const float* __restrict__ ob1,
    const float* __restrict__ ow2,
    const float* __restrict__ ob2,
    const float* __restrict__ vw1,
    const float* __restrict__ vb1,
    const float* __restrict__ vw2,
    const float* __restrict__ vb2,
    float* __restrict__ out,
    int nE)
{
    extern __shared__ float sm[];
    const int tid = threadIdx.x;
    int* iflags = reinterpret_cast<int*>(sm + OFF_FLAG);

    // ---- Stage weights (pair-major), once per block ----
    for (int i = tid; i < 64 * 128; i += 512) {
        int kp = i >> 7, c = i & 127;
        sm[OFF_OW1 + kp * 256 + 2 * c]     = ow1[(2 * kp) * KDIM + c];
        sm[OFF_OW1 + kp * 256 + 2 * c + 1] = ow1[(2 * kp + 1) * KDIM + c];
    }
    for (int i = tid; i < 64 * 32; i += 512) {
        int kp = i >> 5, h = i & 31;
        sm[OFF_OW2 + kp * 64 + 2 * h]     = ow2[(2 * kp) * HDIM + h];
        sm[OFF_OW2 + kp * 64 + 2 * h + 1] = ow2[(2 * kp + 1) * HDIM + h];
        sm[OFF_VW2 + kp * 64 + 2 * h]     = vw2[(2 * kp) * HDIM + h];
        sm[OFF_VW2 + kp * 64 + 2 * h + 1] = vw2[(2 * kp + 1) * HDIM + h];
    }
    if (tid < 3 * KDIM) sm[OFF_VW1 + tid] = vw1[tid];
    if (tid < KDIM) {
        sm[OFF_VB1 + tid] = vb1[tid];
        sm[OFF_OB1 + tid] = ob1[tid];
        float s  = fabsf(stds[tid]) + 1e-5f;
        float is = 1.0f / s;
        sm[OFF_MEAN + tid] = means[tid];
        sm[OFF_ISTD + tid] = is;
        sm[OFF_COEF + tid] = is * (1.0f / sqrtf(2.0f * 3.14159f));
    }
    if (tid < HDIM) sm[OFF_B2 + tid] = ob2[tid] + vb2[tid];
    if (tid == 0) { iflags[0] = 1; iflags[1] = 1; }
    __syncthreads();
    if (tid < KDIM && vb1[tid] != 0.0f) atomicAnd(&iflags[0], 0);
    {
        float m0v = mw[0], b0v = bw[0];
        for (int i = tid; i < nE; i += 512)
            if (mw[i] != m0v || bw[i] != b0v) atomicAnd(&iflags[1], 0);
    }
    __syncthreads();
    // T[d][h] = vw1 @ vw2
    if (tid < 96) {
        int d = tid >> 5, h = tid & 31;
        float s = 0.0f;
        for (int kp = 0; kp < 64; kp++) {
            float2 a = *reinterpret_cast<float2*>(sm + OFF_VW1 + d * 128 + 2 * kp);
            float2 w = *reinterpret_cast<float2*>(sm + OFF_VW2 + kp * 64 + 2 * h);
            s += a.x * w.x + a.y * w.y;
        }
        sm[OFF_TVV + d * 32 + h] = s;
    }
    const int vbzero = iflags[0];
    const int fastmode = iflags[0] & iflags[1];
    const int ntiles = fastmode ? NTILES_FAST : NTILES_SLOW;

    // ---- per-thread decompositions (512 threads, 16 warps) ----
    const int gm  = tid & 63;
    const int gkc = tid >> 6;
    const int s1_wid = tid >> 5, s1_lane = tid & 31;
    const int s1_wm = s1_wid & 3, s1_wn = s1_wid >> 2;
    const int s1_mg = s1_lane >> 3, s1_ng = s1_lane & 7;
    const int s1_mbase = s1_wm * 16 + s1_mg * 4;
    const int s1_cbase = s1_wn * 32;
    const int s1_npA   = s1_wn * 16 + s1_ng;
    const int s2_hg = (tid >> 5) & 3;
    const int s2_kh = (tid >> 7) & 1;
    const int s2_mh = tid >> 8;
    const int s2_h0 = s2_hg * 8;
    const int s2_m  = s2_mh * 32 + (tid & 31);

    // ---- first tile's metadata (synchronous) ----
    {
        int b0, ri0, j00, w0;
        decode_tile((int)blockIdx.x, fastmode, b0, ri0, j00, w0);
        if ((int)blockIdx.x < ntiles && tid < 64) {
            float4 m = load_meta(pos, etype, mw, bw, b0, ri0, j00 + tid);
            *reinterpret_cast<float4*>(sm + OFF_DLM4 + tid * 4) = m;
        }
    }
    __syncthreads();

    int cur = 0;
    int zi = 0;
    for (int t = blockIdx.x; t < ntiles; t += gridDim.x, zi++) {
        int b, rowi, j0, wrM;
        decode_tile(t, fastmode, b, rowi, j0, wrM);

        // ---- background zero-fill of protein-protein quadrant ----
        if (zi < NZI) {
            #pragma unroll
            for (int zz = 0; zz < 3; zz++) {
                int idx = ((zi * 3 + zz) * GRIDX + (int)blockIdx.x) * 512 + tid;
                if (idx < ZTOT_F4) {
                    int jq = idx % 192;
                    int r  = idx / 192;
                    int ip = r % 768;
                    int bhh = r / 768;
                    size_t addr = (((size_t)bhh << 10) + 256 + ip) * 1024 + 256 + 4 * jq;
                    *reinterpret_cast<float4*>(out + addr) = make_float4(0.f, 0.f, 0.f, 0.f);
                }
            }
        }

        // ---- prefetch next tile's metadata (hidden under gaussian) ----
        const int tn = t + gridDim.x;
        float4 pf;
        const bool havePf = (tn < ntiles) && (tid < 64);
        if (havePf) {
            int bn, rin, j0n, wn;
            decode_tile(tn, fastmode, bn, rin, j0n, wn);
            pf = load_meta(pos, etype, mw, bw, bn, rin, j0n + tid);
        }

        // ---- (G) gaussian + vector-MLP hidden ----
        {
            float4 dm = *reinterpret_cast<float4*>(sm + OFF_DLM4 + cur * 256 + gm * 4);
            #pragma unroll
            for (int i = 0; i < 8; i++) {
                int kp = gkc * 8 + i;
                float2 mn = *reinterpret_cast<float2*>(sm + OFF_MEAN + 2 * kp);
                float2 is = *reinterpret_cast<float2*>(sm + OFF_ISTD + 2 * kp);
                float2 cf = *reinterpret_cast<float2*>(sm + OFF_COEF + 2 * kp);
                float2 w0 = *reinterpret_cast<float2*>(sm + OFF_VW1 + 2 * kp);
                float2 w1 = *reinterpret_cast<float2*>(sm + OFF_VW1 + 128 + 2 * kp);
                float2 w2 = *reinterpret_cast<float2*>(sm + OFF_VW1 + 256 + 2 * kp);
                float2 vb = *reinterpret_cast<float2*>(sm + OFF_VB1 + 2 * kp);
                float tx = (dm.w - mn.x) * is.x;
                float ty = (dm.w - mn.y) * is.y;
                float2 g = make_float2(__expf(-0.5f * tx * tx) * cf.x,
                                       __expf(-0.5f * ty * ty) * cf.y);
                float sx = dm.x * w0.x + dm.y * w1.x + dm.z * w2.x + vb.x;
                float sy = dm.x * w0.y + dm.y * w1.y + dm.z * w2.y + vb.y;
                float2 v1 = make_float2(fast_gelu(sx), fast_gelu(sy));
                *reinterpret_cast<float2*>(sm + OFF_GP  + kp * PP + 2 * gm) = g;
                *reinterpret_cast<float2*>(sm + OFF_VP1 + kp * PP + 2 * gm) = v1;
            }
        }
        // publish prefetched metadata into the alternate DLM4 buffer
        if (havePf)
            *reinterpret_cast<float4*>(sm + OFF_DLM4 + (cur ^ 1) * 256 + tid * 4) = pf;
        __syncthreads();   // (2)

        // ---- (S1) H1 = gelu(G @ ow1 + ob1) -> H1P (separate buffer, no extra barrier) ----
        {
            ull acc[4][4];
            #pragma unroll
            for (int r = 0; r < 4; r++)
                #pragma unroll
                for (int j = 0; j < 4; j++) acc[r][j] = 0ull;
            const float* gpB = sm + OFF_GP + 2 * s1_mbase;
            const float* w1B = sm + OFF_OW1 + 2 * s1_cbase + 4 * s1_ng;
            #pragma unroll 4
            for (int kp = 0; kp < 64; kp++) {
                ulonglong2 g01 = *reinterpret_cast<const ulonglong2*>(gpB + kp * PP);
                ulonglong2 g23 = *reinterpret_cast<const ulonglong2*>(gpB + kp * PP + 4);
                ulonglong2 wA  = *reinterpret_cast<const ulonglong2*>(w1B + kp * 256);
                ulonglong2 wB  = *reinterpret_cast<const ulonglong2*>(w1B + kp * 256 + 32);
                acc[0][0] = ffma2(g01.x, wA.x, acc[0][0]);
                acc[0][1] = ffma2(g01.x, wA.y, acc[0][1]);
                acc[0][2] = ffma2(g01.x, wB.x, acc[0][2]);
                acc[0][3] = ffma2(g01.x, wB.y, acc[0][3]);
                acc[1][0] = ffma2(g01.y, wA.x, acc[1][0]);
                acc[1][1] = ffma2(g01.y, wA.y, acc[1][1]);
                acc[1][2] = ffma2(g01.y, wB.x, acc[1][2]);
                acc[1][3] = ffma2(g01.y, wB.y, acc[1][3]);
                acc[2][0] = ffma2(g23.x, wA.x, acc[2][0]);
                acc[2][1] = ffma2(g23.x, wA.y, acc[2][1]);
                acc[2][2] = ffma2(g23.x, wB.x, acc[2][2]);
                acc[2][3] = ffma2(g23.x, wB.y, acc[2][3]);
                acc[3][0] = ffma2(g23.y, wA.x, acc[3][0]);
                acc[3][1] = ffma2(g23.y, wA.y, acc[3][1]);
                acc[3][2] = ffma2(g23.y, wB.x, acc[3][2]);
                acc[3][3] = ffma2(g23.y, wB.y, acc[3][3]);
            }
            float2 obA = *reinterpret_cast<float2*>(sm + OFF_OB1 + s1_cbase + 2 * s1_ng);
            float2 obB = *reinterpret_cast<float2*>(sm + OFF_OB1 + s1_cbase + 2 * s1_ng + 16);
            #pragma unroll
            for (int r = 0; r < 4; r++) {
                int m = s1_mbase + r;
                float2 hA = make_float2(fast_gelu(hadd2(acc[r][0]) + obA.x),
                                        fast_gelu(hadd2(acc[r][1]) + obA.y));
                float2 hB = make_float2(fast_gelu(hadd2(acc[r][2]) + obB.x),
                                        fast_gelu(hadd2(acc[r][3]) + obB.y));
                *reinterpret_cast<float2*>(sm + OFF_H1P + s1_npA * PP + 2 * m) = hA;
                *reinterpret_cast<float2*>(sm + OFF_H1P + (s1_npA + 8) * PP + 2 * m) = hB;
            }
        }
        __syncthreads();   // (4)

        // ---- (S2) merged contraction R = H1@ow2 + V1@vw2; k-split 2 ----
        float rowv[8];
        {
            const float* hB = sm + OFF_H1P + s2_kh * 32 * PP + 2 * s2_m;
            const float* vB = sm + OFF_VP1 + s2_kh * 32 * PP + 2 * s2_m;
            const float* oB = sm + OFF_OW2 + s2_kh * 2048 + 2 * s2_h0;
            const float* wB = sm + OFF_VW2 + s2_kh * 2048 + 2 * s2_h0;
            ull R[8];
            #pragma unroll
            for (int j = 0; j < 8; j++) R[j] = 0ull;
            #pragma unroll 4
            for (int i = 0; i < 32; i++) {
                ull hp = *reinterpret_cast<const ull*>(hB + i * PP);
                ull vp = *reinterpret_cast<const ull*>(vB + i * PP);
                ulonglong2 o01 = *reinterpret_cast<const ulonglong2*>(oB + i * 64);
                ulonglong2 o23 = *reinterpret_cast<const ulonglong2*>(oB + i * 64 + 4);
                ulonglong2 o45 = *reinterpret_cast<const ulonglong2*>(oB + i * 64 + 8);
                ulonglong2 o67 = *reinterpret_cast<const ulonglong2*>(oB + i * 64 + 12);
                R[0] = ffma2(hp, o01.x, R[0]); R[1] = ffma2(hp, o01.y, R[1]);
                R[2] = ffma2(hp, o23.x, R[2]); R[3] = ffma2(hp, o23.y, R[3]);
                R[4] = ffma2(hp, o45.x, R[4]); R[5] = ffma2(hp, o45.y, R[5]);
                R[6] = ffma2(hp, o67.x, R[6]); R[7] = ffma2(hp, o67.y, R[7]);
                ulonglong2 v01 = *reinterpret_cast<const ulonglong2*>(wB + i * 64);
                ulonglong2 v23 = *reinterpret_cast<const ulonglong2*>(wB + i * 64 + 4);
                ulonglong2 v45 = *reinterpret_cast<const ulonglong2*>(wB + i * 64 + 8);
                ulonglong2 v67 = *reinterpret_cast<const ulonglong2*>(wB + i * 64 + 12);
                R[0] = ffma2(vp, v01.x, R[0]); R[1] = ffma2(vp, v01.y, R[1]);
                R[2] = ffma2(vp, v23.x, R[2]); R[3] = ffma2(vp, v23.y, R[3]);
                R[4] = ffma2(vp, v45.x, R[4]); R[5] = ffma2(vp, v45.y, R[5]);
                R[6] = ffma2(vp, v67.x, R[6]); R[7] = ffma2(vp, v67.y, R[7]);
            }
            #pragma unroll
            for (int j = 0; j < 8; j++) rowv[j] = hadd2(R[j]);
        }
        float corr[8];
        if (wrM && vbzero && s2_kh == 0) {
            float4 dmv = *reinterpret_cast<float4*>(sm + OFF_DLM4 + cur * 256 + s2_m * 4);
            #pragma unroll
            for (int j = 0; j < 8; j++) {
                int h = s2_h0 + j;
                corr[j] = dmv.x * sm[OFF_TVV + h]
                        + dmv.y * sm[OFF_TVV + 32 + h]
                        + dmv.z * sm[OFF_TVV + 64 + h];
            }
        }
        if (s2_kh) {
            float* sc = sm + OFF_SCR + s2_m * SCP + s2_h0;
            *reinterpret_cast<float4*>(sc)     = make_float4(rowv[0], rowv[1], rowv[2], rowv[3]);
            *reinterpret_cast<float4*>(sc + 4) = make_float4(rowv[4], rowv[5], rowv[6], rowv[7]);
        }
        __syncthreads();   // (5)
        if (s2_kh == 0) {
            const float* sc = sm + OFF_SCR + s2_m * SCP + s2_h0;
            float4 r0 = *reinterpret_cast<const float4*>(sc);
            float4 r1 = *reinterpret_cast<const float4*>(sc + 4);
            rowv[0] += r0.x; rowv[1] += r0.y; rowv[2] += r0.z; rowv[3] += r0.w;
            rowv[4] += r1.x; rowv[5] += r1.y; rowv[6] += r1.z; rowv[7] += r1.w;
            const size_t bh = (size_t)b * HDIM;
            #pragma unroll
            for (int j = 0; j < 8; j++) {
                int h = s2_h0 + j;
                float v = rowv[j] + sm[OFF_B2 + h];
                out[((bh + h) * NTOT + rowi) * NTOT + j0 + s2_m] = v;
                if (wrM && vbzero)
                    out[((bh + h) * NTOT + (j0 + s2_m)) * NTOT + rowi] = v - corr[j];
            }
        }

        // ---- fallback mirror path (vb1 != 0) ----
        if (wrM && !vbzero) {
            float dp[8];
            {
                float4 dmv = *reinterpret_cast<float4*>(sm + OFF_DLM4 + cur * 256 + s2_m * 4);
                const float* vB = sm + OFF_VP1 + s2_kh * 32 * PP + 2 * s2_m;
                const float* wB = sm + OFF_VW2 + s2_kh * 2048 + 2 * s2_h0;
                ull D[8];
                #pragma unroll
                for (int j = 0; j < 8; j++) D[j] = 0ull;
                for (int i = 0; i < 32; i++) {
                    int kp = s2_kh * 32 + i;
                    float2 w0 = *reinterpret_cast<float2*>(sm + OFF_VW1 + 2 * kp);
                    float2 w1 = *reinterpret_cast<float2*>(sm + OFF_VW1 + 128 + 2 * kp);
                    float2 w2 = *reinterpret_cast<float2*>(sm + OFF_VW1 + 256 + 2 * kp);
                    float2 vb = *reinterpret_cast<float2*>(sm + OFF_VB1 + 2 * kp);
                    float sx = dmv.x * w0.x + dmv.y * w1.x + dmv.z * w2.x + vb.x;
                    float sy = dmv.x * w0.y + dmv.y * w1.y + dmv.z * w2.y + vb.y;
                    float2 pv = u2f2(*reinterpret_cast<const ull*>(vB + i * PP));
                    ull dq = f2pack(fast_gelu(2.0f * vb.x - sx) - pv.x,
                                    fast_gelu(2.0f * vb.y - sy) - pv.y);
                    ulonglong2 v01 = *reinterpret_cast<const ulonglong2*>(wB + i * 64);
                    ulonglong2 v23 = *reinterpret_cast<const ulonglong2*>(wB + i * 64 + 4);
                    ulonglong2 v45 = *reinterpret_cast<const ulonglong2*>(wB + i * 64 + 8);
                    ulonglong2 v67 = *reinterpret_cast<const ulonglong2*>(wB + i * 64 + 12);
                    D[0] = ffma2(dq, v01.x, D[0]); D[1] = ffma2(dq, v01.y, D[1]);
                    D[2] = ffma2(dq, v23.x, D[2]); D[3] = ffma2(dq, v23.y, D[3]);
                    D[4] = ffma2(dq, v45.x, D[4]); D[5] = ffma2(dq, v45.y, D[5]);
                    D[6] = ffma2(dq, v67.x, D[6]); D[7] = ffma2(dq, v67.y, D[7]);
                }
                #pragma unroll
                for (int j = 0; j < 8; j++) dp[j] = hadd2(D[j]);
            }
            __syncthreads();   // (6)
            if (s2_kh) {
                float* sc = sm + OFF_SCR + s2_m * SCP + s2_h0;
                *reinterpret_cast<float4*>(sc)     = make_float4(dp[0], dp[1], dp[2], dp[3]);
                *reinterpret_cast<float4*>(sc + 4) = make_float4(dp[4], dp[5], dp[6], dp[7]);
            }
            __syncthreads();   // (7)
            if (s2_kh == 0) {
                const float* sc = sm + OFF_SCR + s2_m * SCP + s2_h0;
                float4 r0 = *reinterpret_cast<const float4*>(sc);
                float4 r1 = *reinterpret_cast<const float4*>(sc + 4);
                dp[0] += r0.x; dp[1] += r0.y; dp[2] += r0.z; dp[3] += r0.w;
                dp[4] += r1.x; dp[5] += r1.y; dp[6] += r1.z; dp[7] += r1.w;
                const size_t bh = (size_t)b * HDIM;
                #pragma unroll
                for (int j = 0; j < 8; j++) {
                    int h = s2_h0 + j;
                    float v = rowv[j] + dp[j] + sm[OFF_B2 + h];
                    out[((bh + h) * NTOT + (j0 + s2_m)) * NTOT + rowi] = v;
                }
            }
        }
        cur ^= 1;
        // ordering: GP/VP1 rewritten by next gaussian only after (5)/(7) — all
        // S1/S2 reads of them completed before those barriers. DLM4[cur^1] written
        // before (2); read only next tile. Scratch reused after next (4).
    }
}

extern "C" void kernel_launch(void* const* d_in, const int* in_sizes, int n_in,
                              void* d_out, int out_size) {
    const float* pos    = (const float*)d_in[0];
    const int*   etype  = (const int*)d_in[1];
    const float* means  = (const float*)d_in[3];
    const float* stds   = (const float*)d_in[4];
    const float* mul_w  = (const float*)d_in[5];
    const float* bias_w = (const float*)d_in[6];
    const float* ow1    = (const float*)d_in[7];
    const float* ob1    = (const float*)d_in[8];
    const float* ow2    = (const float*)d_in[9];
    const float* ob2    = (const float*)d_in[10];
    const float* vw1    = (const float*)d_in[11];
    const float* vb1    = (const float*)d_in[12];
    const float* vw2    = (const float*)d_in[13];
    const float* vb2    = (const float*)d_in[14];
    float* out = (float*)d_out;
    int nE = in_sizes[5];

    cudaFuncSetAttribute(fused_distbias_kernel,
                         cudaFuncAttributeMaxDynamicSharedMemorySize, SMEM_BYTES);

    fused_distbias_kernel<<<GRIDX, 512, SMEM_BYTES>>>(
        pos, etype, mul_w, bias_w, means, stds,
        ow1, ob1, ow2, ob2, vw1, vb1, vw2, vb2, out, nE);
}

// round 13
// speedup vs baseline: 2.5435x; 2.0500x over previous
#include <cuda_runtime.h>
#include <math.h>

typedef unsigned long long ull;

#define BDIM 2
#define NTOT 1024
#define PLEN 768
#define LLEN 256
#define KDIM 128
#define HDIM 32
#define TABN 32768

constexpr int PP = 132;                          // pair-major row pitch (floats)
constexpr int NT_LP = BDIM * PLEN * 4;           // 6144
constexpr int NT_LL_SLOW = BDIM * LLEN * 4;      // 2048
constexpr int NTILES_SLOW = NT_LL_SLOW + NT_LP;  // 8192
constexpr int NT_LL_FAST = BDIM * 640;           // 1280
constexpr int NTILES_FAST = NT_LL_FAST + NT_LP;  // 7424
constexpr int NTAB_TILES = TABN / 64;            // 512

constexpr int GRIDX = 148;
constexpr int ZTOT_F4 = BDIM * HDIM * PLEN * (PLEN / 4);   // 9437184
constexpr int NZI = (ZTOT_F4 + 3 * GRIDX * 512 - 1) / (3 * GRIDX * 512);  // 42

// shared memory layout (float offsets)
constexpr int OFF_OW1  = 0;                      // 16384
constexpr int OFF_OW2  = 16384;                  // 4096
constexpr int OFF_VW2  = 20480;                  // 4096
constexpr int OFF_TVV  = 24576;                  // 96
constexpr int OFF_VW1  = 24672;                  // 384
constexpr int OFF_VB1  = 25056;                  // 128
constexpr int OFF_OB1  = 25184;                  // 128
constexpr int OFF_MEAN = 25312;                  // 128
constexpr int OFF_ISTD = 25440;                  // 128
constexpr int OFF_COEF = 25568;                  // 128
constexpr int OFF_B2   = 25696;                  // 32
constexpr int OFF_FLAG = 25728;                  // 4 ints
constexpr int OFF_DLM4 = 25732;                  // 512 (two buffers of 256)
constexpr int OFF_GP   = 26244;                  // 8448
constexpr int OFF_VP1  = OFF_GP + 64 * PP;       // 34692
constexpr int OFF_H1P  = OFF_VP1 + 64 * PP;      // 43140
constexpr int SCP = 36;
constexpr int SCSTRIDE = 64 * SCP;               // 2304
constexpr int OFF_SCR  = OFF_H1P + 64 * PP;      // 51588
constexpr int SMEM_FLOATS = OFF_SCR + SCSTRIDE;  // 53892
constexpr int SMEM_BYTES  = SMEM_FLOATS * 4;     // 215568

// ef lookup table: Phi(x0)[h], built by build_tab_kernel when usable
__device__ __align__(16) float g_tab[TABN * HDIM];

__device__ __forceinline__ ull ffma2(ull a, ull b, ull c) {
    ull d; asm("fma.rn.f32x2 %0,%1,%2,%3;" : "=l"(d) : "l"(a), "l"(b), "l"(c)); return d;
}
__device__ __forceinline__ float2 u2f2(ull v) {
    float2 f; asm("mov.b64 {%0,%1},%2;" : "=f"(f.x), "=f"(f.y) : "l"(v)); return f;
}
__device__ __forceinline__ ull f2pack(float x, float y) {
    ull r; asm("mov.b64 %0,{%1,%2};" : "=l"(r) : "f"(x), "f"(y)); return r;
}
__device__ __forceinline__ float hadd2(ull v) { float2 f = u2f2(v); return f.x + f.y; }

// exact-form gelu via A&S 7.1.26 erf (|abs err| <= 1.5e-7), branchless
__device__ __forceinline__ float fast_gelu(float x) {
    float y  = x * 0.70710678118654752f;
    float ax = fabsf(y);
    float t  = __fdividef(1.0f, fmaf(0.3275911f, ax, 1.0f));
    float p  = fmaf(t, 1.061405429f, -1.453152027f);
    p = fmaf(t, p, 1.421413741f);
    p = fmaf(t, p, -0.284496736f);
    p = fmaf(t, p, 0.254829592f);
    p *= t;
    float e = __expf(-ax * ax);
    float erfv = copysignf(fmaf(-p, e, 1.0f), y);
    return 0.5f * x * (1.0f + erfv);
}

__device__ __forceinline__ void decode_tile(int t, int fastmode,
                                            int& b, int& rowi, int& j0, int& wrM) {
    if (fastmode) {
        if (t < NT_LL_FAST) {
            b = t / 640; int r = t - b * 640;
            if (r < 256) { rowi = r; j0 = r & 192; wrM = 0; }
            else {
                int r2 = r - 256; int pr = r2 >> 6;
                int br = (pr < 3) ? 0 : ((pr < 5) ? 1 : 2);
                int bc = (pr == 0) ? 1 : ((pr == 1 || pr == 3) ? 2 : 3);
                rowi = br * 64 + (r2 & 63); j0 = bc * 64; wrM = 1;
            }
        } else {
            int u = t - NT_LL_FAST; b = u / 3072; int r = u - b * 3072;
            rowi = LLEN + (r >> 2); j0 = (r & 3) << 6; wrM = 1;
        }
    } else {
        if (t < NT_LL_SLOW) {
            b = t >> 10; int r = t & 1023;
            rowi = r >> 2; j0 = (r & 3) << 6; wrM = 0;
        } else {
            int u = t - NT_LL_SLOW; b = u / 3072; int r = u - b * 3072;
            rowi = LLEN + (r >> 2); j0 = (r & 3) << 6; wrM = 1;
        }
    }
}

__device__ __forceinline__ float4 load_meta(const float* pos, const int* etype,
                                            const float* mw, const float* bw,
                                            int b, int rowi, int j) {
    const float* pj = pos + ((size_t)b * NTOT + j) * 3;
    const float* pi = pos + ((size_t)b * NTOT + rowi) * 3;
    float d0 = pj[0] - pi[0];
    float d1 = pj[1] - pi[1];
    float d2 = pj[2] - pi[2];
    float d = 1.0f / (d0 * d0 + d1 * d1 + d2 * d2 + 1.0f);
    int e = etype[((size_t)b * NTOT + rowi) * NTOT + j];
    return make_float4(d0, d1, d2, mw[e] * d + bw[e]);
}

// =====================  TABLE BUILD KERNEL  =====================
// Builds g_tab[r][h] = Phi(x0_r)[h] (no bias) for x0 on a uniform grid
// over the achievable x0 range. Runs only when the table path is usable.
__global__ __launch_bounds__(512, 1)
void build_tab_kernel(const float* __restrict__ mw, const float* __restrict__ bw,
                      const float* __restrict__ means, const float* __restrict__ stds,
                      const float* __restrict__ ow1, const float* __restrict__ ob1,
                      const float* __restrict__ ow2, const float* __restrict__ vb1,
                      int nE)
{
    extern __shared__ float sm[];
    const int tid = threadIdx.x;
    int* iflags = reinterpret_cast<int*>(sm + OFF_FLAG);
    if (tid == 0) { iflags[0] = 1; iflags[1] = 1; iflags[2] = 1; }
    __syncthreads();
    if (tid < KDIM && vb1[tid] != 0.0f) atomicAnd(&iflags[0], 0);
    if (tid < KDIM) {
        float s = fabsf(stds[tid]) + 1e-5f;
        if (s < 0.004f) atomicAnd(&iflags[2], 0);
    }
    {
        float m0v = mw[0], b0v = bw[0];
        for (int i = tid; i < nE; i += 512)
            if (mw[i] != m0v || bw[i] != b0v) atomicAnd(&iflags[1], 0);
    }
    __syncthreads();
    if (!(iflags[0] & iflags[1] & iflags[2])) return;

    // stage weights (pair-major) + scalars
    for (int i = tid; i < 64 * 128; i += 512) {
        int kp = i >> 7, c = i & 127;
        sm[OFF_OW1 + kp * 256 + 2 * c]     = ow1[(2 * kp) * KDIM + c];
        sm[OFF_OW1 + kp * 256 + 2 * c + 1] = ow1[(2 * kp + 1) * KDIM + c];
    }
    for (int i = tid; i < 64 * 32; i += 512) {
        int kp = i >> 5, h = i & 31;
        sm[OFF_OW2 + kp * 64 + 2 * h]     = ow2[(2 * kp) * HDIM + h];
        sm[OFF_OW2 + kp * 64 + 2 * h + 1] = ow2[(2 * kp + 1) * HDIM + h];
    }
    if (tid < KDIM) {
        sm[OFF_OB1 + tid] = ob1[tid];
        float s  = fabsf(stds[tid]) + 1e-5f;
        float is = 1.0f / s;
        sm[OFF_MEAN + tid] = means[tid];
        sm[OFF_ISTD + tid] = is;
        sm[OFF_COEF + tid] = is * (1.0f / sqrtf(2.0f * 3.14159f));
    }
    __syncthreads();

    const float m0v = mw[0], b0v = bw[0];
    const float lo = fminf(b0v, m0v + b0v);
    const float span = fmaxf(b0v, m0v + b0v) - lo;
    const float step = span / (float)(TABN - 1);

    const int gm  = tid & 63;
    const int gkc = tid >> 6;
    const int s1_wid = tid >> 5, s1_lane = tid & 31;
    const int s1_wm = s1_wid & 3, s1_wn = s1_wid >> 2;
    const int s1_mg = s1_lane >> 3, s1_ng = s1_lane & 7;
    const int s1_mbase = s1_wm * 16 + s1_mg * 4;
    const int s1_cbase = s1_wn * 32;
    const int s1_npA   = s1_wn * 16 + s1_ng;
    const int s2_hg = (tid >> 5) & 3;
    const int s2_kh = (tid >> 7) & 1;
    const int s2_mh = tid >> 8;
    const int s2_h0 = s2_hg * 8;
    const int s2_m  = s2_mh * 32 + (tid & 31);

    for (int t = blockIdx.x; t < NTAB_TILES; t += gridDim.x) {
        // gaussian features for 64 grid x0 values
        {
            float x0 = lo + (float)(t * 64 + gm) * step;
            #pragma unroll
            for (int i = 0; i < 8; i++) {
                int kp = gkc * 8 + i;
                float2 mn = *reinterpret_cast<float2*>(sm + OFF_MEAN + 2 * kp);
                float2 is = *reinterpret_cast<float2*>(sm + OFF_ISTD + 2 * kp);
                float2 cf = *reinterpret_cast<float2*>(sm + OFF_COEF + 2 * kp);
                float tx = (x0 - mn.x) * is.x;
                float ty = (x0 - mn.y) * is.y;
                float2 g = make_float2(__expf(-0.5f * tx * tx) * cf.x,
                                       __expf(-0.5f * ty * ty) * cf.y);
                *reinterpret_cast<float2*>(sm + OFF_GP + kp * PP + 2 * gm) = g;
            }
        }
        __syncthreads();
        // S1: H1 = gelu(G @ ow1 + ob1)
        {
            ull acc[4][4];
            #pragma unroll
            for (int r = 0; r < 4; r++)
                #pragma unroll
                for (int j = 0; j < 4; j++) acc[r][j] = 0ull;
            const float* gpB = sm + OFF_GP + 2 * s1_mbase;
            const float* w1B = sm + OFF_OW1 + 2 * s1_cbase + 4 * s1_ng;
            #pragma unroll 4
            for (int kp = 0; kp < 64; kp++) {
                ulonglong2 g01 = *reinterpret_cast<const ulonglong2*>(gpB + kp * PP);
                ulonglong2 g23 = *reinterpret_cast<const ulonglong2*>(gpB + kp * PP + 4);
                ulonglong2 wA  = *reinterpret_cast<const ulonglong2*>(w1B + kp * 256);
                ulonglong2 wB  = *reinterpret_cast<const ulonglong2*>(w1B + kp * 256 + 32);
                acc[0][0] = ffma2(g01.x, wA.x, acc[0][0]);
                acc[0][1] = ffma2(g01.x, wA.y, acc[0][1]);
                acc[0][2] = ffma2(g01.x, wB.x, acc[0][2]);
                acc[0][3] = ffma2(g01.x, wB.y, acc[0][3]);
                acc[1][0] = ffma2(g01.y, wA.x, acc[1][0]);
                acc[1][1] = ffma2(g01.y, wA.y, acc[1][1]);
                acc[1][2] = ffma2(g01.y, wB.x, acc[1][2]);
                acc[1][3] = ffma2(g01.y, wB.y, acc[1][3]);
                acc[2][0] = ffma2(g23.x, wA.x, acc[2][0]);
                acc[2][1] = ffma2(g23.x, wA.y, acc[2][1]);
                acc[2][2] = ffma2(g23.x, wB.x, acc[2][2]);
                acc[2][3] = ffma2(g23.x, wB.y, acc[2][3]);
                acc[3][0] = ffma2(g23.y, wA.x, acc[3][0]);
                acc[3][1] = ffma2(g23.y, wA.y, acc[3][1]);
                acc[3][2] = ffma2(g23.y, wB.x, acc[3][2]);
                acc[3][3] = ffma2(g23.y, wB.y, acc[3][3]);
            }
            float2 obA = *reinterpret_cast<float2*>(sm + OFF_OB1 + s1_cbase + 2 * s1_ng);
            float2 obB = *reinterpret_cast<float2*>(sm + OFF_OB1 + s1_cbase + 2 * s1_ng + 16);
            #pragma unroll
            for (int r = 0; r < 4; r++) {
                int m = s1_mbase + r;
                float2 hA = make_float2(fast_gelu(hadd2(acc[r][0]) + obA.x),
                                        fast_gelu(hadd2(acc[r][1]) + obA.y));
                float2 hB = make_float2(fast_gelu(hadd2(acc[r][2]) + obB.x),
                                        fast_gelu(hadd2(acc[r][3]) + obB.y));
                *reinterpret_cast<float2*>(sm + OFF_H1P + s1_npA * PP + 2 * m) = hA;
                *reinterpret_cast<float2*>(sm + OFF_H1P + (s1_npA + 8) * PP + 2 * m) = hB;
            }
        }
        __syncthreads();
        // S2 (ef only): table row = H1 @ ow2
        float rowv[8];
        {
            const float* hB = sm + OFF_H1P + s2_kh * 32 * PP + 2 * s2_m;
            const float* oB = sm + OFF_OW2 + s2_kh * 2048 + 2 * s2_h0;
            ull R[8];
            #pragma unroll
            for (int j = 0; j < 8; j++) R[j] = 0ull;
            #pragma unroll 4
            for (int i = 0; i < 32; i++) {
                ull hp = *reinterpret_cast<const ull*>(hB + i * PP);
                ulonglong2 o01 = *reinterpret_cast<const ulonglong2*>(oB + i * 64);
                ulonglong2 o23 = *reinterpret_cast<const ulonglong2*>(oB + i * 64 + 4);
                ulonglong2 o45 = *reinterpret_cast<const ulonglong2*>(oB + i * 64 + 8);
                ulonglong2 o67 = *reinterpret_cast<const ulonglong2*>(oB + i * 64 + 12);
                R[0] = ffma2(hp, o01.x, R[0]); R[1] = ffma2(hp, o01.y, R[1]);
                R[2] = ffma2(hp, o23.x, R[2]); R[3] = ffma2(hp, o23.y, R[3]);
                R[4] = ffma2(hp, o45.x, R[4]); R[5] = ffma2(hp, o45.y, R[5]);
                R[6] = ffma2(hp, o67.x, R[6]); R[7] = ffma2(hp, o67.y, R[7]);
            }
            #pragma unroll
            for (int j = 0; j < 8; j++) rowv[j] = hadd2(R[j]);
        }
        if (s2_kh) {
            float* sc = sm + OFF_SCR + s2_m * SCP + s2_h0;
            *reinterpret_cast<float4*>(sc)     = make_float4(rowv[0], rowv[1], rowv[2], rowv[3]);
            *reinterpret_cast<float4*>(sc + 4) = make_float4(rowv[4], rowv[5], rowv[6], rowv[7]);
        }
        __syncthreads();
        if (s2_kh == 0) {
            const float* sc = sm + OFF_SCR + s2_m * SCP + s2_h0;
            float4 r0 = *reinterpret_cast<const float4*>(sc);
            float4 r1 = *reinterpret_cast<const float4*>(sc + 4);
            int row = t * 64 + s2_m;
            float4 w0 = make_float4(rowv[0] + r0.x, rowv[1] + r0.y,
                                    rowv[2] + r0.z, rowv[3] + r0.w);
            float4 w1 = make_float4(rowv[4] + r1.x, rowv[5] + r1.y,
                                    rowv[6] + r1.z, rowv[7] + r1.w);
            *reinterpret_cast<float4*>(g_tab + (size_t)row * HDIM + s2_h0)     = w0;
            *reinterpret_cast<float4*>(g_tab + (size_t)row * HDIM + s2_h0 + 4) = w1;
        }
        __syncthreads();
    }
}

// =====================  MAIN KERNEL  =====================
__global__ __launch_bounds__(512, 1)
void fused_distbias_kernel(
    const float* __restrict__ pos,
    const int*   __restrict__ etype,
    const float* __restrict__ mw,
    const float* __restrict__ bw,
    const float* __restrict__ means,
    const float* __restrict__ stds,
    const float* __restrict__ ow1,
    const float* __restrict__ ob1,
    const float* __restrict__ ow2,
    const float* __restrict__ ob2,
    const float* __restrict__ vw1,
    const float* __restrict__ vb1,
    const float* __restrict__ vw2,
    const float* __restrict__ vb2,
    float* __restrict__ out,
    int nE)
{
    extern __shared__ float sm[];
    const int tid = threadIdx.x;
    int* iflags = reinterpret_cast<int*>(sm + OFF_FLAG);

    // ---- Stage weights (pair-major), once per block ----
    for (int i = tid; i < 64 * 128; i += 512) {
        int kp = i >> 7, c = i & 127;
        sm[OFF_OW1 + kp * 256 + 2 * c]     = ow1[(2 * kp) * KDIM + c];
        sm[OFF_OW1 + kp * 256 + 2 * c + 1] = ow1[(2 * kp + 1) * KDIM + c];
    }
    for (int i = tid; i < 64 * 32; i += 512) {
        int kp = i >> 5, h = i & 31;
        sm[OFF_OW2 + kp * 64 + 2 * h]     = ow2[(2 * kp) * HDIM + h];
        sm[OFF_OW2 + kp * 64 + 2 * h + 1] = ow2[(2 * kp + 1) * HDIM + h];
        sm[OFF_VW2 + kp * 64 + 2 * h]     = vw2[(2 * kp) * HDIM + h];
        sm[OFF_VW2 + kp * 64 + 2 * h + 1] = vw2[(2 * kp + 1) * HDIM + h];
    }
    if (tid < 3 * KDIM) sm[OFF_VW1 + tid] = vw1[tid];
    if (tid < KDIM) {
        sm[OFF_VB1 + tid] = vb1[tid];
        sm[OFF_OB1 + tid] = ob1[tid];
        float s  = fabsf(stds[tid]) + 1e-5f;
        float is = 1.0f / s;
        sm[OFF_MEAN + tid] = means[tid];
        sm[OFF_ISTD + tid] = is;
        sm[OFF_COEF + tid] = is * (1.0f / sqrtf(2.0f * 3.14159f));
    }
    if (tid < HDIM) sm[OFF_B2 + tid] = ob2[tid] + vb2[tid];
    if (tid == 0) { iflags[0] = 1; iflags[1] = 1; iflags[2] = 1; }
    __syncthreads();
    if (tid < KDIM && vb1[tid] != 0.0f) atomicAnd(&iflags[0], 0);
    if (tid < KDIM) {
        float s = fabsf(stds[tid]) + 1e-5f;
        if (s < 0.004f) atomicAnd(&iflags[2], 0);
    }
    {
        float m0v = mw[0], b0v = bw[0];
        for (int i = tid; i < nE; i += 512)
            if (mw[i] != m0v || bw[i] != b0v) atomicAnd(&iflags[1], 0);
    }
    __syncthreads();
    // T[d][h] = vw1 @ vw2
    if (tid < 96) {
        int d = tid >> 5, h = tid & 31;
        float s = 0.0f;
        for (int kp = 0; kp < 64; kp++) {
            float2 a = *reinterpret_cast<float2*>(sm + OFF_VW1 + d * 128 + 2 * kp);
            float2 w = *reinterpret_cast<float2*>(sm + OFF_VW2 + kp * 64 + 2 * h);
            s += a.x * w.x + a.y * w.y;
        }
        sm[OFF_TVV + d * 32 + h] = s;
    }
    const int vbzero = iflags[0];
    const int fastmode = iflags[0] & iflags[1];
    const int usetab = fastmode & iflags[2];
    const int ntiles = fastmode ? NTILES_FAST : NTILES_SLOW;

    // ---- per-thread decompositions ----
    const int gm  = tid & 63;
    const int gkc = tid >> 6;
    const int s1_wid = tid >> 5, s1_lane = tid & 31;
    const int s1_wm = s1_wid & 3, s1_wn = s1_wid >> 2;
    const int s1_mg = s1_lane >> 3, s1_ng = s1_lane & 7;
    const int s1_mbase = s1_wm * 16 + s1_mg * 4;
    const int s1_cbase = s1_wn * 32;
    const int s1_npA   = s1_wn * 16 + s1_ng;
    const int s2_hg = (tid >> 5) & 3;
    const int s2_kh = (tid >> 7) & 1;
    const int s2_mh = tid >> 8;
    const int s2_h0 = s2_hg * 8;
    const int s2_m  = s2_mh * 32 + (tid & 31);

    // ---- first tile's metadata (synchronous) ----
    {
        int b0, ri0, j00, w0;
        decode_tile((int)blockIdx.x, fastmode, b0, ri0, j00, w0);
        if ((int)blockIdx.x < ntiles && tid < 64) {
            float4 m = load_meta(pos, etype, mw, bw, b0, ri0, j00 + tid);
            *reinterpret_cast<float4*>(sm + OFF_DLM4 + tid * 4) = m;
        }
    }
    __syncthreads();

    if (usetab) {
        // ================= FAST TABLE LOOP =================
        const float m0v = mw[0], b0v = bw[0];
        const float lo = fminf(b0v, m0v + b0v);
        const float span = fmaxf(b0v, m0v + b0v) - lo;
        const float invd = (span > 0.0f) ? (float)(TABN - 1) / span : 0.0f;
        int cur = 0, zi = 0;
        for (int t = blockIdx.x; t < NTILES_FAST; t += gridDim.x, zi++) {
            int b, rowi, j0, wrM;
            decode_tile(t, 1, b, rowi, j0, wrM);

            if (zi < NZI) {
                #pragma unroll
                for (int zz = 0; zz < 3; zz++) {
                    int idx = ((zi * 3 + zz) * GRIDX + (int)blockIdx.x) * 512 + tid;
                    if (idx < ZTOT_F4) {
                        int jq = idx % 192;
                        int r  = idx / 192;
                        int ip = r % 768;
                        int bhh = r / 768;
                        size_t addr = (((size_t)bhh << 10) + 256 + ip) * 1024 + 256 + 4 * jq;
                        *reinterpret_cast<float4*>(out + addr) = make_float4(0.f, 0.f, 0.f, 0.f);
                    }
                }
            }

            const int tn = t + gridDim.x;
            float4 pf;
            const bool havePf = (tn < NTILES_FAST) && (tid < 64);
            if (havePf) {
                int bn, rin, j0n, wn;
                decode_tile(tn, 1, bn, rin, j0n, wn);
                pf = load_meta(pos, etype, mw, bw, bn, rin, j0n + tid);
            }

            // ---- v1 phase only (no gaussians, no S1) ----
            {
                float4 dm = *reinterpret_cast<float4*>(sm + OFF_DLM4 + cur * 256 + gm * 4);
                #pragma unroll
                for (int i = 0; i < 8; i++) {
                    int kp = gkc * 8 + i;
                    float2 w0 = *reinterpret_cast<float2*>(sm + OFF_VW1 + 2 * kp);
                    float2 w1 = *reinterpret_cast<float2*>(sm + OFF_VW1 + 128 + 2 * kp);
                    float2 w2 = *reinterpret_cast<float2*>(sm + OFF_VW1 + 256 + 2 * kp);
                    float sx = dm.x * w0.x + dm.y * w1.x + dm.z * w2.x;   // vb1 == 0
                    float sy = dm.x * w0.y + dm.y * w1.y + dm.z * w2.y;
                    float2 v1 = make_float2(fast_gelu(sx), fast_gelu(sy));
                    *reinterpret_cast<float2*>(sm + OFF_VP1 + kp * PP + 2 * gm) = v1;
                }
            }
            if (havePf)
                *reinterpret_cast<float4*>(sm + OFF_DLM4 + (cur ^ 1) * 256 + tid * 4) = pf;
            __syncthreads();   // (A)

            // ---- S2': va = V1@vw2 (k-split), ef from table lerp ----
            float rowv[8], eft[8], corr[8];
            {
                if (s2_kh == 0) {
                    float x0 = sm[OFF_DLM4 + cur * 256 + s2_m * 4 + 3];
                    float u = (x0 - lo) * invd;
                    u = fminf(fmaxf(u, 0.0f), (float)(TABN - 1));
                    int i0 = (int)u;
                    if (i0 > TABN - 2) i0 = TABN - 2;
                    float f = u - (float)i0;
                    const float* r0 = g_tab + (size_t)i0 * HDIM + s2_h0;
                    float4 a0 = *reinterpret_cast<const float4*>(r0);
                    float4 a1 = *reinterpret_cast<const float4*>(r0 + 4);
                    float4 c0 = *reinterpret_cast<const float4*>(r0 + HDIM);
                    float4 c1 = *reinterpret_cast<const float4*>(r0 + HDIM + 4);
                    eft[0] = fmaf(f, c0.x - a0.x, a0.x);
                    eft[1] = fmaf(f, c0.y - a0.y, a0.y);
                    eft[2] = fmaf(f, c0.z - a0.z, a0.z);
                    eft[3] = fmaf(f, c0.w - a0.w, a0.w);
                    eft[4] = fmaf(f, c1.x - a1.x, a1.x);
                    eft[5] = fmaf(f, c1.y - a1.y, a1.y);
                    eft[6] = fmaf(f, c1.z - a1.z, a1.z);
                    eft[7] = fmaf(f, c1.w - a1.w, a1.w);
                }
                const float* vB = sm + OFF_VP1 + s2_kh * 32 * PP + 2 * s2_m;
                const float* wB = sm + OFF_VW2 + s2_kh * 2048 + 2 * s2_h0;
                ull A[8];
                #pragma unroll
                for (int j = 0; j < 8; j++) A[j] = 0ull;
                #pragma unroll 4
                for (int i = 0; i < 32; i++) {
                    ull vp = *reinterpret_cast<const ull*>(vB + i * PP);
                    ulonglong2 v01 = *reinterpret_cast<const ulonglong2*>(wB + i * 64);
                    ulonglong2 v23 = *reinterpret_cast<const ulonglong2*>(wB + i * 64 + 4);
                    ulonglong2 v45 = *reinterpret_cast<const ulonglong2*>(wB + i * 64 + 8);
                    ulonglong2 v67 = *reinterpret_cast<const ulonglong2*>(wB + i * 64 + 12);
                    A[0] = ffma2(vp, v01.x, A[0]); A[1] = ffma2(vp, v01.y, A[1]);
                    A[2] = ffma2(vp, v23.x, A[2]); A[3] = ffma2(vp, v23.y, A[3]);
                    A[4] = ffma2(vp, v45.x, A[4]); A[5] = ffma2(vp, v45.y, A[5]);
                    A[6] = ffma2(vp, v67.x, A[6]); A[7] = ffma2(vp, v67.y, A[7]);
                }
                #pragma unroll
                for (int j = 0; j < 8; j++) rowv[j] = hadd2(A[j]);
            }
            if (wrM && s2_kh == 0) {
                float4 dmv = *reinterpret_cast<float4*>(sm + OFF_DLM4 + cur * 256 + s2_m * 4);
                #pragma unroll
                for (int j = 0; j < 8; j++) {
                    int h = s2_h0 + j;
                    corr[j] = dmv.x * sm[OFF_TVV + h]
                            + dmv.y * sm[OFF_TVV + 32 + h]
                            + dmv.z * sm[OFF_TVV + 64 + h];
                }
            }
            if (s2_kh) {
                float* sc = sm + OFF_SCR + s2_m * SCP + s2_h0;
                *reinterpret_cast<float4*>(sc)     = make_float4(rowv[0], rowv[1], rowv[2], rowv[3]);
                *reinterpret_cast<float4*>(sc + 4) = make_float4(rowv[4], rowv[5], rowv[6], rowv[7]);
            }
            __syncthreads();   // (B)
            if (s2_kh == 0) {
                const float* sc = sm + OFF_SCR + s2_m * SCP + s2_h0;
                float4 r0 = *reinterpret_cast<const float4*>(sc);
                float4 r1 = *reinterpret_cast<const float4*>(sc + 4);
                rowv[0] += r0.x + eft[0]; rowv[1] += r0.y + eft[1];
                rowv[2] += r0.z + eft[2]; rowv[3] += r0.w + eft[3];
                rowv[4] += r1.x + eft[4]; rowv[5] += r1.y + eft[5];
                rowv[6] += r1.z + eft[6]; rowv[7] += r1.w + eft[7];
                const size_t bh = (size_t)b * HDIM;
                #pragma unroll
                for (int j = 0; j < 8; j++) {
                    int h = s2_h0 + j;
                    float v = rowv[j] + sm[OFF_B2 + h];
                    out[((bh + h) * NTOT + rowi) * NTOT + j0 + s2_m] = v;
                    if (wrM)
                        out[((bh + h) * NTOT + (j0 + s2_m)) * NTOT + rowi] = v - corr[j];
                }
            }
            cur ^= 1;
        }
        return;
    }

    // ================= EXACT LOOP (R12 path) =================
    int cur = 0;
    int zi = 0;
    for (int t = blockIdx.x; t < ntiles; t += gridDim.x, zi++) {
        int b, rowi, j0, wrM;
        decode_tile(t, fastmode, b, rowi, j0, wrM);

        if (zi < NZI) {
            #pragma unroll
            for (int zz = 0; zz < 3; zz++) {
                int idx = ((zi * 3 + zz) * GRIDX + (int)blockIdx.x) * 512 + tid;
                if (idx < ZTOT_F4) {
                    int jq = idx % 192;
                    int r  = idx / 192;
                    int ip = r % 768;
                    int bhh = r / 768;
                    size_t addr = (((size_t)bhh << 10) + 256 + ip) * 1024 + 256 + 4 * jq;
                    *reinterpret_cast<float4*>(out + addr) = make_float4(0.f, 0.f, 0.f, 0.f);
                }
            }
        }

        const int tn = t + gridDim.x;
        float4 pf;
        const bool havePf = (tn < ntiles) && (tid < 64);
        if (havePf) {
            int bn, rin, j0n, wn;
            decode_tile(tn, fastmode, bn, rin, j0n, wn);
            pf = load_meta(pos, etype, mw, bw, bn, rin, j0n + tid);
        }

        {
            float4 dm = *reinterpret_cast<float4*>(sm + OFF_DLM4 + cur * 256 + gm * 4);
            #pragma unroll
            for (int i = 0; i < 8; i++) {
                int kp = gkc * 8 + i;
                float2 mn = *reinterpret_cast<float2*>(sm + OFF_MEAN + 2 * kp);
                float2 is = *reinterpret_cast<float2*>(sm + OFF_ISTD + 2 * kp);
                float2 cf = *reinterpret_cast<float2*>(sm + OFF_COEF + 2 * kp);
                float2 w0 = *reinterpret_cast<float2*>(sm + OFF_VW1 + 2 * kp);
                float2 w1 = *reinterpret_cast<float2*>(sm + OFF_VW1 + 128 + 2 * kp);
                float2 w2 = *reinterpret_cast<float2*>(sm + OFF_VW1 + 256 + 2 * kp);
                float2 vb = *reinterpret_cast<float2*>(sm + OFF_VB1 + 2 * kp);
                float tx = (dm.w - mn.x) * is.x;
                float ty = (dm.w - mn.y) * is.y;
                float2 g = make_float2(__expf(-0.5f * tx * tx) * cf.x,
                                       __expf(-0.5f * ty * ty) * cf.y);
                float sx = dm.x * w0.x + dm.y * w1.x + dm.z * w2.x + vb.x;
                float sy = dm.x * w0.y + dm.y * w1.y + dm.z * w2.y + vb.y;
                float2 v1 = make_float2(fast_gelu(sx), fast_gelu(sy));
                *reinterpret_cast<float2*>(sm + OFF_GP  + kp * PP + 2 * gm) = g;
                *reinterpret_cast<float2*>(sm + OFF_VP1 + kp * PP + 2 * gm) = v1;
            }
        }
        if (havePf)
            *reinterpret_cast<float4*>(sm + OFF_DLM4 + (cur ^ 1) * 256 + tid * 4) = pf;
        __syncthreads();

        {
            ull acc[4][4];
            #pragma unroll
            for (int r = 0; r < 4; r++)
                #pragma unroll
                for (int j = 0; j < 4; j++) acc[r][j] = 0ull;
            const float* gpB = sm + OFF_GP + 2 * s1_mbase;
            const float* w1B = sm + OFF_OW1 + 2 * s1_cbase + 4 * s1_ng;
            #pragma unroll 4
            for (int kp = 0; kp < 64; kp++) {
                ulonglong2 g01 = *reinterpret_cast<const ulonglong2*>(gpB + kp * PP);
                ulonglong2 g23 = *reinterpret_cast<const ulonglong2*>(gpB + kp * PP + 4);
                ulonglong2 wA  = *reinterpret_cast<const ulonglong2*>(w1B + kp * 256);
                ulonglong2 wB  = *reinterpret_cast<const ulonglong2*>(w1B + kp * 256 + 32);
                acc[0][0] = ffma2(g01.x, wA.x, acc[0][0]);
                acc[0][1] = ffma2(g01.x, wA.y, acc[0][1]);
                acc[0][2] = ffma2(g01.x, wB.x, acc[0][2]);
                acc[0][3] = ffma2(g01.x, wB.y, acc[0][3]);
                acc[1][0] = ffma2(g01.y, wA.x, acc[1][0]);
                acc[1][1] = ffma2(g01.y, wA.y, acc[1][1]);
                acc[1][2] = ffma2(g01.y, wB.x, acc[1][2]);
                acc[1][3] = ffma2(g01.y, wB.y, acc[1][3]);
                acc[2][0] = ffma2(g23.x, wA.x, acc[2][0]);
                acc[2][1] = ffma2(g23.x, wA.y, acc[2][1]);
                acc[2][2] = ffma2(g23.x, wB.x, acc[2][2]);
                acc[2][3] = ffma2(g23.x, wB.y, acc[2][3]);
                acc[3][0] = ffma2(g23.y, wA.x, acc[3][0]);
                acc[3][1] = ffma2(g23.y, wA.y, acc[3][1]);
                acc[3][2] = ffma2(g23.y, wB.x, acc[3][2]);
                acc[3][3] = ffma2(g23.y, wB.y, acc[3][3]);
            }
            float2 obA = *reinterpret_cast<float2*>(sm + OFF_OB1 + s1_cbase + 2 * s1_ng);
            float2 obB = *reinterpret_cast<float2*>(sm + OFF_OB1 + s1_cbase + 2 * s1_ng + 16);
            #pragma unroll
            for (int r = 0; r < 4; r++) {
                int m = s1_mbase + r;
                float2 hA = make_float2(fast_gelu(hadd2(acc[r][0]) + obA.x),
                                        fast_gelu(hadd2(acc[r][1]) + obA.y));
                float2 hB = make_float2(fast_gelu(hadd2(acc[r][2]) + obB.x),
                                        fast_gelu(hadd2(acc[r][3]) + obB.y));
                *reinterpret_cast<float2*>(sm + OFF_H1P + s1_npA * PP + 2 * m) = hA;
                *reinterpret_cast<float2*>(sm + OFF_H1P + (s1_npA + 8) * PP + 2 * m) = hB;
            }
        }
        __syncthreads();

        float rowv[8];
        {
            const float* hB = sm + OFF_H1P + s2_kh * 32 * PP + 2 * s2_m;
            const float* vB = sm + OFF_VP1 + s2_kh * 32 * PP + 2 * s2_m;
            const float* oB = sm + OFF_OW2 + s2_kh * 2048 + 2 * s2_h0;
            const float* wB = sm + OFF_VW2 + s2_kh * 2048 + 2 * s2_h0;
            ull R[8];
            #pragma unroll
            for (int j = 0; j < 8; j++) R[j] = 0ull;
            #pragma unroll 4
            for (int i = 0; i < 32; i++) {
                ull hp = *reinterpret_cast<const ull*>(hB + i * PP);
                ull vp = *reinterpret_cast<const ull*>(vB + i * PP);
                ulonglong2 o01 = *reinterpret_cast<const ulonglong2*>(oB + i * 64);
                ulonglong2 o23 = *reinterpret_cast<const ulonglong2*>(oB + i * 64 + 4);
                ulonglong2 o45 = *reinterpret_cast<const ulonglong2*>(oB + i * 64 + 8);
                ulonglong2 o67 = *reinterpret_cast<const ulonglong2*>(oB + i * 64 + 12);
                R[0] = ffma2(hp, o01.x, R[0]); R[1] = ffma2(hp, o01.y, R[1]);
                R[2] = ffma2(hp, o23.x, R[2]); R[3] = ffma2(hp, o23.y, R[3]);
                R[4] = ffma2(hp, o45.x, R[4]); R[5] = ffma2(hp, o45.y, R[5]);
                R[6] = ffma2(hp, o67.x, R[6]); R[7] = ffma2(hp, o67.y, R[7]);
                ulonglong2 v01 = *reinterpret_cast<const ulonglong2*>(wB + i * 64);
                ulonglong2 v23 = *reinterpret_cast<const ulonglong2*>(wB + i * 64 + 4);
                ulonglong2 v45 = *reinterpret_cast<const ulonglong2*>(wB + i * 64 + 8);
                ulonglong2 v67 = *reinterpret_cast<const ulonglong2*>(wB + i * 64 + 12);
                R[0] = ffma2(vp, v01.x, R[0]); R[1] = ffma2(vp, v01.y, R[1]);
                R[2] = ffma2(vp, v23.x, R[2]); R[3] = ffma2(vp, v23.y, R[3]);
                R[4] = ffma2(vp, v45.x, R[4]); R[5] = ffma2(vp, v45.y, R[5]);
                R[6] = ffma2(vp, v67.x, R[6]); R[7] = ffma2(vp, v67.y, R[7]);
            }
            #pragma unroll
            for (int j = 0; j < 8; j++) rowv[j] = hadd2(R[j]);
        }
        float corr[8];
        if (wrM && vbzero && s2_kh == 0) {
            float4 dmv = *reinterpret_cast<float4*>(sm + OFF_DLM4 + cur * 256 + s2_m * 4);
            #pragma unroll
            for (int j = 0; j < 8; j++) {
                int h = s2_h0 + j;
                corr[j] = dmv.x * sm[OFF_TVV + h]
                        + dmv.y * sm[OFF_TVV + 32 + h]
                        + dmv.z * sm[OFF_TVV + 64 + h];
            }
        }
        if (s2_kh) {
            float* sc = sm + OFF_SCR + s2_m * SCP + s2_h0;
            *reinterpret_cast<float4*>(sc)     = make_float4(rowv[0], rowv[1], rowv[2], rowv[3]);
            *reinterpret_cast<float4*>(sc + 4) = make_float4(rowv[4], rowv[5], rowv[6], rowv[7]);
        }
        __syncthreads();
        if (s2_kh == 0) {
            const float* sc = sm + OFF_SCR + s2_m * SCP + s2_h0;
            float4 r0 = *reinterpret_cast<const float4*>(sc);
            float4 r1 = *reinterpret_cast<const float4*>(sc + 4);
            rowv[0] += r0.x; rowv[1] += r0.y; rowv[2] += r0.z; rowv[3] += r0.w;
            rowv[4] += r1.x; rowv[5] += r1.y; rowv[6] += r1.z; rowv[7] += r1.w;
            const size_t bh = (size_t)b * HDIM;
            #pragma unroll
            for (int j = 0; j < 8; j++) {
                int h = s2_h0 + j;
                float v = rowv[j] + sm[OFF_B2 + h];
                out[((bh + h) * NTOT + rowi) * NTOT + j0 + s2_m] = v;
                if (wrM && vbzero)
                    out[((bh + h) * NTOT + (j0 + s2_m)) * NTOT + rowi] = v - corr[j];
            }
        }

        if (wrM && !vbzero) {
            float dp[8];
            {
                float4 dmv = *reinterpret_cast<float4*>(sm + OFF_DLM4 + cur * 256 + s2_m * 4);
                const float* vB = sm + OFF_VP1 + s2_kh * 32 * PP + 2 * s2_m;
                const float* wB = sm + OFF_VW2 + s2_kh * 2048 + 2 * s2_h0;
                ull D[8];
                #pragma unroll
                for (int j = 0; j < 8; j++) D[j] = 0ull;
                for (int i = 0; i < 32; i++) {
                    int kp = s2_kh * 32 + i;
                    float2 w0 = *reinterpret_cast<float2*>(sm + OFF_VW1 + 2 * kp);
                    float2 w1 = *reinterpret_cast<float2*>(sm + OFF_VW1 + 128 + 2 * kp);
                    float2 w2 = *reinterpret_cast<float2*>(sm + OFF_VW1 + 256 + 2 * kp);
                    float2 vb = *reinterpret_cast<float2*>(sm + OFF_VB1 + 2 * kp);
                    float sx = dmv.x * w0.x + dmv.y * w1.x + dmv.z * w2.x + vb.x;
                    float sy = dmv.x * w0.y + dmv.y * w1.y + dmv.z * w2.y + vb.y;
                    float2 pv = u2f2(*reinterpret_cast<const ull*>(vB + i * PP));
                    ull dq = f2pack(fast_gelu(2.0f * vb.x - sx) - pv.x,
                                    fast_gelu(2.0f * vb.y - sy) - pv.y);
                    ulonglong2 v01 = *reinterpret_cast<const ulonglong2*>(wB + i * 64);
                    ulonglong2 v23 = *reinterpret_cast<const ulonglong2*>(wB + i * 64 + 4);
                    ulonglong2 v45 = *reinterpret_cast<const ulonglong2*>(wB + i * 64 + 8);
                    ulonglong2 v67 = *reinterpret_cast<const ulonglong2*>(wB + i * 64 + 12);
                    D[0] = ffma2(dq, v01.x, D[0]); D[1] = ffma2(dq, v01.y, D[1]);
                    D[2] = ffma2(dq, v23.x, D[2]); D[3] = ffma2(dq, v23.y, D[3]);
                    D[4] = ffma2(dq, v45.x, D[4]); D[5] = ffma2(dq, v45.y, D[5]);
                    D[6] = ffma2(dq, v67.x, D[6]); D[7] = ffma2(dq, v67.y, D[7]);
                }
                #pragma unroll
                for (int j = 0; j < 8; j++) dp[j] = hadd2(D[j]);
            }
            __syncthreads();
            if (s2_kh) {
                float* sc = sm + OFF_SCR + s2_m * SCP + s2_h0;
                *reinterpret_cast<float4*>(sc)     = make_float4(dp[0], dp[1], dp[2], dp[3]);
                *reinterpret_cast<float4*>(sc + 4) = make_float4(dp[4], dp[5], dp[6], dp[7]);
            }
            __syncthreads();
            if (s2_kh == 0) {
                const float* sc = sm + OFF_SCR + s2_m * SCP + s2_h0;
                float4 r0 = *reinterpret_cast<const float4*>(sc);
                float4 r1 = *reinterpret_cast<const float4*>(sc + 4);
                dp[0] += r0.x; dp[1] += r0.y; dp[2] += r0.z; dp[3] += r0.w;
                dp[4] += r1.x; dp[5] += r1.y; dp[6] += r1.z; dp[7] += r1.w;
                const size_t bh = (size_t)b * HDIM;
                #pragma unroll
                for (int j = 0; j < 8; j++) {
                    int h = s2_h0 + j;
                    float v = rowv[j] + dp[j] + sm[OFF_B2 + h];
                    out[((bh + h) * NTOT + (j0 + s2_m)) * NTOT + rowi] = v;
                }
            }
        }
        cur ^= 1;
    }
}

extern "C" void kernel_launch(void* const* d_in, const int* in_sizes, int n_in,
                              void* d_out, int out_size) {
    const float* pos    = (const float*)d_in[0];
    const int*   etype  = (const int*)d_in[1];
    const float* means  = (const float*)d_in[3];
    const float* stds   = (const float*)d_in[4];
    const float* mul_w  = (const float*)d_in[5];
    const float* bias_w = (const float*)d_in[6];
    const float* ow1    = (const float*)d_in[7];
    const float* ob1    = (const float*)d_in[8];
    const float* ow2    = (const float*)d_in[9];
    const float* ob2    = (const float*)d_in[10];
    const float* vw1    = (const float*)d_in[11];
    const float* vb1    = (const float*)d_in[12];
    const float* vw2    = (const float*)d_in[13];
    const float* vb2    = (const float*)d_in[14];
    float* out = (float*)d_out;
    int nE = in_sizes[5];

    cudaFuncSetAttribute(build_tab_kernel,
                         cudaFuncAttributeMaxDynamicSharedMemorySize, SMEM_BYTES);
    cudaFuncSetAttribute(fused_distbias_kernel,
                         cudaFuncAttributeMaxDynamicSharedMemorySize, SMEM_BYTES);

    build_tab_kernel<<<GRIDX, 512, SMEM_BYTES>>>(
        mul_w, bias_w, means, stds, ow1, ob1, ow2, vb1, nE);

    fused_distbias_kernel<<<GRIDX, 512, SMEM_BYTES>>>(
        pos, etype, mul_w, bias_w, means, stds,
        ow1, ob1, ow2, ob2, vw1, vb1, vw2, vb2, out, nE);
}

// round 14
// speedup vs baseline: 2.8690x; 1.1279x over previous
#include <cuda_runtime.h>
#include <math.h>

typedef unsigned long long ull;

#define BDIM 2
#define NTOT 1024
#define PLEN 768
#define LLEN 256
#define KDIM 128
#define HDIM 32
#define TABN 32768

constexpr int PP = 132;
constexpr int NT_LP = BDIM * PLEN * 4;           // 6144
constexpr int NT_LL_SLOW = BDIM * LLEN * 4;      // 2048
constexpr int NTILES_SLOW = NT_LL_SLOW + NT_LP;  // 8192
constexpr int NT_LL_FAST = BDIM * 640;           // 1280
constexpr int NTILES_FAST = NT_LL_FAST + NT_LP;  // 7424
constexpr int NTAB_TILES = TABN / 64;            // 512

constexpr int GRIDX = 148;
constexpr int GRIDF = 296;                       // fast kernel: 2 CTAs/SM
constexpr int ZTOT_F4 = BDIM * HDIM * PLEN * (PLEN / 4);   // 9437184
constexpr int NZI  = (ZTOT_F4 + 3 * GRIDX * 512 - 1) / (3 * GRIDX * 512);  // 42
constexpr int NZIF = (ZTOT_F4 + 3 * GRIDF * 512 - 1) / (3 * GRIDF * 512);  // 21

// ---------- big-smem layout (exact + build kernels) ----------
constexpr int OFF_OW1  = 0;
constexpr int OFF_OW2  = 16384;
constexpr int OFF_VW2  = 20480;
constexpr int OFF_TVV  = 24576;
constexpr int OFF_VW1  = 24672;
constexpr int OFF_VB1  = 25056;
constexpr int OFF_OB1  = 25184;
constexpr int OFF_MEAN = 25312;
constexpr int OFF_ISTD = 25440;
constexpr int OFF_COEF = 25568;
constexpr int OFF_B2   = 25696;
constexpr int OFF_FLAG = 25728;
constexpr int OFF_DLM4 = 25732;
constexpr int OFF_GP   = 26244;
constexpr int OFF_VP1  = OFF_GP + 64 * PP;       // 34692
constexpr int OFF_H1P  = OFF_VP1 + 64 * PP;      // 43140
constexpr int SCP = 36;
constexpr int SCSTRIDE = 64 * SCP;               // 2304
constexpr int OFF_SCR  = OFF_H1P + 64 * PP;      // 51588
constexpr int SMEM_FLOATS = OFF_SCR + SCSTRIDE;  // 53892
constexpr int SMEM_BYTES  = SMEM_FLOATS * 4;     // 215568

// ---------- slim layout (fast kernel) ----------
constexpr int F_VW2  = 0;                        // 4096
constexpr int F_VW1  = 4096;                     // 384
constexpr int F_TVV  = 4480;                     // 96
constexpr int F_B2   = 4576;                     // 32
constexpr int F_FLAG = 4608;                     // 4
constexpr int F_DLM4 = 4612;                     // 512 (2 buffers); 4612*4%16==0
constexpr int F_VP1  = 5124;                     // 8448; 5124*4%16==0
constexpr int F_SCR  = F_VP1 + 64 * PP;          // 13572; *4%16==0
constexpr int FSMEM_FLOATS = F_SCR + SCSTRIDE;   // 15876
constexpr int FSMEM_BYTES  = FSMEM_FLOATS * 4;   // 63504

__device__ __align__(16) float g_tab[TABN * HDIM];

__device__ __forceinline__ ull ffma2(ull a, ull b, ull c) {
    ull d; asm("fma.rn.f32x2 %0,%1,%2,%3;" : "=l"(d) : "l"(a), "l"(b), "l"(c)); return d;
}
__device__ __forceinline__ float2 u2f2(ull v) {
    float2 f; asm("mov.b64 {%0,%1},%2;" : "=f"(f.x), "=f"(f.y) : "l"(v)); return f;
}
__device__ __forceinline__ ull f2pack(float x, float y) {
    ull r; asm("mov.b64 %0,{%1,%2};" : "=l"(r) : "f"(x), "f"(y)); return r;
}
__device__ __forceinline__ float hadd2(ull v) { float2 f = u2f2(v); return f.x + f.y; }

__device__ __forceinline__ float fast_gelu(float x) {
    float y  = x * 0.70710678118654752f;
    float ax = fabsf(y);
    float t  = __fdividef(1.0f, fmaf(0.3275911f, ax, 1.0f));
    float p  = fmaf(t, 1.061405429f, -1.453152027f);
    p = fmaf(t, p, 1.421413741f);
    p = fmaf(t, p, -0.284496736f);
    p = fmaf(t, p, 0.254829592f);
    p *= t;
    float e = __expf(-ax * ax);
    float erfv = copysignf(fmaf(-p, e, 1.0f), y);
    return 0.5f * x * (1.0f + erfv);
}

__device__ __forceinline__ void decode_tile(int t, int fastmode,
                                            int& b, int& rowi, int& j0, int& wrM) {
    if (fastmode) {
        if (t < NT_LL_FAST) {
            b = t / 640; int r = t - b * 640;
            if (r < 256) { rowi = r; j0 = r & 192; wrM = 0; }
            else {
                int r2 = r - 256; int pr = r2 >> 6;
                int br = (pr < 3) ? 0 : ((pr < 5) ? 1 : 2);
                int bc = (pr == 0) ? 1 : ((pr == 1 || pr == 3) ? 2 : 3);
                rowi = br * 64 + (r2 & 63); j0 = bc * 64; wrM = 1;
            }
        } else {
            int u = t - NT_LL_FAST; b = u / 3072; int r = u - b * 3072;
            rowi = LLEN + (r >> 2); j0 = (r & 3) << 6; wrM = 1;
        }
    } else {
        if (t < NT_LL_SLOW) {
            b = t >> 10; int r = t & 1023;
            rowi = r >> 2; j0 = (r & 3) << 6; wrM = 0;
        } else {
            int u = t - NT_LL_SLOW; b = u / 3072; int r = u - b * 3072;
            rowi = LLEN + (r >> 2); j0 = (r & 3) << 6; wrM = 1;
        }
    }
}

__device__ __forceinline__ float4 load_meta(const float* pos, const int* etype,
                                            const float* mw, const float* bw,
                                            int b, int rowi, int j) {
    const float* pj = pos + ((size_t)b * NTOT + j) * 3;
    const float* pi = pos + ((size_t)b * NTOT + rowi) * 3;
    float d0 = pj[0] - pi[0];
    float d1 = pj[1] - pi[1];
    float d2 = pj[2] - pi[2];
    float d = 1.0f / (d0 * d0 + d1 * d1 + d2 * d2 + 1.0f);
    int e = etype[((size_t)b * NTOT + rowi) * NTOT + j];
    return make_float4(d0, d1, d2, mw[e] * d + bw[e]);
}

// Computes the 3 condition flags into ifl[0..2] (vbzero, symw, stdok). Caller syncs.
__device__ __forceinline__ void compute_flags(int* ifl, const float* vb1,
                                              const float* stds, const float* mw,
                                              const float* bw, int nE, int tid, int nthr) {
    if (tid == 0) { ifl[0] = 1; ifl[1] = 1; ifl[2] = 1; }
    __syncthreads();
    if (tid < KDIM && vb1[tid] != 0.0f) atomicAnd(&ifl[0], 0);
    if (tid < KDIM) {
        float s = fabsf(stds[tid]) + 1e-5f;
        if (s < 0.004f) atomicAnd(&ifl[2], 0);
    }
    float m0v = mw[0], b0v = bw[0];
    for (int i = tid; i < nE; i += nthr)
        if (mw[i] != m0v || bw[i] != b0v) atomicAnd(&ifl[1], 0);
    __syncthreads();
}

// =====================  TABLE BUILD KERNEL  =====================
__global__ __launch_bounds__(512, 1)
void build_tab_kernel(const float* __restrict__ mw, const float* __restrict__ bw,
                      const float* __restrict__ means, const float* __restrict__ stds,
                      const float* __restrict__ ow1, const float* __restrict__ ob1,
                      const float* __restrict__ ow2, const float* __restrict__ vb1,
                      int nE)
{
    extern __shared__ float sm[];
    const int tid = threadIdx.x;
    int* iflags = reinterpret_cast<int*>(sm + OFF_FLAG);
    compute_flags(iflags, vb1, stds, mw, bw, nE, tid, 512);
    if (!(iflags[0] & iflags[1] & iflags[2])) return;

    for (int i = tid; i < 64 * 128; i += 512) {
        int kp = i >> 7, c = i & 127;
        sm[OFF_OW1 + kp * 256 + 2 * c]     = ow1[(2 * kp) * KDIM + c];
        sm[OFF_OW1 + kp * 256 + 2 * c + 1] = ow1[(2 * kp + 1) * KDIM + c];
    }
    for (int i = tid; i < 64 * 32; i += 512) {
        int kp = i >> 5, h = i & 31;
        sm[OFF_OW2 + kp * 64 + 2 * h]     = ow2[(2 * kp) * HDIM + h];
        sm[OFF_OW2 + kp * 64 + 2 * h + 1] = ow2[(2 * kp + 1) * HDIM + h];
    }
    if (tid < KDIM) {
        sm[OFF_OB1 + tid] = ob1[tid];
        float s  = fabsf(stds[tid]) + 1e-5f;
        float is = 1.0f / s;
        sm[OFF_MEAN + tid] = means[tid];
        sm[OFF_ISTD + tid] = is;
        sm[OFF_COEF + tid] = is * (1.0f / sqrtf(2.0f * 3.14159f));
    }
    __syncthreads();

    const float m0v = mw[0], b0v = bw[0];
    const float lo = fminf(b0v, m0v + b0v);
    const float span = fmaxf(b0v, m0v + b0v) - lo;
    const float step = span / (float)(TABN - 1);

    const int gm  = tid & 63;
    const int gkc = tid >> 6;
    const int s1_wid = tid >> 5, s1_lane = tid & 31;
    const int s1_wm = s1_wid & 3, s1_wn = s1_wid >> 2;
    const int s1_mg = s1_lane >> 3, s1_ng = s1_lane & 7;
    const int s1_mbase = s1_wm * 16 + s1_mg * 4;
    const int s1_cbase = s1_wn * 32;
    const int s1_npA   = s1_wn * 16 + s1_ng;
    const int s2_hg = (tid >> 5) & 3;
    const int s2_kh = (tid >> 7) & 1;
    const int s2_mh = tid >> 8;
    const int s2_h0 = s2_hg * 8;
    const int s2_m  = s2_mh * 32 + (tid & 31);

    for (int t = blockIdx.x; t < NTAB_TILES; t += gridDim.x) {
        {
            float x0 = lo + (float)(t * 64 + gm) * step;
            #pragma unroll
            for (int i = 0; i < 8; i++) {
                int kp = gkc * 8 + i;
                float2 mn = *reinterpret_cast<float2*>(sm + OFF_MEAN + 2 * kp);
                float2 is = *reinterpret_cast<float2*>(sm + OFF_ISTD + 2 * kp);
                float2 cf = *reinterpret_cast<float2*>(sm + OFF_COEF + 2 * kp);
                float tx = (x0 - mn.x) * is.x;
                float ty = (x0 - mn.y) * is.y;
                float2 g = make_float2(__expf(-0.5f * tx * tx) * cf.x,
                                       __expf(-0.5f * ty * ty) * cf.y);
                *reinterpret_cast<float2*>(sm + OFF_GP + kp * PP + 2 * gm) = g;
            }
        }
        __syncthreads();
        {
            ull acc[4][4];
            #pragma unroll
            for (int r = 0; r < 4; r++)
                #pragma unroll
                for (int j = 0; j < 4; j++) acc[r][j] = 0ull;
            const float* gpB = sm + OFF_GP + 2 * s1_mbase;
            const float* w1B = sm + OFF_OW1 + 2 * s1_cbase + 4 * s1_ng;
            #pragma unroll 4
            for (int kp = 0; kp < 64; kp++) {
                ulonglong2 g01 = *reinterpret_cast<const ulonglong2*>(gpB + kp * PP);
                ulonglong2 g23 = *reinterpret_cast<const ulonglong2*>(gpB + kp * PP + 4);
                ulonglong2 wA  = *reinterpret_cast<const ulonglong2*>(w1B + kp * 256);
                ulonglong2 wB  = *reinterpret_cast<const ulonglong2*>(w1B + kp * 256 + 32);
                acc[0][0] = ffma2(g01.x, wA.x, acc[0][0]);
                acc[0][1] = ffma2(g01.x, wA.y, acc[0][1]);
                acc[0][2] = ffma2(g01.x, wB.x, acc[0][2]);
                acc[0][3] = ffma2(g01.x, wB.y, acc[0][3]);
                acc[1][0] = ffma2(g01.y, wA.x, acc[1][0]);
                acc[1][1] = ffma2(g01.y, wA.y, acc[1][1]);
                acc[1][2] = ffma2(g01.y, wB.x, acc[1][2]);
                acc[1][3] = ffma2(g01.y, wB.y, acc[1][3]);
                acc[2][0] = ffma2(g23.x, wA.x, acc[2][0]);
                acc[2][1] = ffma2(g23.x, wA.y, acc[2][1]);
                acc[2][2] = ffma2(g23.x, wB.x, acc[2][2]);
                acc[2][3] = ffma2(g23.x, wB.y, acc[2][3]);
                acc[3][0] = ffma2(g23.y, wA.x, acc[3][0]);
                acc[3][1] = ffma2(g23.y, wA.y, acc[3][1]);
                acc[3][2] = ffma2(g23.y, wB.x, acc[3][2]);
                acc[3][3] = ffma2(g23.y, wB.y, acc[3][3]);
            }
            float2 obA = *reinterpret_cast<float2*>(sm + OFF_OB1 + s1_cbase + 2 * s1_ng);
            float2 obB = *reinterpret_cast<float2*>(sm + OFF_OB1 + s1_cbase + 2 * s1_ng + 16);
            #pragma unroll
            for (int r = 0; r < 4; r++) {
                int m = s1_mbase + r;
                float2 hA = make_float2(fast_gelu(hadd2(acc[r][0]) + obA.x),
                                        fast_gelu(hadd2(acc[r][1]) + obA.y));
                float2 hB = make_float2(fast_gelu(hadd2(acc[r][2]) + obB.x),
                                        fast_gelu(hadd2(acc[r][3]) + obB.y));
                *reinterpret_cast<float2*>(sm + OFF_H1P + s1_npA * PP + 2 * m) = hA;
                *reinterpret_cast<float2*>(sm + OFF_H1P + (s1_npA + 8) * PP + 2 * m) = hB;
            }
        }
        __syncthreads();
        float rowv[8];
        {
            const float* hB = sm + OFF_H1P + s2_kh * 32 * PP + 2 * s2_m;
            const float* oB = sm + OFF_OW2 + s2_kh * 2048 + 2 * s2_h0;
            ull R[8];
            #pragma unroll
            for (int j = 0; j < 8; j++) R[j] = 0ull;
            #pragma unroll 4
            for (int i = 0; i < 32; i++) {
                ull hp = *reinterpret_cast<const ull*>(hB + i * PP);
                ulonglong2 o01 = *reinterpret_cast<const ulonglong2*>(oB + i * 64);
                ulonglong2 o23 = *reinterpret_cast<const ulonglong2*>(oB + i * 64 + 4);
                ulonglong2 o45 = *reinterpret_cast<const ulonglong2*>(oB + i * 64 + 8);
                ulonglong2 o67 = *reinterpret_cast<const ulonglong2*>(oB + i * 64 + 12);
                R[0] = ffma2(hp, o01.x, R[0]); R[1] = ffma2(hp, o01.y, R[1]);
                R[2] = ffma2(hp, o23.x, R[2]); R[3] = ffma2(hp, o23.y, R[3]);
                R[4] = ffma2(hp, o45.x, R[4]); R[5] = ffma2(hp, o45.y, R[5]);
                R[6] = ffma2(hp, o67.x, R[6]); R[7] = ffma2(hp, o67.y, R[7]);
            }
            #pragma unroll
            for (int j = 0; j < 8; j++) rowv[j] = hadd2(R[j]);
        }
        if (s2_kh) {
            float* sc = sm + OFF_SCR + s2_m * SCP + s2_h0;
            *reinterpret_cast<float4*>(sc)     = make_float4(rowv[0], rowv[1], rowv[2], rowv[3]);
            *reinterpret_cast<float4*>(sc + 4) = make_float4(rowv[4], rowv[5], rowv[6], rowv[7]);
        }
        __syncthreads();
        if (s2_kh == 0) {
            const float* sc = sm + OFF_SCR + s2_m * SCP + s2_h0;
            float4 r0 = *reinterpret_cast<const float4*>(sc);
            float4 r1 = *reinterpret_cast<const float4*>(sc + 4);
            int row = t * 64 + s2_m;
            float4 w0 = make_float4(rowv[0] + r0.x, rowv[1] + r0.y,
                                    rowv[2] + r0.z, rowv[3] + r0.w);
            float4 w1 = make_float4(rowv[4] + r1.x, rowv[5] + r1.y,
                                    rowv[6] + r1.z, rowv[7] + r1.w);
            *reinterpret_cast<float4*>(g_tab + (size_t)row * HDIM + s2_h0)     = w0;
            *reinterpret_cast<float4*>(g_tab + (size_t)row * HDIM + s2_h0 + 4) = w1;
        }
        __syncthreads();
    }
}

// =====================  FAST KERNEL (slim smem, 2 CTA/SM)  =====================
__global__ __launch_bounds__(512, 2)
void fast_tab_kernel(
    const float* __restrict__ pos,
    const int*   __restrict__ etype,
    const float* __restrict__ mw,
    const float* __restrict__ bw,
    const float* __restrict__ stds,
    const float* __restrict__ ob2,
    const float* __restrict__ vw1,
    const float* __restrict__ vb1,
    const float* __restrict__ vw2,
    const float* __restrict__ vb2,
    float* __restrict__ out,
    int nE)
{
    extern __shared__ float sm[];
    const int tid = threadIdx.x;
    int* iflags = reinterpret_cast<int*>(sm + F_FLAG);
    compute_flags(iflags, vb1, stds, mw, bw, nE, tid, 512);
    if (!(iflags[0] & iflags[1] & iflags[2])) return;   // exact kernel handles it

    for (int i = tid; i < 64 * 32; i += 512) {
        int kp = i >> 5, h = i & 31;
        sm[F_VW2 + kp * 64 + 2 * h]     = vw2[(2 * kp) * HDIM + h];
        sm[F_VW2 + kp * 64 + 2 * h + 1] = vw2[(2 * kp + 1) * HDIM + h];
    }
    if (tid < 3 * KDIM) sm[F_VW1 + tid] = vw1[tid];
    if (tid < HDIM) sm[F_B2 + tid] = ob2[tid] + vb2[tid];
    __syncthreads();
    if (tid < 96) {
        int d = tid >> 5, h = tid & 31;
        float s = 0.0f;
        for (int kp = 0; kp < 64; kp++) {
            float2 a = *reinterpret_cast<float2*>(sm + F_VW1 + d * 128 + 2 * kp);
            float2 w = *reinterpret_cast<float2*>(sm + F_VW2 + kp * 64 + 2 * h);
            s += a.x * w.x + a.y * w.y;
        }
        sm[F_TVV + d * 32 + h] = s;
    }

    const float m0v = mw[0], b0v = bw[0];
    const float lo = fminf(b0v, m0v + b0v);
    const float span = fmaxf(b0v, m0v + b0v) - lo;
    const float invd = (span > 0.0f) ? (float)(TABN - 1) / span : 0.0f;

    const int gm  = tid & 63;
    const int gkc = tid >> 6;
    const int s2_hg = (tid >> 5) & 3;
    const int s2_kh = (tid >> 7) & 1;
    const int s2_mh = tid >> 8;
    const int s2_h0 = s2_hg * 8;
    const int s2_m  = s2_mh * 32 + (tid & 31);

    // first tile metadata
    {
        int b0, ri0, j00, w0;
        decode_tile((int)blockIdx.x, 1, b0, ri0, j00, w0);
        if ((int)blockIdx.x < NTILES_FAST && tid < 64) {
            float4 m = load_meta(pos, etype, mw, bw, b0, ri0, j00 + tid);
            *reinterpret_cast<float4*>(sm + F_DLM4 + tid * 4) = m;
        }
    }
    __syncthreads();

    int cur = 0, zi = 0;
    for (int t = blockIdx.x; t < NTILES_FAST; t += gridDim.x, zi++) {
        int b, rowi, j0, wrM;
        decode_tile(t, 1, b, rowi, j0, wrM);

        if (zi < NZIF) {
            #pragma unroll
            for (int zz = 0; zz < 3; zz++) {
                int idx = ((zi * 3 + zz) * GRIDF + (int)blockIdx.x) * 512 + tid;
                if (idx < ZTOT_F4) {
                    int jq = idx % 192;
                    int r  = idx / 192;
                    int ip = r % 768;
                    int bhh = r / 768;
                    size_t addr = (((size_t)bhh << 10) + 256 + ip) * 1024 + 256 + 4 * jq;
                    *reinterpret_cast<float4*>(out + addr) = make_float4(0.f, 0.f, 0.f, 0.f);
                }
            }
        }

        const int tn = t + gridDim.x;
        float4 pf;
        const bool havePf = (tn < NTILES_FAST) && (tid < 64);
        if (havePf) {
            int bn, rin, j0n, wn;
            decode_tile(tn, 1, bn, rin, j0n, wn);
            pf = load_meta(pos, etype, mw, bw, bn, rin, j0n + tid);
        }

        // v1 phase
        {
            float4 dm = *reinterpret_cast<float4*>(sm + F_DLM4 + cur * 256 + gm * 4);
            #pragma unroll
            for (int i = 0; i < 8; i++) {
                int kp = gkc * 8 + i;
                float2 w0 = *reinterpret_cast<float2*>(sm + F_VW1 + 2 * kp);
                float2 w1 = *reinterpret_cast<float2*>(sm + F_VW1 + 128 + 2 * kp);
                float2 w2 = *reinterpret_cast<float2*>(sm + F_VW1 + 256 + 2 * kp);
                float sx = dm.x * w0.x + dm.y * w1.x + dm.z * w2.x;   // vb1 == 0
                float sy = dm.x * w0.y + dm.y * w1.y + dm.z * w2.y;
                float2 v1 = make_float2(fast_gelu(sx), fast_gelu(sy));
                *reinterpret_cast<float2*>(sm + F_VP1 + kp * PP + 2 * gm) = v1;
            }
        }
        if (havePf)
            *reinterpret_cast<float4*>(sm + F_DLM4 + (cur ^ 1) * 256 + tid * 4) = pf;
        __syncthreads();   // (A)

        float rowv[8], eft[8], corr[8];
        {
            if (s2_kh == 0) {
                float x0 = sm[F_DLM4 + cur * 256 + s2_m * 4 + 3];
                float u = (x0 - lo) * invd;
                u = fminf(fmaxf(u, 0.0f), (float)(TABN - 1));
                int i0 = (int)u;
                if (i0 > TABN - 2) i0 = TABN - 2;
                float f = u - (float)i0;
                const float* r0 = g_tab + (size_t)i0 * HDIM + s2_h0;
                float4 a0 = *reinterpret_cast<const float4*>(r0);
                float4 a1 = *reinterpret_cast<const float4*>(r0 + 4);
                float4 c0 = *reinterpret_cast<const float4*>(r0 + HDIM);
                float4 c1 = *reinterpret_cast<const float4*>(r0 + HDIM + 4);
                eft[0] = fmaf(f, c0.x - a0.x, a0.x);
                eft[1] = fmaf(f, c0.y - a0.y, a0.y);
                eft[2] = fmaf(f, c0.z - a0.z, a0.z);
                eft[3] = fmaf(f, c0.w - a0.w, a0.w);
                eft[4] = fmaf(f, c1.x - a1.x, a1.x);
                eft[5] = fmaf(f, c1.y - a1.y, a1.y);
                eft[6] = fmaf(f, c1.z - a1.z, a1.z);
                eft[7] = fmaf(f, c1.w - a1.w, a1.w);
            }
            const float* vB = sm + F_VP1 + s2_kh * 32 * PP + 2 * s2_m;
            const float* wB = sm + F_VW2 + s2_kh * 2048 + 2 * s2_h0;
            ull A[8];
            #pragma unroll
            for (int j = 0; j < 8; j++) A[j] = 0ull;
            #pragma unroll 4
            for (int i = 0; i < 32; i++) {
                ull vp = *reinterpret_cast<const ull*>(vB + i * PP);
                ulonglong2 v01 = *reinterpret_cast<const ulonglong2*>(wB + i * 64);
                ulonglong2 v23 = *reinterpret_cast<const ulonglong2*>(wB + i * 64 + 4);
                ulonglong2 v45 = *reinterpret_cast<const ulonglong2*>(wB + i * 64 + 8);
                ulonglong2 v67 = *reinterpret_cast<const ulonglong2*>(wB + i * 64 + 12);
                A[0] = ffma2(vp, v01.x, A[0]); A[1] = ffma2(vp, v01.y, A[1]);
                A[2] = ffma2(vp, v23.x, A[2]); A[3] = ffma2(vp, v23.y, A[3]);
                A[4] = ffma2(vp, v45.x, A[4]); A[5] = ffma2(vp, v45.y, A[5]);
                A[6] = ffma2(vp, v67.x, A[6]); A[7] = ffma2(vp, v67.y, A[7]);
            }
            #pragma unroll
            for (int j = 0; j < 8; j++) rowv[j] = hadd2(A[j]);
        }
        if (wrM && s2_kh == 0) {
            float4 dmv = *reinterpret_cast<float4*>(sm + F_DLM4 + cur * 256 + s2_m * 4);
            #pragma unroll
            for (int j = 0; j < 8; j++) {
                int h = s2_h0 + j;
                corr[j] = dmv.x * sm[F_TVV + h]
                        + dmv.y * sm[F_TVV + 32 + h]
                        + dmv.z * sm[F_TVV + 64 + h];
            }
        }
        if (s2_kh) {
            float* sc = sm + F_SCR + s2_m * SCP + s2_h0;
            *reinterpret_cast<float4*>(sc)     = make_float4(rowv[0], rowv[1], rowv[2], rowv[3]);
            *reinterpret_cast<float4*>(sc + 4) = make_float4(rowv[4], rowv[5], rowv[6], rowv[7]);
        }
        __syncthreads();   // (B)
        if (s2_kh == 0) {
            const float* sc = sm + F_SCR + s2_m * SCP + s2_h0;
            float4 r0 = *reinterpret_cast<const float4*>(sc);
            float4 r1 = *reinterpret_cast<const float4*>(sc + 4);
            rowv[0] += r0.x + eft[0]; rowv[1] += r0.y + eft[1];
            rowv[2] += r0.z + eft[2]; rowv[3] += r0.w + eft[3];
            rowv[4] += r1.x + eft[4]; rowv[5] += r1.y + eft[5];
            rowv[6] += r1.z + eft[6]; rowv[7] += r1.w + eft[7];
            const size_t bh = (size_t)b * HDIM;
            #pragma unroll
            for (int j = 0; j < 8; j++) {
                int h = s2_h0 + j;
                float v = rowv[j] + sm[F_B2 + h];
                out[((bh + h) * NTOT + rowi) * NTOT + j0 + s2_m] = v;
                if (wrM)
                    out[((bh + h) * NTOT + (j0 + s2_m)) * NTOT + rowi] = v - corr[j];
            }
        }
        cur ^= 1;
    }
}

// =====================  EXACT KERNEL (fallback; returns if table path active)  ==
__global__ __launch_bounds__(512, 1)
void fused_distbias_kernel(
    const float* __restrict__ pos,
    const int*   __restrict__ etype,
    const float* __restrict__ mw,
    const float* __restrict__ bw,
    const float* __restrict__ means,
    const float* __restrict__ stds,
    const float* __restrict__ ow1,
    const float* __restrict__ ob1,
    const float* __restrict__ ow2,
    const float* __restrict__ ob2,
    const float* __restrict__ vw1,
    const float* __restrict__ vb1,
    const float* __restrict__ vw2,
    const float* __restrict__ vb2,
    float* __restrict__ out,
    int nE)
{
    extern __shared__ float sm[];
    const int tid = threadIdx.x;
    int* iflags = reinterpret_cast<int*>(sm + OFF_FLAG);
    compute_flags(iflags, vb1, stds, mw, bw, nE, tid, 512);
    const int vbzero = iflags[0];
    const int fastmode = iflags[0] & iflags[1];
    if (fastmode & iflags[2]) return;   // fast kernel handles it
    const int ntiles = fastmode ? NTILES_FAST : NTILES_SLOW;

    for (int i = tid; i < 64 * 128; i += 512) {
        int kp = i >> 7, c = i & 127;
        sm[OFF_OW1 + kp * 256 + 2 * c]     = ow1[(2 * kp) * KDIM + c];
        sm[OFF_OW1 + kp * 256 + 2 * c + 1] = ow1[(2 * kp + 1) * KDIM + c];
    }
    for (int i = tid; i < 64 * 32; i += 512) {
        int kp = i >> 5, h = i & 31;
        sm[OFF_OW2 + kp * 64 + 2 * h]     = ow2[(2 * kp) * HDIM + h];
        sm[OFF_OW2 + kp * 64 + 2 * h + 1] = ow2[(2 * kp + 1) * HDIM + h];
        sm[OFF_VW2 + kp * 64 + 2 * h]     = vw2[(2 * kp) * HDIM + h];
        sm[OFF_VW2 + kp * 64 + 2 * h + 1] = vw2[(2 * kp + 1) * HDIM + h];
    }
    if (tid < 3 * KDIM) sm[OFF_VW1 + tid] = vw1[tid];
    if (tid < KDIM) {
        sm[OFF_VB1 + tid] = vb1[tid];
        sm[OFF_OB1 + tid] = ob1[tid];
        float s  = fabsf(stds[tid]) + 1e-5f;
        float is = 1.0f / s;
        sm[OFF_MEAN + tid] = means[tid];
        sm[OFF_ISTD + tid] = is;
        sm[OFF_COEF + tid] = is * (1.0f / sqrtf(2.0f * 3.14159f));
    }
    if (tid < HDIM) sm[OFF_B2 + tid] = ob2[tid] + vb2[tid];
    __syncthreads();
    if (tid < 96) {
        int d = tid >> 5, h = tid & 31;
        float s = 0.0f;
        for (int kp = 0; kp < 64; kp++) {
            float2 a = *reinterpret_cast<float2*>(sm + OFF_VW1 + d * 128 + 2 * kp);
            float2 w = *reinterpret_cast<float2*>(sm + OFF_VW2 + kp * 64 + 2 * h);
            s += a.x * w.x + a.y * w.y;
        }
        sm[OFF_TVV + d * 32 + h] = s;
    }

    const int gm  = tid & 63;
    const int gkc = tid >> 6;
    const int s1_wid = tid >> 5, s1_lane = tid & 31;
    const int s1_wm = s1_wid & 3, s1_wn = s1_wid >> 2;
    const int s1_mg = s1_lane >> 3, s1_ng = s1_lane & 7;
    const int s1_mbase = s1_wm * 16 + s1_mg * 4;
    const int s1_cbase = s1_wn * 32;
    const int s1_npA   = s1_wn * 16 + s1_ng;
    const int s2_hg = (tid >> 5) & 3;
    const int s2_kh = (tid >> 7) & 1;
    const int s2_mh = tid >> 8;
    const int s2_h0 = s2_hg * 8;
    const int s2_m  = s2_mh * 32 + (tid & 31);

    {
        int b0, ri0, j00, w0;
        decode_tile((int)blockIdx.x, fastmode, b0, ri0, j00, w0);
        if ((int)blockIdx.x < ntiles && tid < 64) {
            float4 m = load_meta(pos, etype, mw, bw, b0, ri0, j00 + tid);
            *reinterpret_cast<float4*>(sm + OFF_DLM4 + tid * 4) = m;
        }
    }
    __syncthreads();

    int cur = 0, zi = 0;
    for (int t = blockIdx.x; t < ntiles; t += gridDim.x, zi++) {
        int b, rowi, j0, wrM;
        decode_tile(t, fastmode, b, rowi, j0, wrM);

        if (zi < NZI) {
            #pragma unroll
            for (int zz = 0; zz < 3; zz++) {
                int idx = ((zi * 3 + zz) * GRIDX + (int)blockIdx.x) * 512 + tid;
                if (idx < ZTOT_F4) {
                    int jq = idx % 192;
                    int r  = idx / 192;
                    int ip = r % 768;
                    int bhh = r / 768;
                    size_t addr = (((size_t)bhh << 10) + 256 + ip) * 1024 + 256 + 4 * jq;
                    *reinterpret_cast<float4*>(out + addr) = make_float4(0.f, 0.f, 0.f, 0.f);
                }
            }
        }

        const int tn = t + gridDim.x;
        float4 pf;
        const bool havePf = (tn < ntiles) && (tid < 64);
        if (havePf) {
            int bn, rin, j0n, wn;
            decode_tile(tn, fastmode, bn, rin, j0n, wn);
            pf = load_meta(pos, etype, mw, bw, bn, rin, j0n + tid);
        }

        {
            float4 dm = *reinterpret_cast<float4*>(sm + OFF_DLM4 + cur * 256 + gm * 4);
            #pragma unroll
            for (int i = 0; i < 8; i++) {
                int kp = gkc * 8 + i;
                float2 mn = *reinterpret_cast<float2*>(sm + OFF_MEAN + 2 * kp);
                float2 is = *reinterpret_cast<float2*>(sm + OFF_ISTD + 2 * kp);
                float2 cf = *reinterpret_cast<float2*>(sm + OFF_COEF + 2 * kp);
                float2 w0 = *reinterpret_cast<float2*>(sm + OFF_VW1 + 2 * kp);
                float2 w1 = *reinterpret_cast<float2*>(sm + OFF_VW1 + 128 + 2 * kp);
                float2 w2 = *reinterpret_cast<float2*>(sm + OFF_VW1 + 256 + 2 * kp);
                float2 vb = *reinterpret_cast<float2*>(sm + OFF_VB1 + 2 * kp);
                float tx = (dm.w - mn.x) * is.x;
                float ty = (dm.w - mn.y) * is.y;
                float2 g = make_float2(__expf(-0.5f * tx * tx) * cf.x,
                                       __expf(-0.5f * ty * ty) * cf.y);
                float sx = dm.x * w0.x + dm.y * w1.x + dm.z * w2.x + vb.x;
                float sy = dm.x * w0.y + dm.y * w1.y + dm.z * w2.y + vb.y;
                float2 v1 = make_float2(fast_gelu(sx), fast_gelu(sy));
                *reinterpret_cast<float2*>(sm + OFF_GP  + kp * PP + 2 * gm) = g;
                *reinterpret_cast<float2*>(sm + OFF_VP1 + kp * PP + 2 * gm) = v1;
            }
        }
        if (havePf)
            *reinterpret_cast<float4*>(sm + OFF_DLM4 + (cur ^ 1) * 256 + tid * 4) = pf;
        __syncthreads();

        {
            ull acc[4][4];
            #pragma unroll
            for (int r = 0; r < 4; r++)
                #pragma unroll
                for (int j = 0; j < 4; j++) acc[r][j] = 0ull;
            const float* gpB = sm + OFF_GP + 2 * s1_mbase;
            const float* w1B = sm + OFF_OW1 + 2 * s1_cbase + 4 * s1_ng;
            #pragma unroll 4
            for (int kp = 0; kp < 64; kp++) {
                ulonglong2 g01 = *reinterpret_cast<const ulonglong2*>(gpB + kp * PP);
                ulonglong2 g23 = *reinterpret_cast<const ulonglong2*>(gpB + kp * PP + 4);
                ulonglong2 wA  = *reinterpret_cast<const ulonglong2*>(w1B + kp * 256);
                ulonglong2 wB  = *reinterpret_cast<const ulonglong2*>(w1B + kp * 256 + 32);
                acc[0][0] = ffma2(g01.x, wA.x, acc[0][0]);
                acc[0][1] = ffma2(g01.x, wA.y, acc[0][1]);
                acc[0][2] = ffma2(g01.x, wB.x, acc[0][2]);
                acc[0][3] = ffma2(g01.x, wB.y, acc[0][3]);
                acc[1][0] = ffma2(g01.y, wA.x, acc[1][0]);
                acc[1][1] = ffma2(g01.y, wA.y, acc[1][1]);
                acc[1][2] = ffma2(g01.y, wB.x, acc[1][2]);
                acc[1][3] = ffma2(g01.y, wB.y, acc[1][3]);
                acc[2][0] = ffma2(g23.x, wA.x, acc[2][0]);
                acc[2][1] = ffma2(g23.x, wA.y, acc[2][1]);
                acc[2][2] = ffma2(g23.x, wB.x, acc[2][2]);
                acc[2][3] = ffma2(g23.x, wB.y, acc[2][3]);
                acc[3][0] = ffma2(g23.y, wA.x, acc[3][0]);
                acc[3][1] = ffma2(g23.y, wA.y, acc[3][1]);
                acc[3][2] = ffma2(g23.y, wB.x, acc[3][2]);
                acc[3][3] = ffma2(g23.y, wB.y, acc[3][3]);
            }
            float2 obA = *reinterpret_cast<float2*>(sm + OFF_OB1 + s1_cbase + 2 * s1_ng);
            float2 obB = *reinterpret_cast<float2*>(sm + OFF_OB1 + s1_cbase + 2 * s1_ng + 16);
            #pragma unroll
            for (int r = 0; r < 4; r++) {
                int m = s1_mbase + r;
                float2 hA = make_float2(fast_gelu(hadd2(acc[r][0]) + obA.x),
                                        fast_gelu(hadd2(acc[r][1]) + obA.y));
                float2 hB = make_float2(fast_gelu(hadd2(acc[r][2]) + obB.x),
                                        fast_gelu(hadd2(acc[r][3]) + obB.y));
                *reinterpret_cast<float2*>(sm + OFF_H1P + s1_npA * PP + 2 * m) = hA;
                *reinterpret_cast<float2*>(sm + OFF_H1P + (s1_npA + 8) * PP + 2 * m) = hB;
            }
        }
        __syncthreads();

        float rowv[8];
        {
            const float* hB = sm + OFF_H1P + s2_kh * 32 * PP + 2 * s2_m;
            const float* vB = sm + OFF_VP1 + s2_kh * 32 * PP + 2 * s2_m;
            const float* oB = sm + OFF_OW2 + s2_kh * 2048 + 2 * s2_h0;
            const float* wB = sm + OFF_VW2 + s2_kh * 2048 + 2 * s2_h0;
            ull R[8];
            #pragma unroll
            for (int j = 0; j < 8; j++) R[j] = 0ull;
            #pragma unroll 4
            for (int i = 0; i < 32; i++) {
                ull hp = *reinterpret_cast<const ull*>(hB + i * PP);
                ull vp = *reinterpret_cast<const ull*>(vB + i * PP);
                ulonglong2 o01 = *reinterpret_cast<const ulonglong2*>(oB + i * 64);
                ulonglong2 o23 = *reinterpret_cast<const ulonglong2*>(oB + i * 64 + 4);
                ulonglong2 o45 = *reinterpret_cast<const ulonglong2*>(oB + i * 64 + 8);
                ulonglong2 o67 = *reinterpret_cast<const ulonglong2*>(oB + i * 64 + 12);
                R[0] = ffma2(hp, o01.x, R[0]); R[1] = ffma2(hp, o01.y, R[1]);
                R[2] = ffma2(hp, o23.x, R[2]); R[3] = ffma2(hp, o23.y, R[3]);
                R[4] = ffma2(hp, o45.x, R[4]); R[5] = ffma2(hp, o45.y, R[5]);
                R[6] = ffma2(hp, o67.x, R[6]); R[7] = ffma2(hp, o67.y, R[7]);
                ulonglong2 v01 = *reinterpret_cast<const ulonglong2*>(wB + i * 64);
                ulonglong2 v23 = *reinterpret_cast<const ulonglong2*>(wB + i * 64 + 4);
                ulonglong2 v45 = *reinterpret_cast<const ulonglong2*>(wB + i * 64 + 8);
                ulonglong2 v67 = *reinterpret_cast<const ulonglong2*>(wB + i * 64 + 12);
                R[0] = ffma2(vp, v01.x, R[0]); R[1] = ffma2(vp, v01.y, R[1]);
                R[2] = ffma2(vp, v23.x, R[2]); R[3] = ffma2(vp, v23.y, R[3]);
                R[4] = ffma2(vp, v45.x, R[4]); R[5] = ffma2(vp, v45.y, R[5]);
                R[6] = ffma2(vp, v67.x, R[6]); R[7] = ffma2(vp, v67.y, R[7]);
            }
            #pragma unroll
            for (int j = 0; j < 8; j++) rowv[j] = hadd2(R[j]);
        }
        float corr[8];
        if (wrM && vbzero && s2_kh == 0) {
            float4 dmv = *reinterpret_cast<float4*>(sm + OFF_DLM4 + cur * 256 + s2_m * 4);
            #pragma unroll
            for (int j = 0; j < 8; j++) {
                int h = s2_h0 + j;
                corr[j] = dmv.x * sm[OFF_TVV + h]
                        + dmv.y * sm[OFF_TVV + 32 + h]
                        + dmv.z * sm[OFF_TVV + 64 + h];
            }
        }
        if (s2_kh) {
            float* sc = sm + OFF_SCR + s2_m * SCP + s2_h0;
            *reinterpret_cast<float4*>(sc)     = make_float4(rowv[0], rowv[1], rowv[2], rowv[3]);
            *reinterpret_cast<float4*>(sc + 4) = make_float4(rowv[4], rowv[5], rowv[6], rowv[7]);
        }
        __syncthreads();
        if (s2_kh == 0) {
            const float* sc = sm + OFF_SCR + s2_m * SCP + s2_h0;
            float4 r0 = *reinterpret_cast<const float4*>(sc);
            float4 r1 = *reinterpret_cast<const float4*>(sc + 4);
            rowv[0] += r0.x; rowv[1] += r0.y; rowv[2] += r0.z; rowv[3] += r0.w;
            rowv[4] += r1.x; rowv[5] += r1.y; rowv[6] += r1.z; rowv[7] += r1.w;
            const size_t bh = (size_t)b * HDIM;
            #pragma unroll
            for (int j = 0; j < 8; j++) {
                int h = s2_h0 + j;
                float v = rowv[j] + sm[OFF_B2 + h];
                out[((bh + h) * NTOT + rowi) * NTOT + j0 + s2_m] = v;
                if (wrM && vbzero)
                    out[((bh + h) * NTOT + (j0 + s2_m)) * NTOT + rowi] = v - corr[j];
            }
        }

        if (wrM && !vbzero) {
            float dp[8];
            {
                float4 dmv = *reinterpret_cast<float4*>(sm + OFF_DLM4 + cur * 256 + s2_m * 4);
                const float* vB = sm + OFF_VP1 + s2_kh * 32 * PP + 2 * s2_m;
                const float* wB = sm + OFF_VW2 + s2_kh * 2048 + 2 * s2_h0;
                ull D[8];
                #pragma unroll
                for (int j = 0; j < 8; j++) D[j] = 0ull;
                for (int i = 0; i < 32; i++) {
                    int kp = s2_kh * 32 + i;
                    float2 w0 = *reinterpret_cast<float2*>(sm + OFF_VW1 + 2 * kp);
                    float2 w1 = *reinterpret_cast<float2*>(sm + OFF_VW1 + 128 + 2 * kp);
                    float2 w2 = *reinterpret_cast<float2*>(sm + OFF_VW1 + 256 + 2 * kp);
                    float2 vb = *reinterpret_cast<float2*>(sm + OFF_VB1 + 2 * kp);
                    float sx = dmv.x * w0.x + dmv.y * w1.x + dmv.z * w2.x + vb.x;
                    float sy = dmv.x * w0.y + dmv.y * w1.y + dmv.z * w2.y + vb.y;
                    float2 pv = u2f2(*reinterpret_cast<const ull*>(vB + i * PP));
                    ull dq = f2pack(fast_gelu(2.0f * vb.x - sx) - pv.x,
                                    fast_gelu(2.0f * vb.y - sy) - pv.y);
                    ulonglong2 v01 = *reinterpret_cast<const ulonglong2*>(wB + i * 64);
                    ulonglong2 v23 = *reinterpret_cast<const ulonglong2*>(wB + i * 64 + 4);
                    ulonglong2 v45 = *reinterpret_cast<const ulonglong2*>(wB + i * 64 + 8);
                    ulonglong2 v67 = *reinterpret_cast<const ulonglong2*>(wB + i * 64 + 12);
                    D[0] = ffma2(dq, v01.x, D[0]); D[1] = ffma2(dq, v01.y, D[1]);
                    D[2] = ffma2(dq, v23.x, D[2]); D[3] = ffma2(dq, v23.y, D[3]);
                    D[4] = ffma2(dq, v45.x, D[4]); D[5] = ffma2(dq, v45.y, D[5]);
                    D[6] = ffma2(dq, v67.x, D[6]); D[7] = ffma2(dq, v67.y, D[7]);
                }
                #pragma unroll
                for (int j = 0; j < 8; j++) dp[j] = hadd2(D[j]);
            }
            __syncthreads();
            if (s2_kh) {
                float* sc = sm + OFF_SCR + s2_m * SCP + s2_h0;
                *reinterpret_cast<float4*>(sc)     = make_float4(dp[0], dp[1], dp[2], dp[3]);
                *reinterpret_cast<float4*>(sc + 4) = make_float4(dp[4], dp[5], dp[6], dp[7]);
            }
            __syncthreads();
            if (s2_kh == 0) {
                const float* sc = sm + OFF_SCR + s2_m * SCP + s2_h0;
                float4 r0 = *reinterpret_cast<const float4*>(sc);
                float4 r1 = *reinterpret_cast<const float4*>(sc + 4);
                dp[0] += r0.x; dp[1] += r0.y; dp[2] += r0.z; dp[3] += r0.w;
                dp[4] += r1.x; dp[5] += r1.y; dp[6] += r1.z; dp[7] += r1.w;
                const size_t bh = (size_t)b * HDIM;
                #pragma unroll
                for (int j = 0; j < 8; j++) {
                    int h = s2_h0 + j;
                    float v = rowv[j] + dp[j] + sm[OFF_B2 + h];
                    out[((bh + h) * NTOT + (j0 + s2_m)) * NTOT + rowi] = v;
                }
            }
        }
        cur ^= 1;
    }
}

extern "C" void kernel_launch(void* const* d_in, const int* in_sizes, int n_in,
                              void* d_out, int out_size) {
    const float* pos    = (const float*)d_in[0];
    const int*   etype  = (const int*)d_in[1];
    const float* means  = (const float*)d_in[3];
    const float* stds   = (const float*)d_in[4];
    const float* mul_w  = (const float*)d_in[5];
    const float* bias_w = (const float*)d_in[6];
    const float* ow1    = (const float*)d_in[7];
    const float* ob1    = (const float*)d_in[8];
    const float* ow2    = (const float*)d_in[9];
    const float* ob2    = (const float*)d_in[10];
    const float* vw1    = (const float*)d_in[11];
    const float* vb1    = (const float*)d_in[12];
    const float* vw2    = (const float*)d_in[13];
    const float* vb2    = (const float*)d_in[14];
    float* out = (float*)d_out;
    int nE = in_sizes[5];

    cudaFuncSetAttribute(build_tab_kernel,
                         cudaFuncAttributeMaxDynamicSharedMemorySize, SMEM_BYTES);
    cudaFuncSetAttribute(fast_tab_kernel,
                         cudaFuncAttributeMaxDynamicSharedMemorySize, FSMEM_BYTES);
    cudaFuncSetAttribute(fused_distbias_kernel,
                         cudaFuncAttributeMaxDynamicSharedMemorySize, SMEM_BYTES);

    build_tab_kernel<<<GRIDX, 512, SMEM_BYTES>>>(
        mul_w, bias_w, means, stds, ow1, ob1, ow2, vb1, nE);

    fast_tab_kernel<<<GRIDF, 512, FSMEM_BYTES>>>(
        pos, etype, mul_w, bias_w, stds, ob2, vw1, vb1, vw2, vb2, out, nE);

    fused_distbias_kernel<<<GRIDX, 512, SMEM_BYTES>>>(
        pos, etype, mul_w, bias_w, means, stds,
        ow1, ob1, ow2, ob2, vw1, vb1, vw2, vb2, out, nE);
}

// round 15
// speedup vs baseline: 3.1528x; 1.0989x over previous
#include <cuda_runtime.h>
#include <math.h>

typedef unsigned long long ull;

#define BDIM 2
#define NTOT 1024
#define PLEN 768
#define LLEN 256
#define KDIM 128
#define HDIM 32
#define TABN 8192

constexpr int PP = 132;
constexpr int NT_LP = BDIM * PLEN * 4;           // 6144
constexpr int NT_LL_SLOW = BDIM * LLEN * 4;      // 2048
constexpr int NTILES_SLOW = NT_LL_SLOW + NT_LP;  // 8192
constexpr int NT_LL_FAST = BDIM * 640;           // 1280
constexpr int NTILES_FAST = NT_LL_FAST + NT_LP;  // 7424
constexpr int NTAB_TILES = TABN / 64;            // 128

constexpr int GRIDX = 148;
constexpr int GRIDF = 296;
constexpr int ZTOT_F4 = BDIM * HDIM * PLEN * (PLEN / 4);   // 9437184
constexpr int NZI  = (ZTOT_F4 + 3 * GRIDX * 512 - 1) / (3 * GRIDX * 512);  // 42
constexpr int NZIF = (ZTOT_F4 + 3 * GRIDF * 512 - 1) / (3 * GRIDF * 512);  // 21

// mirror transpose kernel tiling: 192 LP tiles + 24 LL-upper tiles per (b,h)
constexpr int NTT_PER_BH = 216;
constexpr int NTT_TOTAL  = NTT_PER_BH * BDIM * HDIM;   // 13824

// ---------- big-smem layout (exact + build kernels) ----------
constexpr int OFF_OW1  = 0;
constexpr int OFF_OW2  = 16384;
constexpr int OFF_VW2  = 20480;
constexpr int OFF_TVV  = 24576;
constexpr int OFF_VW1  = 24672;
constexpr int OFF_VB1  = 25056;
constexpr int OFF_OB1  = 25184;
constexpr int OFF_MEAN = 25312;
constexpr int OFF_ISTD = 25440;
constexpr int OFF_COEF = 25568;
constexpr int OFF_B2   = 25696;
constexpr int OFF_FLAG = 25728;
constexpr int OFF_DLM4 = 25732;
constexpr int OFF_GP   = 26244;
constexpr int OFF_VP1  = OFF_GP + 64 * PP;       // 34692
constexpr int OFF_H1P  = OFF_VP1 + 64 * PP;      // 43140
constexpr int SCP = 36;
constexpr int SCSTRIDE = 64 * SCP;               // 2304
constexpr int OFF_SCR  = OFF_H1P + 64 * PP;      // 51588
constexpr int SMEM_FLOATS = OFF_SCR + SCSTRIDE;  // 53892
constexpr int SMEM_BYTES  = SMEM_FLOATS * 4;     // 215568

// ---------- slim layout (fast kernel) ----------
constexpr int F_VW2  = 0;                        // 4096
constexpr int F_VW1  = 4096;                     // 384
constexpr int F_B2   = 4480;                     // 32
constexpr int F_FLAG = 4512;                     // 4
constexpr int F_DLM4 = 4516;                     // 512 (2 buffers); 4516*4%16==0
constexpr int F_VP1  = 5028;                     // 8448; 5028*4%16==0
constexpr int F_SCR  = F_VP1 + 64 * PP;          // 13476; *4%16==0
constexpr int FSMEM_FLOATS = F_SCR + SCSTRIDE;   // 15780
constexpr int FSMEM_BYTES  = FSMEM_FLOATS * 4;   // 63120

__device__ __align__(16) float g_tab[TABN * HDIM];

__device__ __forceinline__ ull ffma2(ull a, ull b, ull c) {
    ull d; asm("fma.rn.f32x2 %0,%1,%2,%3;" : "=l"(d) : "l"(a), "l"(b), "l"(c)); return d;
}
__device__ __forceinline__ float2 u2f2(ull v) {
    float2 f; asm("mov.b64 {%0,%1},%2;" : "=f"(f.x), "=f"(f.y) : "l"(v)); return f;
}
__device__ __forceinline__ ull f2pack(float x, float y) {
    ull r; asm("mov.b64 %0,{%1,%2};" : "=l"(r) : "f"(x), "f"(y)); return r;
}
__device__ __forceinline__ float hadd2(ull v) { float2 f = u2f2(v); return f.x + f.y; }

__device__ __forceinline__ float fast_gelu(float x) {
    float y  = x * 0.70710678118654752f;
    float ax = fabsf(y);
    float t  = __fdividef(1.0f, fmaf(0.3275911f, ax, 1.0f));
    float p  = fmaf(t, 1.061405429f, -1.453152027f);
    p = fmaf(t, p, 1.421413741f);
    p = fmaf(t, p, -0.284496736f);
    p = fmaf(t, p, 0.254829592f);
    p *= t;
    float e = __expf(-ax * ax);
    float erfv = copysignf(fmaf(-p, e, 1.0f), y);
    return 0.5f * x * (1.0f + erfv);
}

__device__ __forceinline__ void decode_tile(int t, int fastmode,
                                            int& b, int& rowi, int& j0, int& wrM) {
    if (fastmode) {
        if (t < NT_LL_FAST) {
            b = t / 640; int r = t - b * 640;
            if (r < 256) { rowi = r; j0 = r & 192; wrM = 0; }
            else {
                int r2 = r - 256; int pr = r2 >> 6;
                int br = (pr < 3) ? 0 : ((pr < 5) ? 1 : 2);
                int bc = (pr == 0) ? 1 : ((pr == 1 || pr == 3) ? 2 : 3);
                rowi = br * 64 + (r2 & 63); j0 = bc * 64; wrM = 1;
            }
        } else {
            int u = t - NT_LL_FAST; b = u / 3072; int r = u - b * 3072;
            rowi = LLEN + (r >> 2); j0 = (r & 3) << 6; wrM = 1;
        }
    } else {
        if (t < NT_LL_SLOW) {
            b = t >> 10; int r = t & 1023;
            rowi = r >> 2; j0 = (r & 3) << 6; wrM = 0;
        } else {
            int u = t - NT_LL_SLOW; b = u / 3072; int r = u - b * 3072;
            rowi = LLEN + (r >> 2); j0 = (r & 3) << 6; wrM = 1;
        }
    }
}

__device__ __forceinline__ float4 load_meta(const float* pos, const int* etype,
                                            const float* mw, const float* bw,
                                            int b, int rowi, int j) {
    const float* pj = pos + ((size_t)b * NTOT + j) * 3;
    const float* pi = pos + ((size_t)b * NTOT + rowi) * 3;
    float d0 = pj[0] - pi[0];
    float d1 = pj[1] - pi[1];
    float d2 = pj[2] - pi[2];
    float d = 1.0f / (d0 * d0 + d1 * d1 + d2 * d2 + 1.0f);
    int e = etype[((size_t)b * NTOT + rowi) * NTOT + j];
    return make_float4(d0, d1, d2, mw[e] * d + bw[e]);
}

__device__ __forceinline__ void compute_flags(int* ifl, const float* vb1,
                                              const float* stds, const float* mw,
                                              const float* bw, int nE, int tid, int nthr) {
    if (tid == 0) { ifl[0] = 1; ifl[1] = 1; ifl[2] = 1; }
    __syncthreads();
    if (tid < KDIM && vb1[tid] != 0.0f) atomicAnd(&ifl[0], 0);
    if (tid < KDIM) {
        float s = fabsf(stds[tid]) + 1e-5f;
        if (s < 0.004f) atomicAnd(&ifl[2], 0);
    }
    float m0v = mw[0], b0v = bw[0];
    for (int i = tid; i < nE; i += nthr)
        if (mw[i] != m0v || bw[i] != b0v) atomicAnd(&ifl[1], 0);
    __syncthreads();
}

// =====================  TABLE BUILD KERNEL  =====================
__global__ __launch_bounds__(512, 1)
void build_tab_kernel(const float* __restrict__ mw, const float* __restrict__ bw,
                      const float* __restrict__ means, const float* __restrict__ stds,
                      const float* __restrict__ ow1, const float* __restrict__ ob1,
                      const float* __restrict__ ow2, const float* __restrict__ vb1,
                      int nE)
{
    extern __shared__ float sm[];
    const int tid = threadIdx.x;
    int* iflags = reinterpret_cast<int*>(sm + OFF_FLAG);
    compute_flags(iflags, vb1, stds, mw, bw, nE, tid, 512);
    if (!(iflags[0] & iflags[1] & iflags[2])) return;

    for (int i = tid; i < 64 * 128; i += 512) {
        int kp = i >> 7, c = i & 127;
        sm[OFF_OW1 + kp * 256 + 2 * c]     = ow1[(2 * kp) * KDIM + c];
        sm[OFF_OW1 + kp * 256 + 2 * c + 1] = ow1[(2 * kp + 1) * KDIM + c];
    }
    for (int i = tid; i < 64 * 32; i += 512) {
        int kp = i >> 5, h = i & 31;
        sm[OFF_OW2 + kp * 64 + 2 * h]     = ow2[(2 * kp) * HDIM + h];
        sm[OFF_OW2 + kp * 64 + 2 * h + 1] = ow2[(2 * kp + 1) * HDIM + h];
    }
    if (tid < KDIM) {
        sm[OFF_OB1 + tid] = ob1[tid];
        float s  = fabsf(stds[tid]) + 1e-5f;
        float is = 1.0f / s;
        sm[OFF_MEAN + tid] = means[tid];
        sm[OFF_ISTD + tid] = is;
        sm[OFF_COEF + tid] = is * (1.0f / sqrtf(2.0f * 3.14159f));
    }
    __syncthreads();

    const float m0v = mw[0], b0v = bw[0];
    const float lo = fminf(b0v, m0v + b0v);
    const float span = fmaxf(b0v, m0v + b0v) - lo;
    const float step = span / (float)(TABN - 1);

    const int gm  = tid & 63;
    const int gkc = tid >> 6;
    const int s1_wid = tid >> 5, s1_lane = tid & 31;
    const int s1_wm = s1_wid & 3, s1_wn = s1_wid >> 2;
    const int s1_mg = s1_lane >> 3, s1_ng = s1_lane & 7;
    const int s1_mbase = s1_wm * 16 + s1_mg * 4;
    const int s1_cbase = s1_wn * 32;
    const int s1_npA   = s1_wn * 16 + s1_ng;
    const int s2_hg = (tid >> 5) & 3;
    const int s2_kh = (tid >> 7) & 1;
    const int s2_mh = tid >> 8;
    const int s2_h0 = s2_hg * 8;
    const int s2_m  = s2_mh * 32 + (tid & 31);

    for (int t = blockIdx.x; t < NTAB_TILES; t += gridDim.x) {
        {
            float x0 = lo + (float)(t * 64 + gm) * step;
            #pragma unroll
            for (int i = 0; i < 8; i++) {
                int kp = gkc * 8 + i;
                float2 mn = *reinterpret_cast<float2*>(sm + OFF_MEAN + 2 * kp);
                float2 is = *reinterpret_cast<float2*>(sm + OFF_ISTD + 2 * kp);
                float2 cf = *reinterpret_cast<float2*>(sm + OFF_COEF + 2 * kp);
                float tx = (x0 - mn.x) * is.x;
                float ty = (x0 - mn.y) * is.y;
                float2 g = make_float2(__expf(-0.5f * tx * tx) * cf.x,
                                       __expf(-0.5f * ty * ty) * cf.y);
                *reinterpret_cast<float2*>(sm + OFF_GP + kp * PP + 2 * gm) = g;
            }
        }
        __syncthreads();
        {
            ull acc[4][4];
            #pragma unroll
            for (int r = 0; r < 4; r++)
                #pragma unroll
                for (int j = 0; j < 4; j++) acc[r][j] = 0ull;
            const float* gpB = sm + OFF_GP + 2 * s1_mbase;
            const float* w1B = sm + OFF_OW1 + 2 * s1_cbase + 4 * s1_ng;
            #pragma unroll 4
            for (int kp = 0; kp < 64; kp++) {
                ulonglong2 g01 = *reinterpret_cast<const ulonglong2*>(gpB + kp * PP);
                ulonglong2 g23 = *reinterpret_cast<const ulonglong2*>(gpB + kp * PP + 4);
                ulonglong2 wA  = *reinterpret_cast<const ulonglong2*>(w1B + kp * 256);
                ulonglong2 wB  = *reinterpret_cast<const ulonglong2*>(w1B + kp * 256 + 32);
                acc[0][0] = ffma2(g01.x, wA.x, acc[0][0]);
                acc[0][1] = ffma2(g01.x, wA.y, acc[0][1]);
                acc[0][2] = ffma2(g01.x, wB.x, acc[0][2]);
                acc[0][3] = ffma2(g01.x, wB.y, acc[0][3]);
                acc[1][0] = ffma2(g01.y, wA.x, acc[1][0]);
                acc[1][1] = ffma2(g01.y, wA.y, acc[1][1]);
                acc[1][2] = ffma2(g01.y, wB.x, acc[1][2]);
                acc[1][3] = ffma2(g01.y, wB.y, acc[1][3]);
                acc[2][0] = ffma2(g23.x, wA.x, acc[2][0]);
                acc[2][1] = ffma2(g23.x, wA.y, acc[2][1]);
                acc[2][2] = ffma2(g23.x, wB.x, acc[2][2]);
                acc[2][3] = ffma2(g23.x, wB.y, acc[2][3]);
                acc[3][0] = ffma2(g23.y, wA.x, acc[3][0]);
                acc[3][1] = ffma2(g23.y, wA.y, acc[3][1]);
                acc[3][2] = ffma2(g23.y, wB.x, acc[3][2]);
                acc[3][3] = ffma2(g23.y, wB.y, acc[3][3]);
            }
            float2 obA = *reinterpret_cast<float2*>(sm + OFF_OB1 + s1_cbase + 2 * s1_ng);
            float2 obB = *reinterpret_cast<float2*>(sm + OFF_OB1 + s1_cbase + 2 * s1_ng + 16);
            #pragma unroll
            for (int r = 0; r < 4; r++) {
                int m = s1_mbase + r;
                float2 hA = make_float2(fast_gelu(hadd2(acc[r][0]) + obA.x),
                                        fast_gelu(hadd2(acc[r][1]) + obA.y));
                float2 hB = make_float2(fast_gelu(hadd2(acc[r][2]) + obB.x),
                                        fast_gelu(hadd2(acc[r][3]) + obB.y));
                *reinterpret_cast<float2*>(sm + OFF_H1P + s1_npA * PP + 2 * m) = hA;
                *reinterpret_cast<float2*>(sm + OFF_H1P + (s1_npA + 8) * PP + 2 * m) = hB;
            }
        }
        __syncthreads();
        float rowv[8];
        {
            const float* hB = sm + OFF_H1P + s2_kh * 32 * PP + 2 * s2_m;
            const float* oB = sm + OFF_OW2 + s2_kh * 2048 + 2 * s2_h0;
            ull R[8];
            #pragma unroll
            for (int j = 0; j < 8; j++) R[j] = 0ull;
            #pragma unroll 4
            for (int i = 0; i < 32; i++) {
                ull hp = *reinterpret_cast<const ull*>(hB + i * PP);
                ulonglong2 o01 = *reinterpret_cast<const ulonglong2*>(oB + i * 64);
                ulonglong2 o23 = *reinterpret_cast<const ulonglong2*>(oB + i * 64 + 4);
                ulonglong2 o45 = *reinterpret_cast<const ulonglong2*>(oB + i * 64 + 8);
                ulonglong2 o67 = *reinterpret_cast<const ulonglong2*>(oB + i * 64 + 12);
                R[0] = ffma2(hp, o01.x, R[0]); R[1] = ffma2(hp, o01.y, R[1]);
                R[2] = ffma2(hp, o23.x, R[2]); R[3] = ffma2(hp, o23.y, R[3]);
                R[4] = ffma2(hp, o45.x, R[4]); R[5] = ffma2(hp, o45.y, R[5]);
                R[6] = ffma2(hp, o67.x, R[6]); R[7] = ffma2(hp, o67.y, R[7]);
            }
            #pragma unroll
            for (int j = 0; j < 8; j++) rowv[j] = hadd2(R[j]);
        }
        if (s2_kh) {
            float* sc = sm + OFF_SCR + s2_m * SCP + s2_h0;
            *reinterpret_cast<float4*>(sc)     = make_float4(rowv[0], rowv[1], rowv[2], rowv[3]);
            *reinterpret_cast<float4*>(sc + 4) = make_float4(rowv[4], rowv[5], rowv[6], rowv[7]);
        }
        __syncthreads();
        if (s2_kh == 0) {
            const float* sc = sm + OFF_SCR + s2_m * SCP + s2_h0;
            float4 r0 = *reinterpret_cast<const float4*>(sc);
            float4 r1 = *reinterpret_cast<const float4*>(sc + 4);
            int row = t * 64 + s2_m;
            float4 w0 = make_float4(rowv[0] + r0.x, rowv[1] + r0.y,
                                    rowv[2] + r0.z, rowv[3] + r0.w);
            float4 w1 = make_float4(rowv[4] + r1.x, rowv[5] + r1.y,
                                    rowv[6] + r1.z, rowv[7] + r1.w);
            *reinterpret_cast<float4*>(g_tab + (size_t)row * HDIM + s2_h0)     = w0;
            *reinterpret_cast<float4*>(g_tab + (size_t)row * HDIM + s2_h0 + 4) = w1;
        }
        __syncthreads();
    }
}

// =====================  FAST KERNEL (row slab only, 2 CTA/SM)  =================
__global__ __launch_bounds__(512, 2)
void fast_tab_kernel(
    const float* __restrict__ pos,
    const int*   __restrict__ etype,
    const float* __restrict__ mw,
    const float* __restrict__ bw,
    const float* __restrict__ stds,
    const float* __restrict__ ob2,
    const float* __restrict__ vw1,
    const float* __restrict__ vb1,
    const float* __restrict__ vw2,
    const float* __restrict__ vb2,
    float* __restrict__ out,
    int nE)
{
    extern __shared__ float sm[];
    const int tid = threadIdx.x;
    int* iflags = reinterpret_cast<int*>(sm + F_FLAG);
    compute_flags(iflags, vb1, stds, mw, bw, nE, tid, 512);
    if (!(iflags[0] & iflags[1] & iflags[2])) return;

    for (int i = tid; i < 64 * 32; i += 512) {
        int kp = i >> 5, h = i & 31;
        sm[F_VW2 + kp * 64 + 2 * h]     = vw2[(2 * kp) * HDIM + h];
        sm[F_VW2 + kp * 64 + 2 * h + 1] = vw2[(2 * kp + 1) * HDIM + h];
    }
    if (tid < 3 * KDIM) sm[F_VW1 + tid] = vw1[tid];
    if (tid < HDIM) sm[F_B2 + tid] = ob2[tid] + vb2[tid];

    const float m0v = mw[0], b0v = bw[0];
    const float lo = fminf(b0v, m0v + b0v);
    const float span = fmaxf(b0v, m0v + b0v) - lo;
    const float invd = (span > 0.0f) ? (float)(TABN - 1) / span : 0.0f;

    const int gm  = tid & 63;
    const int gkc = tid >> 6;
    const int s2_hg = (tid >> 5) & 3;
    const int s2_kh = (tid >> 7) & 1;
    const int s2_mh = tid >> 8;
    const int s2_h0 = s2_hg * 8;
    const int s2_m  = s2_mh * 32 + (tid & 31);

    {
        int b0, ri0, j00, w0;
        decode_tile((int)blockIdx.x, 1, b0, ri0, j00, w0);
        if ((int)blockIdx.x < NTILES_FAST && tid < 64) {
            float4 m = load_meta(pos, etype, mw, bw, b0, ri0, j00 + tid);
            *reinterpret_cast<float4*>(sm + F_DLM4 + tid * 4) = m;
        }
    }
    __syncthreads();

    int cur = 0, zi = 0;
    for (int t = blockIdx.x; t < NTILES_FAST; t += gridDim.x, zi++) {
        int b, rowi, j0, wrM;
        decode_tile(t, 1, b, rowi, j0, wrM);

        if (zi < NZIF) {
            #pragma unroll
            for (int zz = 0; zz < 3; zz++) {
                int idx = ((zi * 3 + zz) * GRIDF + (int)blockIdx.x) * 512 + tid;
                if (idx < ZTOT_F4) {
                    int jq = idx % 192;
                    int r  = idx / 192;
                    int ip = r % 768;
                    int bhh = r / 768;
                    size_t addr = (((size_t)bhh << 10) + 256 + ip) * 1024 + 256 + 4 * jq;
                    *reinterpret_cast<float4*>(out + addr) = make_float4(0.f, 0.f, 0.f, 0.f);
                }
            }
        }

        const int tn = t + gridDim.x;
        float4 pf;
        const bool havePf = (tn < NTILES_FAST) && (tid < 64);
        if (havePf) {
            int bn, rin, j0n, wn;
            decode_tile(tn, 1, bn, rin, j0n, wn);
            pf = load_meta(pos, etype, mw, bw, bn, rin, j0n + tid);
        }

        // v1 phase
        {
            float4 dm = *reinterpret_cast<float4*>(sm + F_DLM4 + cur * 256 + gm * 4);
            #pragma unroll
            for (int i = 0; i < 8; i++) {
                int kp = gkc * 8 + i;
                float2 w0 = *reinterpret_cast<float2*>(sm + F_VW1 + 2 * kp);
                float2 w1 = *reinterpret_cast<float2*>(sm + F_VW1 + 128 + 2 * kp);
                float2 w2 = *reinterpret_cast<float2*>(sm + F_VW1 + 256 + 2 * kp);
                float sx = dm.x * w0.x + dm.y * w1.x + dm.z * w2.x;   // vb1 == 0
                float sy = dm.x * w0.y + dm.y * w1.y + dm.z * w2.y;
                float2 v1 = make_float2(fast_gelu(sx), fast_gelu(sy));
                *reinterpret_cast<float2*>(sm + F_VP1 + kp * PP + 2 * gm) = v1;
            }
        }
        if (havePf)
            *reinterpret_cast<float4*>(sm + F_DLM4 + (cur ^ 1) * 256 + tid * 4) = pf;
        __syncthreads();   // (A)

        float rowv[8], eft[8];
        {
            if (s2_kh == 0) {
                float x0 = sm[F_DLM4 + cur * 256 + s2_m * 4 + 3];
                float u = (x0 - lo) * invd;
                u = fminf(fmaxf(u, 0.0f), (float)(TABN - 1));
                int i0 = (int)u;
                if (i0 > TABN - 2) i0 = TABN - 2;
                float f = u - (float)i0;
                const float* r0 = g_tab + (size_t)i0 * HDIM + s2_h0;
                float4 a0 = *reinterpret_cast<const float4*>(r0);
                float4 a1 = *reinterpret_cast<const float4*>(r0 + 4);
                float4 c0 = *reinterpret_cast<const float4*>(r0 + HDIM);
                float4 c1 = *reinterpret_cast<const float4*>(r0 + HDIM + 4);
                eft[0] = fmaf(f, c0.x - a0.x, a0.x);
                eft[1] = fmaf(f, c0.y - a0.y, a0.y);
                eft[2] = fmaf(f, c0.z - a0.z, a0.z);
                eft[3] = fmaf(f, c0.w - a0.w, a0.w);
                eft[4] = fmaf(f, c1.x - a1.x, a1.x);
                eft[5] = fmaf(f, c1.y - a1.y, a1.y);
                eft[6] = fmaf(f, c1.z - a1.z, a1.z);
                eft[7] = fmaf(f, c1.w - a1.w, a1.w);
            }
            const float* vB = sm + F_VP1 + s2_kh * 32 * PP + 2 * s2_m;
            const float* wB = sm + F_VW2 + s2_kh * 2048 + 2 * s2_h0;
            ull A[8];
            #pragma unroll
            for (int j = 0; j < 8; j++) A[j] = 0ull;
            #pragma unroll 4
            for (int i = 0; i < 32; i++) {
                ull vp = *reinterpret_cast<const ull*>(vB + i * PP);
                ulonglong2 v01 = *reinterpret_cast<const ulonglong2*>(wB + i * 64);
                ulonglong2 v23 = *reinterpret_cast<const ulonglong2*>(wB + i * 64 + 4);
                ulonglong2 v45 = *reinterpret_cast<const ulonglong2*>(wB + i * 64 + 8);
                ulonglong2 v67 = *reinterpret_cast<const ulonglong2*>(wB + i * 64 + 12);
                A[0] = ffma2(vp, v01.x, A[0]); A[1] = ffma2(vp, v01.y, A[1]);
                A[2] = ffma2(vp, v23.x, A[2]); A[3] = ffma2(vp, v23.y, A[3]);
                A[4] = ffma2(vp, v45.x, A[4]); A[5] = ffma2(vp, v45.y, A[5]);
                A[6] = ffma2(vp, v67.x, A[6]); A[7] = ffma2(vp, v67.y, A[7]);
            }
            #pragma unroll
            for (int j = 0; j < 8; j++) rowv[j] = hadd2(A[j]);
        }
        if (s2_kh) {
            float* sc = sm + F_SCR + s2_m * SCP + s2_h0;
            *reinterpret_cast<float4*>(sc)     = make_float4(rowv[0], rowv[1], rowv[2], rowv[3]);
            *reinterpret_cast<float4*>(sc + 4) = make_float4(rowv[4], rowv[5], rowv[6], rowv[7]);
        }
        __syncthreads();   // (B)
        if (s2_kh == 0) {
            const float* sc = sm + F_SCR + s2_m * SCP + s2_h0;
            float4 r0 = *reinterpret_cast<const float4*>(sc);
            float4 r1 = *reinterpret_cast<const float4*>(sc + 4);
            rowv[0] += r0.x + eft[0]; rowv[1] += r0.y + eft[1];
            rowv[2] += r0.z + eft[2]; rowv[3] += r0.w + eft[3];
            rowv[4] += r1.x + eft[4]; rowv[5] += r1.y + eft[5];
            rowv[6] += r1.z + eft[6]; rowv[7] += r1.w + eft[7];
            const size_t bh = (size_t)b * HDIM;
            #pragma unroll
            for (int j = 0; j < 8; j++) {
                int h = s2_h0 + j;
                out[((bh + h) * NTOT + rowi) * NTOT + j0 + s2_m] =
                    rowv[j] + sm[F_B2 + h];
            }
        }
        cur ^= 1;
    }
}

// ============  MIRROR TRANSPOSE KERNEL (coalesced col-slab writes)  ============
// Reads the row slab written by fast_tab_kernel, writes out[b,h,j,i] =
// row[b,h,i,j] - (pos[j]-pos[i])·T[:,h] via a 32x32 smem transpose.
__global__ __launch_bounds__(256)
void mirror_transpose_kernel(
    const float* __restrict__ pos,
    const float* __restrict__ mw,
    const float* __restrict__ bw,
    const float* __restrict__ stds,
    const float* __restrict__ vb1,
    const float* __restrict__ vw1,
    const float* __restrict__ vw2,
    float* __restrict__ out,
    int nE)
{
    __shared__ float tile[32 * 33];
    __shared__ float pjv[32 * 3];
    __shared__ float piv[32 * 3];
    __shared__ float T3[3];
    __shared__ int ifl[3];
    const int tid = threadIdx.x;
    compute_flags(ifl, vb1, stds, mw, bw, nE, tid, 256);
    if (!(ifl[0] & ifl[1] & ifl[2])) return;

    int tt = (int)blockIdx.x % NTT_PER_BH;
    int bh = (int)blockIdx.x / NTT_PER_BH;     // b*32+h
    int h = bh & 31, b = bh >> 5;
    int i0, j0;
    if (tt < 192) {
        int it = tt % 24, jt = tt / 24;
        i0 = 256 + it * 32; j0 = jt * 32;
    } else {
        int u = tt - 192;
        int p = u >> 2, si = (u >> 1) & 1, sj = u & 1;
        const int brt[6] = {0, 0, 0, 1, 1, 2};
        const int bct[6] = {1, 2, 3, 2, 3, 3};
        i0 = brt[p] * 64 + si * 32;
        j0 = bct[p] * 64 + sj * 32;
    }

    // T3[d] = vw1[d,:]·vw2[:,h]
    if (tid < 3) {
        float s = 0.0f;
        for (int k = 0; k < KDIM; k++) s += vw1[tid * KDIM + k] * vw2[k * HDIM + h];
        T3[tid] = s;
    }
    // stage pos rows
    if (tid < 32) {
        const float* p3 = pos + ((size_t)b * NTOT + j0 + tid) * 3;
        pjv[tid * 3] = p3[0]; pjv[tid * 3 + 1] = p3[1]; pjv[tid * 3 + 2] = p3[2];
    } else if (tid < 64) {
        int l = tid - 32;
        const float* p3 = pos + ((size_t)b * NTOT + i0 + l) * 3;
        piv[l * 3] = p3[0]; piv[l * 3 + 1] = p3[1]; piv[l * 3 + 2] = p3[2];
    }

    const int wy = tid >> 5, lane = tid & 31;
    const size_t base = (size_t)bh * NTOT * NTOT;
    #pragma unroll
    for (int r = 0; r < 4; r++) {
        int il = wy + 8 * r;
        tile[il * 33 + lane] = out[base + (size_t)(i0 + il) * NTOT + j0 + lane];
    }
    __syncthreads();
    #pragma unroll
    for (int r = 0; r < 4; r++) {
        int jl = wy + 8 * r;
        float v = tile[lane * 33 + jl];          // value at (i=i0+lane, j=j0+jl)
        float d0 = pjv[jl * 3]     - piv[lane * 3];
        float d1 = pjv[jl * 3 + 1] - piv[lane * 3 + 1];
        float d2 = pjv[jl * 3 + 2] - piv[lane * 3 + 2];
        float corr = d0 * T3[0] + d1 * T3[1] + d2 * T3[2];
        out[base + (size_t)(j0 + jl) * NTOT + i0 + lane] = v - corr;
    }
}

// =====================  EXACT KERNEL (fallback)  ================================
__global__ __launch_bounds__(512, 1)
void fused_distbias_kernel(
    const float* __restrict__ pos,
    const int*   __restrict__ etype,
    const float* __restrict__ mw,
    const float* __restrict__ bw,
    const float* __restrict__ means,
    const float* __restrict__ stds,
    const float* __restrict__ ow1,
    const float* __restrict__ ob1,
    const float* __restrict__ ow2,
    const float* __restrict__ ob2,
    const float* __restrict__ vw1,
    const float* __restrict__ vb1,
    const float* __restrict__ vw2,
    const float* __restrict__ vb2,
    float* __restrict__ out,
    int nE)
{
    extern __shared__ float sm[];
    const int tid = threadIdx.x;
    int* iflags = reinterpret_cast<int*>(sm + OFF_FLAG);
    compute_flags(iflags, vb1, stds, mw, bw, nE, tid, 512);
    const int vbzero = iflags[0];
    const int fastmode = iflags[0] & iflags[1];
    if (fastmode & iflags[2]) return;
    const int ntiles = fastmode ? NTILES_FAST : NTILES_SLOW;

    for (int i = tid; i < 64 * 128; i += 512) {
        int kp = i >> 7, c = i & 127;
        sm[OFF_OW1 + kp * 256 + 2 * c]     = ow1[(2 * kp) * KDIM + c];
        sm[OFF_OW1 + kp * 256 + 2 * c + 1] = ow1[(2 * kp + 1) * KDIM + c];
    }
    for (int i = tid; i < 64 * 32; i += 512) {
        int kp = i >> 5, h = i & 31;
        sm[OFF_OW2 + kp * 64 + 2 * h]     = ow2[(2 * kp) * HDIM + h];
        sm[OFF_OW2 + kp * 64 + 2 * h + 1] = ow2[(2 * kp + 1) * HDIM + h];
        sm[OFF_VW2 + kp * 64 + 2 * h]     = vw2[(2 * kp) * HDIM + h];
        sm[OFF_VW2 + kp * 64 + 2 * h + 1] = vw2[(2 * kp + 1) * HDIM + h];
    }
    if (tid < 3 * KDIM) sm[OFF_VW1 + tid] = vw1[tid];
    if (tid < KDIM) {
        sm[OFF_VB1 + tid] = vb1[tid];
        sm[OFF_OB1 + tid] = ob1[tid];
        float s  = fabsf(stds[tid]) + 1e-5f;
        float is = 1.0f / s;
        sm[OFF_MEAN + tid] = means[tid];
        sm[OFF_ISTD + tid] = is;
        sm[OFF_COEF + tid] = is * (1.0f / sqrtf(2.0f * 3.14159f));
    }
    if (tid < HDIM) sm[OFF_B2 + tid] = ob2[tid] + vb2[tid];
    __syncthreads();
    if (tid < 96) {
        int d = tid >> 5, h = tid & 31;
        float s = 0.0f;
        for (int kp = 0; kp < 64; kp++) {
            float2 a = *reinterpret_cast<float2*>(sm + OFF_VW1 + d * 128 + 2 * kp);
            float2 w = *reinterpret_cast<float2*>(sm + OFF_VW2 + kp * 64 + 2 * h);
            s += a.x * w.x + a.y * w.y;
        }
        sm[OFF_TVV + d * 32 + h] = s;
    }

    const int gm  = tid & 63;
    const int gkc = tid >> 6;
    const int s1_wid = tid >> 5, s1_lane = tid & 31;
    const int s1_wm = s1_wid & 3, s1_wn = s1_wid >> 2;
    const int s1_mg = s1_lane >> 3, s1_ng = s1_lane & 7;
    const int s1_mbase = s1_wm * 16 + s1_mg * 4;
    const int s1_cbase = s1_wn * 32;
    const int s1_npA   = s1_wn * 16 + s1_ng;
    const int s2_hg = (tid >> 5) & 3;
    const int s2_kh = (tid >> 7) & 1;
    const int s2_mh = tid >> 8;
    const int s2_h0 = s2_hg * 8;
    const int s2_m  = s2_mh * 32 + (tid & 31);

    {
        int b0, ri0, j00, w0;
        decode_tile((int)blockIdx.x, fastmode, b0, ri0, j00, w0);
        if ((int)blockIdx.x < ntiles && tid < 64) {
            float4 m = load_meta(pos, etype, mw, bw, b0, ri0, j00 + tid);
            *reinterpret_cast<float4*>(sm + OFF_DLM4 + tid * 4) = m;
        }
    }
    __syncthreads();

    int cur = 0, zi = 0;
    for (int t = blockIdx.x; t < ntiles; t += gridDim.x, zi++) {
        int b, rowi, j0, wrM;
        decode_tile(t, fastmode, b, rowi, j0, wrM);

        if (zi < NZI) {
            #pragma unroll
            for (int zz = 0; zz < 3; zz++) {
                int idx = ((zi * 3 + zz) * GRIDX + (int)blockIdx.x) * 512 + tid;
                if (idx < ZTOT_F4) {
                    int jq = idx % 192;
                    int r  = idx / 192;
                    int ip = r % 768;
                    int bhh = r / 768;
                    size_t addr = (((size_t)bhh << 10) + 256 + ip) * 1024 + 256 + 4 * jq;
                    *reinterpret_cast<float4*>(out + addr) = make_float4(0.f, 0.f, 0.f, 0.f);
                }
            }
        }

        const int tn = t + gridDim.x;
        float4 pf;
        const bool havePf = (tn < ntiles) && (tid < 64);
        if (havePf) {
            int bn, rin, j0n, wn;
            decode_tile(tn, fastmode, bn, rin, j0n, wn);
            pf = load_meta(pos, etype, mw, bw, bn, rin, j0n + tid);
        }

        {
            float4 dm = *reinterpret_cast<float4*>(sm + OFF_DLM4 + cur * 256 + gm * 4);
            #pragma unroll
            for (int i = 0; i < 8; i++) {
                int kp = gkc * 8 + i;
                float2 mn = *reinterpret_cast<float2*>(sm + OFF_MEAN + 2 * kp);
                float2 is = *reinterpret_cast<float2*>(sm + OFF_ISTD + 2 * kp);
                float2 cf = *reinterpret_cast<float2*>(sm + OFF_COEF + 2 * kp);
                float2 w0 = *reinterpret_cast<float2*>(sm + OFF_VW1 + 2 * kp);
                float2 w1 = *reinterpret_cast<float2*>(sm + OFF_VW1 + 128 + 2 * kp);
                float2 w2 = *reinterpret_cast<float2*>(sm + OFF_VW1 + 256 + 2 * kp);
                float2 vb = *reinterpret_cast<float2*>(sm + OFF_VB1 + 2 * kp);
                float tx = (dm.w - mn.x) * is.x;
                float ty = (dm.w - mn.y) * is.y;
                float2 g = make_float2(__expf(-0.5f * tx * tx) * cf.x,
                                       __expf(-0.5f * ty * ty) * cf.y);
                float sx = dm.x * w0.x + dm.y * w1.x + dm.z * w2.x + vb.x;
                float sy = dm.x * w0.y + dm.y * w1.y + dm.z * w2.y + vb.y;
                float2 v1 = make_float2(fast_gelu(sx), fast_gelu(sy));
                *reinterpret_cast<float2*>(sm + OFF_GP  + kp * PP + 2 * gm) = g;
                *reinterpret_cast<float2*>(sm + OFF_VP1 + kp * PP + 2 * gm) = v1;
            }
        }
        if (havePf)
            *reinterpret_cast<float4*>(sm + OFF_DLM4 + (cur ^ 1) * 256 + tid * 4) = pf;
        __syncthreads();

        {
            ull acc[4][4];
            #pragma unroll
            for (int r = 0; r < 4; r++)
                #pragma unroll
                for (int j = 0; j < 4; j++) acc[r][j] = 0ull;
            const float* gpB = sm + OFF_GP + 2 * s1_mbase;
            const float* w1B = sm + OFF_OW1 + 2 * s1_cbase + 4 * s1_ng;
            #pragma unroll 4
            for (int kp = 0; kp < 64; kp++) {
                ulonglong2 g01 = *reinterpret_cast<const ulonglong2*>(gpB + kp * PP);
                ulonglong2 g23 = *reinterpret_cast<const ulonglong2*>(gpB + kp * PP + 4);
                ulonglong2 wA  = *reinterpret_cast<const ulonglong2*>(w1B + kp * 256);
                ulonglong2 wB  = *reinterpret_cast<const ulonglong2*>(w1B + kp * 256 + 32);
                acc[0][0] = ffma2(g01.x, wA.x, acc[0][0]);
                acc[0][1] = ffma2(g01.x, wA.y, acc[0][1]);
                acc[0][2] = ffma2(g01.x, wB.x, acc[0][2]);
                acc[0][3] = ffma2(g01.x, wB.y, acc[0][3]);
                acc[1][0] = ffma2(g01.y, wA.x, acc[1][0]);
                acc[1][1] = ffma2(g01.y, wA.y, acc[1][1]);
                acc[1][2] = ffma2(g01.y, wB.x, acc[1][2]);
                acc[1][3] = ffma2(g01.y, wB.y, acc[1][3]);
                acc[2][0] = ffma2(g23.x, wA.x, acc[2][0]);
                acc[2][1] = ffma2(g23.x, wA.y, acc[2][1]);
                acc[2][2] = ffma2(g23.x, wB.x, acc[2][2]);
                acc[2][3] = ffma2(g23.x, wB.y, acc[2][3]);
                acc[3][0] = ffma2(g23.y, wA.x, acc[3][0]);
                acc[3][1] = ffma2(g23.y, wA.y, acc[3][1]);
                acc[3][2] = ffma2(g23.y, wB.x, acc[3][2]);
                acc[3][3] = ffma2(g23.y, wB.y, acc[3][3]);
            }
            float2 obA = *reinterpret_cast<float2*>(sm + OFF_OB1 + s1_cbase + 2 * s1_ng);
            float2 obB = *reinterpret_cast<float2*>(sm + OFF_OB1 + s1_cbase + 2 * s1_ng + 16);
            #pragma unroll
            for (int r = 0; r < 4; r++) {
                int m = s1_mbase + r;
                float2 hA = make_float2(fast_gelu(hadd2(acc[r][0]) + obA.x),
                                        fast_gelu(hadd2(acc[r][1]) + obA.y));
                float2 hB = make_float2(fast_gelu(hadd2(acc[r][2]) + obB.x),
                                        fast_gelu(hadd2(acc[r][3]) + obB.y));
                *reinterpret_cast<float2*>(sm + OFF_H1P + s1_npA * PP + 2 * m) = hA;
                *reinterpret_cast<float2*>(sm + OFF_H1P + (s1_npA + 8) * PP + 2 * m) = hB;
            }
        }
        __syncthreads();

        float rowv[8];
        {
            const float* hB = sm + OFF_H1P + s2_kh * 32 * PP + 2 * s2_m;
            const float* vB = sm + OFF_VP1 + s2_kh * 32 * PP + 2 * s2_m;
            const float* oB = sm + OFF_OW2 + s2_kh * 2048 + 2 * s2_h0;
            const float* wB = sm + OFF_VW2 + s2_kh * 2048 + 2 * s2_h0;
            ull R[8];
            #pragma unroll
            for (int j = 0; j < 8; j++) R[j] = 0ull;
            #pragma unroll 4
            for (int i = 0; i < 32; i++) {
                ull hp = *reinterpret_cast<const ull*>(hB + i * PP);
                ull vp = *reinterpret_cast<const ull*>(vB + i * PP);
                ulonglong2 o01 = *reinterpret_cast<const ulonglong2*>(oB + i * 64);
                ulonglong2 o23 = *reinterpret_cast<const ulonglong2*>(oB + i * 64 + 4);
                ulonglong2 o45 = *reinterpret_cast<const ulonglong2*>(oB + i * 64 + 8);
                ulonglong2 o67 = *reinterpret_cast<const ulonglong2*>(oB + i * 64 + 12);
                R[0] = ffma2(hp, o01.x, R[0]); R[1] = ffma2(hp, o01.y, R[1]);
                R[2] = ffma2(hp, o23.x, R[2]); R[3] = ffma2(hp, o23.y, R[3]);
                R[4] = ffma2(hp, o45.x, R[4]); R[5] = ffma2(hp, o45.y, R[5]);
                R[6] = ffma2(hp, o67.x, R[6]); R[7] = ffma2(hp, o67.y, R[7]);
                ulonglong2 v01 = *reinterpret_cast<const ulonglong2*>(wB + i * 64);
                ulonglong2 v23 = *reinterpret_cast<const ulonglong2*>(wB + i * 64 + 4);
                ulonglong2 v45 = *reinterpret_cast<const ulonglong2*>(wB + i * 64 + 8);
                ulonglong2 v67 = *reinterpret_cast<const ulonglong2*>(wB + i * 64 + 12);
                R[0] = ffma2(vp, v01.x, R[0]); R[1] = ffma2(vp, v01.y, R[1]);
                R[2] = ffma2(vp, v23.x, R[2]); R[3] = ffma2(vp, v23.y, R[3]);
                R[4] = ffma2(vp, v45.x, R[4]); R[5] = ffma2(vp, v45.y, R[5]);
                R[6] = ffma2(vp, v67.x, R[6]); R[7] = ffma2(vp, v67.y, R[7]);
            }
            #pragma unroll
            for (int j = 0; j < 8; j++) rowv[j] = hadd2(R[j]);
        }
        float corr[8];
        if (wrM && vbzero && s2_kh == 0) {
            float4 dmv = *reinterpret_cast<float4*>(sm + OFF_DLM4 + cur * 256 + s2_m * 4);
            #pragma unroll
            for (int j = 0; j < 8; j++) {
                int h = s2_h0 + j;
                corr[j] = dmv.x * sm[OFF_TVV + h]
                        + dmv.y * sm[OFF_TVV + 32 + h]
                        + dmv.z * sm[OFF_TVV + 64 + h];
            }
        }
        if (s2_kh) {
            float* sc = sm + OFF_SCR + s2_m * SCP + s2_h0;
            *reinterpret_cast<float4*>(sc)     = make_float4(rowv[0], rowv[1], rowv[2], rowv[3]);
            *reinterpret_cast<float4*>(sc + 4) = make_float4(rowv[4], rowv[5], rowv[6], rowv[7]);
        }
        __syncthreads();
        if (s2_kh == 0) {
            const float* sc = sm + OFF_SCR + s2_m * SCP + s2_h0;
            float4 r0 = *reinterpret_cast<const float4*>(sc);
            float4 r1 = *reinterpret_cast<const float4*>(sc + 4);
            rowv[0] += r0.x; rowv[1] += r0.y; rowv[2] += r0.z; rowv[3] += r0.w;
            rowv[4] += r1.x; rowv[5] += r1.y; rowv[6] += r1.z; rowv[7] += r1.w;
            const size_t bh = (size_t)b * HDIM;
            #pragma unroll
            for (int j = 0; j < 8; j++) {
                int h = s2_h0 + j;
                float v = rowv[j] + sm[OFF_B2 + h];
                out[((bh + h) * NTOT + rowi) * NTOT + j0 + s2_m] = v;
                if (wrM && vbzero)
                    out[((bh + h) * NTOT + (j0 + s2_m)) * NTOT + rowi] = v - corr[j];
            }
        }

        if (wrM && !vbzero) {
            float dp[8];
            {
                float4 dmv = *reinterpret_cast<float4*>(sm + OFF_DLM4 + cur * 256 + s2_m * 4);
                const float* vB = sm + OFF_VP1 + s2_kh * 32 * PP + 2 * s2_m;
                const float* wB = sm + OFF_VW2 + s2_kh * 2048 + 2 * s2_h0;
                ull D[8];
                #pragma unroll
                for (int j = 0; j < 8; j++) D[j] = 0ull;
                for (int i = 0; i < 32; i++) {
                    int kp = s2_kh * 32 + i;
                    float2 w0 = *reinterpret_cast<float2*>(sm + OFF_VW1 + 2 * kp);
                    float2 w1 = *reinterpret_cast<float2*>(sm + OFF_VW1 + 128 + 2 * kp);
                    float2 w2 = *reinterpret_cast<float2*>(sm + OFF_VW1 + 256 + 2 * kp);
                    float2 vb = *reinterpret_cast<float2*>(sm + OFF_VB1 + 2 * kp);
                    float sx = dmv.x * w0.x + dmv.y * w1.x + dmv.z * w2.x + vb.x;
                    float sy = dmv.x * w0.y + dmv.y * w1.y + dmv.z * w2.y + vb.y;
                    float2 pv = u2f2(*reinterpret_cast<const ull*>(vB + i * PP));
                    ull dq = f2pack(fast_gelu(2.0f * vb.x - sx) - pv.x,
                                    fast_gelu(2.0f * vb.y - sy) - pv.y);
                    ulonglong2 v01 = *reinterpret_cast<const ulonglong2*>(wB + i * 64);
                    ulonglong2 v23 = *reinterpret_cast<const ulonglong2*>(wB + i * 64 + 4);
                    ulonglong2 v45 = *reinterpret_cast<const ulonglong2*>(wB + i * 64 + 8);
                    ulonglong2 v67 = *reinterpret_cast<const ulonglong2*>(wB + i * 64 + 12);
                    D[0] = ffma2(dq, v01.x, D[0]); D[1] = ffma2(dq, v01.y, D[1]);
                    D[2] = ffma2(dq, v23.x, D[2]); D[3] = ffma2(dq, v23.y, D[3]);
                    D[4] = ffma2(dq, v45.x, D[4]); D[5] = ffma2(dq, v45.y, D[5]);
                    D[6] = ffma2(dq, v67.x, D[6]); D[7] = ffma2(dq, v67.y, D[7]);
                }
                #pragma unroll
                for (int j = 0; j < 8; j++) dp[j] = hadd2(D[j]);
            }
            __syncthreads();
            if (s2_kh) {
                float* sc = sm + OFF_SCR + s2_m * SCP + s2_h0;
                *reinterpret_cast<float4*>(sc)     = make_float4(dp[0], dp[1], dp[2], dp[3]);
                *reinterpret_cast<float4*>(sc + 4) = make_float4(dp[4], dp[5], dp[6], dp[7]);
            }
            __syncthreads();
            if (s2_kh == 0) {
                const float* sc = sm + OFF_SCR + s2_m * SCP + s2_h0;
                float4 r0 = *reinterpret_cast<const float4*>(sc);
                float4 r1 = *reinterpret_cast<const float4*>(sc + 4);
                dp[0] += r0.x; dp[1] += r0.y; dp[2] += r0.z; dp[3] += r0.w;
                dp[4] += r1.x; dp[5] += r1.y; dp[6] += r1.z; dp[7] += r1.w;
                const size_t bh = (size_t)b * HDIM;
                #pragma unroll
                for (int j = 0; j < 8; j++) {
                    int h = s2_h0 + j;
                    float v = rowv[j] + dp[j] + sm[OFF_B2 + h];
                    out[((bh + h) * NTOT + (j0 + s2_m)) * NTOT + rowi] = v;
                }
            }
        }
        cur ^= 1;
    }
}

extern "C" void kernel_launch(void* const* d_in, const int* in_sizes, int n_in,
                              void* d_out, int out_size) {
    const float* pos    = (const float*)d_in[0];
    const int*   etype  = (const int*)d_in[1];
    const float* means  = (const float*)d_in[3];
    const float* stds   = (const float*)d_in[4];
    const float* mul_w  = (const float*)d_in[5];
    const float* bias_w = (const float*)d_in[6];
    const float* ow1    = (const float*)d_in[7];
    const float* ob1    = (const float*)d_in[8];
    const float* ow2    = (const float*)d_in[9];
    const float* ob2    = (const float*)d_in[10];
    const float* vw1    = (const float*)d_in[11];
    const float* vb1    = (const float*)d_in[12];
    const float* vw2    = (const float*)d_in[13];
    const float* vb2    = (const float*)d_in[14];
    float* out = (float*)d_out;
    int nE = in_sizes[5];

    cudaFuncSetAttribute(build_tab_kernel,
                         cudaFuncAttributeMaxDynamicSharedMemorySize, SMEM_BYTES);
    cudaFuncSetAttribute(fast_tab_kernel,
                         cudaFuncAttributeMaxDynamicSharedMemorySize, FSMEM_BYTES);
    cudaFuncSetAttribute(fused_distbias_kernel,
                         cudaFuncAttributeMaxDynamicSharedMemorySize, SMEM_BYTES);

    build_tab_kernel<<<GRIDX, 512, SMEM_BYTES>>>(
        mul_w, bias_w, means, stds, ow1, ob1, ow2, vb1, nE);

    fast_tab_kernel<<<GRIDF, 512, FSMEM_BYTES>>>(
        pos, etype, mul_w, bias_w, stds, ob2, vw1, vb1, vw2, vb2, out, nE);

    mirror_transpose_kernel<<<NTT_TOTAL, 256>>>(
        pos, mul_w, bias_w, stds, vb1, vw1, vw2, out, nE);

    fused_distbias_kernel<<<GRIDX, 512, SMEM_BYTES>>>(
        pos, etype, mul_w, bias_w, means, stds,
        ow1, ob1, ow2, ob2, vw1, vb1, vw2, vb2, out, nE);
}

// round 16
// speedup vs baseline: 3.7439x; 1.1875x over previous
#include <cuda_runtime.h>
#include <math.h>

typedef unsigned long long ull;

#define BDIM 2
#define NTOT 1024
#define PLEN 768
#define LLEN 256
#define KDIM 128
#define HDIM 32
#define TABN 8192

constexpr int PP = 132;
constexpr int NT_LP = BDIM * PLEN * 4;           // 6144
constexpr int NT_LL_SLOW = BDIM * LLEN * 4;      // 2048
constexpr int NTILES_SLOW = NT_LL_SLOW + NT_LP;  // 8192
constexpr int NT_LL_FAST = BDIM * 640;           // 1280
constexpr int NTILES_FAST = NT_LL_FAST + NT_LP;  // 7424
constexpr int NTAB_TILES = TABN / 64;            // 128

constexpr int GRIDX = 148;
constexpr int GRIDF = 296;
constexpr int ZTOT_F4 = BDIM * HDIM * PLEN * (PLEN / 4);   // 9437184
constexpr int NZI  = (ZTOT_F4 + 3 * GRIDX * 512 - 1) / (3 * GRIDX * 512);  // 42
constexpr int NZIF = (ZTOT_F4 + 3 * GRIDF * 512 - 1) / (3 * GRIDF * 512);  // 21

constexpr int NTT_PER_BH = 216;
constexpr int NTT_TOTAL  = NTT_PER_BH * BDIM * HDIM;   // 13824

// ---------- big-smem layout (exact + build kernels) ----------
constexpr int OFF_OW1  = 0;
constexpr int OFF_OW2  = 16384;
constexpr int OFF_VW2  = 20480;
constexpr int OFF_TVV  = 24576;
constexpr int OFF_VW1  = 24672;
constexpr int OFF_VB1  = 25056;
constexpr int OFF_OB1  = 25184;
constexpr int OFF_MEAN = 25312;
constexpr int OFF_ISTD = 25440;
constexpr int OFF_COEF = 25568;
constexpr int OFF_B2   = 25696;
constexpr int OFF_FLAG = 25728;
constexpr int OFF_DLM4 = 25732;
constexpr int OFF_GP   = 26244;
constexpr int OFF_VP1  = OFF_GP + 64 * PP;       // 34692
constexpr int OFF_H1P  = OFF_VP1 + 64 * PP;      // 43140
constexpr int SCP = 36;
constexpr int SCSTRIDE = 64 * SCP;               // 2304
constexpr int OFF_SCR  = OFF_H1P + 64 * PP;      // 51588
constexpr int SMEM_FLOATS = OFF_SCR + SCSTRIDE;  // 53892
constexpr int SMEM_BYTES  = SMEM_FLOATS * 4;     // 215568

// ---------- slim layout (fast kernel) ----------
constexpr int F_VW2  = 0;                        // 4096
constexpr int F_VW1  = 4096;                     // 384
constexpr int F_B2   = 4480;                     // 32
constexpr int F_DLM4 = 4512;                     // 512 (2 buffers); 4512*4%16==0
constexpr int F_VP1  = 5024;                     // 8448
constexpr int F_SCR  = F_VP1 + 64 * PP;          // 13472
constexpr int FSMEM_FLOATS = F_SCR + SCSTRIDE;   // 15776
constexpr int FSMEM_BYTES  = FSMEM_FLOATS * 4;   // 63104

__device__ __align__(16) float g_tab[TABN * HDIM];
__device__ __align__(16) float g_T3[96];
__device__ int g_flags;

__device__ __forceinline__ ull ffma2(ull a, ull b, ull c) {
    ull d; asm("fma.rn.f32x2 %0,%1,%2,%3;" : "=l"(d) : "l"(a), "l"(b), "l"(c)); return d;
}
__device__ __forceinline__ float2 u2f2(ull v) {
    float2 f; asm("mov.b64 {%0,%1},%2;" : "=f"(f.x), "=f"(f.y) : "l"(v)); return f;
}
__device__ __forceinline__ ull f2pack(float x, float y) {
    ull r; asm("mov.b64 %0,{%1,%2};" : "=l"(r) : "f"(x), "f"(y)); return r;
}
__device__ __forceinline__ float hadd2(ull v) { float2 f = u2f2(v); return f.x + f.y; }

__device__ __forceinline__ float fast_gelu(float x) {
    float y  = x * 0.70710678118654752f;
    float ax = fabsf(y);
    float t  = __fdividef(1.0f, fmaf(0.3275911f, ax, 1.0f));
    float p  = fmaf(t, 1.061405429f, -1.453152027f);
    p = fmaf(t, p, 1.421413741f);
    p = fmaf(t, p, -0.284496736f);
    p = fmaf(t, p, 0.254829592f);
    p *= t;
    float e = __expf(-ax * ax);
    float erfv = copysignf(fmaf(-p, e, 1.0f), y);
    return 0.5f * x * (1.0f + erfv);
}

__device__ __forceinline__ void decode_tile(int t, int fastmode,
                                            int& b, int& rowi, int& j0, int& wrM) {
    if (fastmode) {
        if (t < NT_LL_FAST) {
            b = t / 640; int r = t - b * 640;
            if (r < 256) { rowi = r; j0 = r & 192; wrM = 0; }
            else {
                int r2 = r - 256; int pr = r2 >> 6;
                int br = (pr < 3) ? 0 : ((pr < 5) ? 1 : 2);
                int bc = (pr == 0) ? 1 : ((pr == 1 || pr == 3) ? 2 : 3);
                rowi = br * 64 + (r2 & 63); j0 = bc * 64; wrM = 1;
            }
        } else {
            int u = t - NT_LL_FAST; b = u / 3072; int r = u - b * 3072;
            rowi = LLEN + (r >> 2); j0 = (r & 3) << 6; wrM = 1;
        }
    } else {
        if (t < NT_LL_SLOW) {
            b = t >> 10; int r = t & 1023;
            rowi = r >> 2; j0 = (r & 3) << 6; wrM = 0;
        } else {
            int u = t - NT_LL_SLOW; b = u / 3072; int r = u - b * 3072;
            rowi = LLEN + (r >> 2); j0 = (r & 3) << 6; wrM = 1;
        }
    }
}

// fastmode metadata: mw/bw constant, no etype gather
__device__ __forceinline__ float4 load_meta_fast(const float* pos,
                                                 float m0v, float b0v,
                                                 int b, int rowi, int j) {
    const float* pj = pos + ((size_t)b * NTOT + j) * 3;
    const float* pi = pos + ((size_t)b * NTOT + rowi) * 3;
    float d0 = pj[0] - pi[0];
    float d1 = pj[1] - pi[1];
    float d2 = pj[2] - pi[2];
    float d = 1.0f / (d0 * d0 + d1 * d1 + d2 * d2 + 1.0f);
    return make_float4(d0, d1, d2, m0v * d + b0v);
}

__device__ __forceinline__ float4 load_meta(const float* pos, const int* etype,
                                            const float* mw, const float* bw,
                                            int b, int rowi, int j) {
    const float* pj = pos + ((size_t)b * NTOT + j) * 3;
    const float* pi = pos + ((size_t)b * NTOT + rowi) * 3;
    float d0 = pj[0] - pi[0];
    float d1 = pj[1] - pi[1];
    float d2 = pj[2] - pi[2];
    float d = 1.0f / (d0 * d0 + d1 * d1 + d2 * d2 + 1.0f);
    int e = etype[((size_t)b * NTOT + rowi) * NTOT + j];
    return make_float4(d0, d1, d2, mw[e] * d + bw[e]);
}

__device__ __forceinline__ void compute_flags(int* ifl, const float* vb1,
                                              const float* stds, const float* mw,
                                              const float* bw, int nE, int tid, int nthr) {
    if (tid == 0) { ifl[0] = 1; ifl[1] = 1; ifl[2] = 1; }
    __syncthreads();
    if (tid < KDIM && vb1[tid] != 0.0f) atomicAnd(&ifl[0], 0);
    if (tid < KDIM) {
        float s = fabsf(stds[tid]) + 1e-5f;
        if (s < 0.004f) atomicAnd(&ifl[2], 0);
    }
    float m0v = mw[0], b0v = bw[0];
    for (int i = tid; i < nE; i += nthr)
        if (mw[i] != m0v || bw[i] != b0v) atomicAnd(&ifl[1], 0);
    __syncthreads();
}

// =====================  TABLE BUILD KERNEL  =====================
// Also publishes g_flags and g_T3 for the downstream kernels.
__global__ __launch_bounds__(512, 1)
void build_tab_kernel(const float* __restrict__ mw, const float* __restrict__ bw,
                      const float* __restrict__ means, const float* __restrict__ stds,
                      const float* __restrict__ ow1, const float* __restrict__ ob1,
                      const float* __restrict__ ow2, const float* __restrict__ vb1,
                      const float* __restrict__ vw1, const float* __restrict__ vw2,
                      int nE)
{
    extern __shared__ float sm[];
    const int tid = threadIdx.x;
    int* iflags = reinterpret_cast<int*>(sm + OFF_FLAG);
    compute_flags(iflags, vb1, stds, mw, bw, nE, tid, 512);
    const int fl = iflags[0] | (iflags[1] << 1) | (iflags[2] << 2);
    if (blockIdx.x == 0 && tid == 0) g_flags = fl;
    // T3[d][h] = vw1[d,:]·vw2[:,h] (needed by mirror kernel; also by exact path
    // via smem, but publish globally once)
    if (blockIdx.x == 0 && tid < 96) {
        int d = tid >> 5, h = tid & 31;
        float s = 0.0f;
        #pragma unroll 4
        for (int k = 0; k < KDIM; k++) s += vw1[d * KDIM + k] * vw2[k * HDIM + h];
        g_T3[d * 32 + h] = s;
    }
    if (fl != 7) return;

    for (int i = tid; i < 64 * 128; i += 512) {
        int kp = i >> 7, c = i & 127;
        sm[OFF_OW1 + kp * 256 + 2 * c]     = ow1[(2 * kp) * KDIM + c];
        sm[OFF_OW1 + kp * 256 + 2 * c + 1] = ow1[(2 * kp + 1) * KDIM + c];
    }
    for (int i = tid; i < 64 * 32; i += 512) {
        int kp = i >> 5, h = i & 31;
        sm[OFF_OW2 + kp * 64 + 2 * h]     = ow2[(2 * kp) * HDIM + h];
        sm[OFF_OW2 + kp * 64 + 2 * h + 1] = ow2[(2 * kp + 1) * HDIM + h];
    }
    if (tid < KDIM) {
        sm[OFF_OB1 + tid] = ob1[tid];
        float s  = fabsf(stds[tid]) + 1e-5f;
        float is = 1.0f / s;
        sm[OFF_MEAN + tid] = means[tid];
        sm[OFF_ISTD + tid] = is;
        sm[OFF_COEF + tid] = is * (1.0f / sqrtf(2.0f * 3.14159f));
    }
    __syncthreads();

    const float m0v = mw[0], b0v = bw[0];
    const float lo = fminf(b0v, m0v + b0v);
    const float span = fmaxf(b0v, m0v + b0v) - lo;
    const float step = span / (float)(TABN - 1);

    const int gm  = tid & 63;
    const int gkc = tid >> 6;
    const int s1_wid = tid >> 5, s1_lane = tid & 31;
    const int s1_wm = s1_wid & 3, s1_wn = s1_wid >> 2;
    const int s1_mg = s1_lane >> 3, s1_ng = s1_lane & 7;
    const int s1_mbase = s1_wm * 16 + s1_mg * 4;
    const int s1_cbase = s1_wn * 32;
    const int s1_npA   = s1_wn * 16 + s1_ng;
    const int s2_hg = (tid >> 5) & 3;
    const int s2_kh = (tid >> 7) & 1;
    const int s2_mh = tid >> 8;
    const int s2_h0 = s2_hg * 8;
    const int s2_m  = s2_mh * 32 + (tid & 31);

    for (int t = blockIdx.x; t < NTAB_TILES; t += gridDim.x) {
        {
            float x0 = lo + (float)(t * 64 + gm) * step;
            #pragma unroll
            for (int i = 0; i < 8; i++) {
                int kp = gkc * 8 + i;
                float2 mn = *reinterpret_cast<float2*>(sm + OFF_MEAN + 2 * kp);
                float2 is = *reinterpret_cast<float2*>(sm + OFF_ISTD + 2 * kp);
                float2 cf = *reinterpret_cast<float2*>(sm + OFF_COEF + 2 * kp);
                float tx = (x0 - mn.x) * is.x;
                float ty = (x0 - mn.y) * is.y;
                float2 g = make_float2(__expf(-0.5f * tx * tx) * cf.x,
                                       __expf(-0.5f * ty * ty) * cf.y);
                *reinterpret_cast<float2*>(sm + OFF_GP + kp * PP + 2 * gm) = g;
            }
        }
        __syncthreads();
        {
            ull acc[4][4];
            #pragma unroll
            for (int r = 0; r < 4; r++)
                #pragma unroll
                for (int j = 0; j < 4; j++) acc[r][j] = 0ull;
            const float* gpB = sm + OFF_GP + 2 * s1_mbase;
            const float* w1B = sm + OFF_OW1 + 2 * s1_cbase + 4 * s1_ng;
            #pragma unroll 4
            for (int kp = 0; kp < 64; kp++) {
                ulonglong2 g01 = *reinterpret_cast<const ulonglong2*>(gpB + kp * PP);
                ulonglong2 g23 = *reinterpret_cast<const ulonglong2*>(gpB + kp * PP + 4);
                ulonglong2 wA  = *reinterpret_cast<const ulonglong2*>(w1B + kp * 256);
                ulonglong2 wB  = *reinterpret_cast<const ulonglong2*>(w1B + kp * 256 + 32);
                acc[0][0] = ffma2(g01.x, wA.x, acc[0][0]);
                acc[0][1] = ffma2(g01.x, wA.y, acc[0][1]);
                acc[0][2] = ffma2(g01.x, wB.x, acc[0][2]);
                acc[0][3] = ffma2(g01.x, wB.y, acc[0][3]);
                acc[1][0] = ffma2(g01.y, wA.x, acc[1][0]);
                acc[1][1] = ffma2(g01.y, wA.y, acc[1][1]);
                acc[1][2] = ffma2(g01.y, wB.x, acc[1][2]);
                acc[1][3] = ffma2(g01.y, wB.y, acc[1][3]);
                acc[2][0] = ffma2(g23.x, wA.x, acc[2][0]);
                acc[2][1] = ffma2(g23.x, wA.y, acc[2][1]);
                acc[2][2] = ffma2(g23.x, wB.x, acc[2][2]);
                acc[2][3] = ffma2(g23.x, wB.y, acc[2][3]);
                acc[3][0] = ffma2(g23.y, wA.x, acc[3][0]);
                acc[3][1] = ffma2(g23.y, wA.y, acc[3][1]);
                acc[3][2] = ffma2(g23.y, wB.x, acc[3][2]);
                acc[3][3] = ffma2(g23.y, wB.y, acc[3][3]);
            }
            float2 obA = *reinterpret_cast<float2*>(sm + OFF_OB1 + s1_cbase + 2 * s1_ng);
            float2 obB = *reinterpret_cast<float2*>(sm + OFF_OB1 + s1_cbase + 2 * s1_ng + 16);
            #pragma unroll
            for (int r = 0; r < 4; r++) {
                int m = s1_mbase + r;
                float2 hA = make_float2(fast_gelu(hadd2(acc[r][0]) + obA.x),
                                        fast_gelu(hadd2(acc[r][1]) + obA.y));
                float2 hB = make_float2(fast_gelu(hadd2(acc[r][2]) + obB.x),
                                        fast_gelu(hadd2(acc[r][3]) + obB.y));
                *reinterpret_cast<float2*>(sm + OFF_H1P + s1_npA * PP + 2 * m) = hA;
                *reinterpret_cast<float2*>(sm + OFF_H1P + (s1_npA + 8) * PP + 2 * m) = hB;
            }
        }
        __syncthreads();
        float rowv[8];
        {
            const float* hB = sm + OFF_H1P + s2_kh * 32 * PP + 2 * s2_m;
            const float* oB = sm + OFF_OW2 + s2_kh * 2048 + 2 * s2_h0;
            ull R[8];
            #pragma unroll
            for (int j = 0; j < 8; j++) R[j] = 0ull;
            #pragma unroll 4
            for (int i = 0; i < 32; i++) {
                ull hp = *reinterpret_cast<const ull*>(hB + i * PP);
                ulonglong2 o01 = *reinterpret_cast<const ulonglong2*>(oB + i * 64);
                ulonglong2 o23 = *reinterpret_cast<const ulonglong2*>(oB + i * 64 + 4);
                ulonglong2 o45 = *reinterpret_cast<const ulonglong2*>(oB + i * 64 + 8);
                ulonglong2 o67 = *reinterpret_cast<const ulonglong2*>(oB + i * 64 + 12);
                R[0] = ffma2(hp, o01.x, R[0]); R[1] = ffma2(hp, o01.y, R[1]);
                R[2] = ffma2(hp, o23.x, R[2]); R[3] = ffma2(hp, o23.y, R[3]);
                R[4] = ffma2(hp, o45.x, R[4]); R[5] = ffma2(hp, o45.y, R[5]);
                R[6] = ffma2(hp, o67.x, R[6]); R[7] = ffma2(hp, o67.y, R[7]);
            }
            #pragma unroll
            for (int j = 0; j < 8; j++) rowv[j] = hadd2(R[j]);
        }
        if (s2_kh) {
            float* sc = sm + OFF_SCR + s2_m * SCP + s2_h0;
            *reinterpret_cast<float4*>(sc)     = make_float4(rowv[0], rowv[1], rowv[2], rowv[3]);
            *reinterpret_cast<float4*>(sc + 4) = make_float4(rowv[4], rowv[5], rowv[6], rowv[7]);
        }
        __syncthreads();
        if (s2_kh == 0) {
            const float* sc = sm + OFF_SCR + s2_m * SCP + s2_h0;
            float4 r0 = *reinterpret_cast<const float4*>(sc);
            float4 r1 = *reinterpret_cast<const float4*>(sc + 4);
            int row = t * 64 + s2_m;
            float4 w0 = make_float4(rowv[0] + r0.x, rowv[1] + r0.y,
                                    rowv[2] + r0.z, rowv[3] + r0.w);
            float4 w1 = make_float4(rowv[4] + r1.x, rowv[5] + r1.y,
                                    rowv[6] + r1.z, rowv[7] + r1.w);
            *reinterpret_cast<float4*>(g_tab + (size_t)row * HDIM + s2_h0)     = w0;
            *reinterpret_cast<float4*>(g_tab + (size_t)row * HDIM + s2_h0 + 4) = w1;
        }
        __syncthreads();
    }
}

// =====================  FAST KERNEL (row slab only, 2 CTA/SM)  =================
__global__ __launch_bounds__(512, 2)
void fast_tab_kernel(
    const float* __restrict__ pos,
    const float* __restrict__ mw,
    const float* __restrict__ bw,
    const float* __restrict__ ob2,
    const float* __restrict__ vw1,
    const float* __restrict__ vw2,
    const float* __restrict__ vb2,
    float* __restrict__ out)
{
    extern __shared__ float sm[];
    const int tid = threadIdx.x;
    if (g_flags != 7) return;   // exact kernel handles it

    for (int i = tid; i < 64 * 32; i += 512) {
        int kp = i >> 5, h = i & 31;
        sm[F_VW2 + kp * 64 + 2 * h]     = vw2[(2 * kp) * HDIM + h];
        sm[F_VW2 + kp * 64 + 2 * h + 1] = vw2[(2 * kp + 1) * HDIM + h];
    }
    if (tid < 3 * KDIM) sm[F_VW1 + tid] = vw1[tid];
    if (tid < HDIM) sm[F_B2 + tid] = ob2[tid] + vb2[tid];

    const float m0v = mw[0], b0v = bw[0];
    const float lo = fminf(b0v, m0v + b0v);
    const float span = fmaxf(b0v, m0v + b0v) - lo;
    const float invd = (span > 0.0f) ? (float)(TABN - 1) / span : 0.0f;

    const int gm  = tid & 63;
    const int gkc = tid >> 6;
    const int s2_hg = (tid >> 5) & 3;
    const int s2_kh = (tid >> 7) & 1;
    const int s2_mh = tid >> 8;
    const int s2_h0 = s2_hg * 8;
    const int s2_m  = s2_mh * 32 + (tid & 31);

    {
        int b0, ri0, j00, w0;
        decode_tile((int)blockIdx.x, 1, b0, ri0, j00, w0);
        if ((int)blockIdx.x < NTILES_FAST && tid < 64) {
            float4 m = load_meta_fast(pos, m0v, b0v, b0, ri0, j00 + tid);
            *reinterpret_cast<float4*>(sm + F_DLM4 + tid * 4) = m;
        }
    }
    __syncthreads();

    int cur = 0, zi = 0;
    for (int t = blockIdx.x; t < NTILES_FAST; t += gridDim.x, zi++) {
        int b, rowi, j0, wrM;
        decode_tile(t, 1, b, rowi, j0, wrM);

        if (zi < NZIF) {
            #pragma unroll
            for (int zz = 0; zz < 3; zz++) {
                int idx = ((zi * 3 + zz) * GRIDF + (int)blockIdx.x) * 512 + tid;
                if (idx < ZTOT_F4) {
                    int jq = idx % 192;
                    int r  = idx / 192;
                    int ip = r % 768;
                    int bhh = r / 768;
                    size_t addr = (((size_t)bhh << 10) + 256 + ip) * 1024 + 256 + 4 * jq;
                    *reinterpret_cast<float4*>(out + addr) = make_float4(0.f, 0.f, 0.f, 0.f);
                }
            }
        }

        const int tn = t + gridDim.x;
        float4 pf;
        const bool havePf = (tn < NTILES_FAST) && (tid < 64);
        if (havePf) {
            int bn, rin, j0n, wn;
            decode_tile(tn, 1, bn, rin, j0n, wn);
            pf = load_meta_fast(pos, m0v, b0v, bn, rin, j0n + tid);
        }

        // v1 phase
        {
            float4 dm = *reinterpret_cast<float4*>(sm + F_DLM4 + cur * 256 + gm * 4);
            #pragma unroll
            for (int i = 0; i < 8; i++) {
                int kp = gkc * 8 + i;
                float2 w0 = *reinterpret_cast<float2*>(sm + F_VW1 + 2 * kp);
                float2 w1 = *reinterpret_cast<float2*>(sm + F_VW1 + 128 + 2 * kp);
                float2 w2 = *reinterpret_cast<float2*>(sm + F_VW1 + 256 + 2 * kp);
                float sx = dm.x * w0.x + dm.y * w1.x + dm.z * w2.x;   // vb1 == 0
                float sy = dm.x * w0.y + dm.y * w1.y + dm.z * w2.y;
                float2 v1 = make_float2(fast_gelu(sx), fast_gelu(sy));
                *reinterpret_cast<float2*>(sm + F_VP1 + kp * PP + 2 * gm) = v1;
            }
        }
        if (havePf)
            *reinterpret_cast<float4*>(sm + F_DLM4 + (cur ^ 1) * 256 + tid * 4) = pf;

        // table lerp hoisted before the barrier: the scattered g_tab L2 loads
        // drain while this warp waits at (A)
        float eft[8];
        if (s2_kh == 0) {
            float x0 = sm[F_DLM4 + cur * 256 + s2_m * 4 + 3];
            float u = (x0 - lo) * invd;
            u = fminf(fmaxf(u, 0.0f), (float)(TABN - 1));
            int i0 = (int)u;
            if (i0 > TABN - 2) i0 = TABN - 2;
            float f = u - (float)i0;
            const float* r0 = g_tab + (size_t)i0 * HDIM + s2_h0;
            float4 a0 = *reinterpret_cast<const float4*>(r0);
            float4 a1 = *reinterpret_cast<const float4*>(r0 + 4);
            float4 c0 = *reinterpret_cast<const float4*>(r0 + HDIM);
            float4 c1 = *reinterpret_cast<const float4*>(r0 + HDIM + 4);
            eft[0] = fmaf(f, c0.x - a0.x, a0.x);
            eft[1] = fmaf(f, c0.y - a0.y, a0.y);
            eft[2] = fmaf(f, c0.z - a0.z, a0.z);
            eft[3] = fmaf(f, c0.w - a0.w, a0.w);
            eft[4] = fmaf(f, c1.x - a1.x, a1.x);
            eft[5] = fmaf(f, c1.y - a1.y, a1.y);
            eft[6] = fmaf(f, c1.z - a1.z, a1.z);
            eft[7] = fmaf(f, c1.w - a1.w, a1.w);
        }
        __syncthreads();   // (A)

        float rowv[8];
        {
            const float* vB = sm + F_VP1 + s2_kh * 32 * PP + 2 * s2_m;
            const float* wB = sm + F_VW2 + s2_kh * 2048 + 2 * s2_h0;
            ull A[8];
            #pragma unroll
            for (int j = 0; j < 8; j++) A[j] = 0ull;
            #pragma unroll 4
            for (int i = 0; i < 32; i++) {
                ull vp = *reinterpret_cast<const ull*>(vB + i * PP);
                ulonglong2 v01 = *reinterpret_cast<const ulonglong2*>(wB + i * 64);
                ulonglong2 v23 = *reinterpret_cast<const ulonglong2*>(wB + i * 64 + 4);
                ulonglong2 v45 = *reinterpret_cast<const ulonglong2*>(wB + i * 64 + 8);
                ulonglong2 v67 = *reinterpret_cast<const ulonglong2*>(wB + i * 64 + 12);
                A[0] = ffma2(vp, v01.x, A[0]); A[1] = ffma2(vp, v01.y, A[1]);
                A[2] = ffma2(vp, v23.x, A[2]); A[3] = ffma2(vp, v23.y, A[3]);
                A[4] = ffma2(vp, v45.x, A[4]); A[5] = ffma2(vp, v45.y, A[5]);
                A[6] = ffma2(vp, v67.x, A[6]); A[7] = ffma2(vp, v67.y, A[7]);
            }
            #pragma unroll
            for (int j = 0; j < 8; j++) rowv[j] = hadd2(A[j]);
        }
        if (s2_kh) {
            float* sc = sm + F_SCR + s2_m * SCP + s2_h0;
            *reinterpret_cast<float4*>(sc)     = make_float4(rowv[0], rowv[1], rowv[2], rowv[3]);
            *reinterpret_cast<float4*>(sc + 4) = make_float4(rowv[4], rowv[5], rowv[6], rowv[7]);
        }
        __syncthreads();   // (B)
        if (s2_kh == 0) {
            const float* sc = sm + F_SCR + s2_m * SCP + s2_h0;
            float4 r0 = *reinterpret_cast<const float4*>(sc);
            float4 r1 = *reinterpret_cast<const float4*>(sc + 4);
            rowv[0] += r0.x + eft[0]; rowv[1] += r0.y + eft[1];
            rowv[2] += r0.z + eft[2]; rowv[3] += r0.w + eft[3];
            rowv[4] += r1.x + eft[4]; rowv[5] += r1.y + eft[5];
            rowv[6] += r1.z + eft[6]; rowv[7] += r1.w + eft[7];
            const size_t bh = (size_t)b * HDIM;
            #pragma unroll
            for (int j = 0; j < 8; j++) {
                int h = s2_h0 + j;
                out[((bh + h) * NTOT + rowi) * NTOT + j0 + s2_m] =
                    rowv[j] + sm[F_B2 + h];
            }
        }
        cur ^= 1;
    }
}

// ============  MIRROR TRANSPOSE KERNEL (coalesced col-slab writes)  ============
__global__ __launch_bounds__(256)
void mirror_transpose_kernel(
    const float* __restrict__ pos,
    float* __restrict__ out)
{
    __shared__ float tile[32 * 33];
    __shared__ float pjv[32 * 3];
    __shared__ float piv[32 * 3];
    const int tid = threadIdx.x;
    if (g_flags != 7) return;

    int tt = (int)blockIdx.x % NTT_PER_BH;
    int bh = (int)blockIdx.x / NTT_PER_BH;     // b*32+h
    int h = bh & 31, b = bh >> 5;
    int i0, j0;
    if (tt < 192) {
        int it = tt % 24, jt = tt / 24;
        i0 = 256 + it * 32; j0 = jt * 32;
    } else {
        int u = tt - 192;
        int p = u >> 2, si = (u >> 1) & 1, sj = u & 1;
        const int brt[6] = {0, 0, 0, 1, 1, 2};
        const int bct[6] = {1, 2, 3, 2, 3, 3};
        i0 = brt[p] * 64 + si * 32;
        j0 = bct[p] * 64 + sj * 32;
    }

    const float t3x = g_T3[h], t3y = g_T3[32 + h], t3z = g_T3[64 + h];

    if (tid < 32) {
        const float* p3 = pos + ((size_t)b * NTOT + j0 + tid) * 3;
        pjv[tid * 3] = p3[0]; pjv[tid * 3 + 1] = p3[1]; pjv[tid * 3 + 2] = p3[2];
    } else if (tid < 64) {
        int l = tid - 32;
        const float* p3 = pos + ((size_t)b * NTOT + i0 + l) * 3;
        piv[l * 3] = p3[0]; piv[l * 3 + 1] = p3[1]; piv[l * 3 + 2] = p3[2];
    }

    const int wy = tid >> 5, lane = tid & 31;
    const size_t base = (size_t)bh * NTOT * NTOT;
    #pragma unroll
    for (int r = 0; r < 4; r++) {
        int il = wy + 8 * r;
        tile[il * 33 + lane] = out[base + (size_t)(i0 + il) * NTOT + j0 + lane];
    }
    __syncthreads();
    #pragma unroll
    for (int r = 0; r < 4; r++) {
        int jl = wy + 8 * r;
        float v = tile[lane * 33 + jl];
        float d0 = pjv[jl * 3]     - piv[lane * 3];
        float d1 = pjv[jl * 3 + 1] - piv[lane * 3 + 1];
        float d2 = pjv[jl * 3 + 2] - piv[lane * 3 + 2];
        float corr = d0 * t3x + d1 * t3y + d2 * t3z;
        out[base + (size_t)(j0 + jl) * NTOT + i0 + lane] = v - corr;
    }
}

// =====================  EXACT KERNEL (fallback)  ================================
__global__ __launch_bounds__(512, 1)
void fused_distbias_kernel(
    const float* __restrict__ pos,
    const int*   __restrict__ etype,
    const float* __restrict__ mw,
    const float* __restrict__ bw,
    const float* __restrict__ means,
    const float* __restrict__ stds,
    const float* __restrict__ ow1,
    const float* __restrict__ ob1,
    const float* __restrict__ ow2,
    const float* __restrict__ ob2,
    const float* __restrict__ vw1,
    const float* __restrict__ vb1,
    const float* __restrict__ vw2,
    const float* __restrict__ vb2,
    float* __restrict__ out)
{
    extern __shared__ float sm[];
    const int tid = threadIdx.x;
    const int fl = g_flags;
    if (fl == 7) return;   // fast path handled it
    const int vbzero = fl & 1;
    const int fastmode = (fl & 3) == 3;
    const int ntiles = fastmode ? NTILES_FAST : NTILES_SLOW;

    for (int i = tid; i < 64 * 128; i += 512) {
        int kp = i >> 7, c = i & 127;
        sm[OFF_OW1 + kp * 256 + 2 * c]     = ow1[(2 * kp) * KDIM + c];
        sm[OFF_OW1 + kp * 256 + 2 * c + 1] = ow1[(2 * kp + 1) * KDIM + c];
    }
    for (int i = tid; i < 64 * 32; i += 512) {
        int kp = i >> 5, h = i & 31;
        sm[OFF_OW2 + kp * 64 + 2 * h]     = ow2[(2 * kp) * HDIM + h];
        sm[OFF_OW2 + kp * 64 + 2 * h + 1] = ow2[(2 * kp + 1) * HDIM + h];
        sm[OFF_VW2 + kp * 64 + 2 * h]     = vw2[(2 * kp) * HDIM + h];
        sm[OFF_VW2 + kp * 64 + 2 * h + 1] = vw2[(2 * kp + 1) * HDIM + h];
    }
    if (tid < 3 * KDIM) sm[OFF_VW1 + tid] = vw1[tid];
    if (tid < KDIM) {
        sm[OFF_VB1 + tid] = vb1[tid];
        sm[OFF_OB1 + tid] = ob1[tid];
        float s  = fabsf(stds[tid]) + 1e-5f;
        float is = 1.0f / s;
        sm[OFF_MEAN + tid] = means[tid];
        sm[OFF_ISTD + tid] = is;
        sm[OFF_COEF + tid] = is * (1.0f / sqrtf(2.0f * 3.14159f));
    }
    if (tid < HDIM) sm[OFF_B2 + tid] = ob2[tid] + vb2[tid];
    if (tid < 96) sm[OFF_TVV + tid] = g_T3[tid];
    __syncthreads();

    const int gm  = tid & 63;
    const int gkc = tid >> 6;
    const int s1_wid = tid >> 5, s1_lane = tid & 31;
    const int s1_wm = s1_wid & 3, s1_wn = s1_wid >> 2;
    const int s1_mg = s1_lane >> 3, s1_ng = s1_lane & 7;
    const int s1_mbase = s1_wm * 16 + s1_mg * 4;
    const int s1_cbase = s1_wn * 32;
    const int s1_npA   = s1_wn * 16 + s1_ng;
    const int s2_hg = (tid >> 5) & 3;
    const int s2_kh = (tid >> 7) & 1;
    const int s2_mh = tid >> 8;
    const int s2_h0 = s2_hg * 8;
    const int s2_m  = s2_mh * 32 + (tid & 31);

    {
        int b0, ri0, j00, w0;
        decode_tile((int)blockIdx.x, fastmode, b0, ri0, j00, w0);
        if ((int)blockIdx.x < ntiles && tid < 64) {
            float4 m = load_meta(pos, etype, mw, bw, b0, ri0, j00 + tid);
            *reinterpret_cast<float4*>(sm + OFF_DLM4 + tid * 4) = m;
        }
    }
    __syncthreads();

    int cur = 0, zi = 0;
    for (int t = blockIdx.x; t < ntiles; t += gridDim.x, zi++) {
        int b, rowi, j0, wrM;
        decode_tile(t, fastmode, b, rowi, j0, wrM);

        if (zi < NZI) {
            #pragma unroll
            for (int zz = 0; zz < 3; zz++) {
                int idx = ((zi * 3 + zz) * GRIDX + (int)blockIdx.x) * 512 + tid;
                if (idx < ZTOT_F4) {
                    int jq = idx % 192;
                    int r  = idx / 192;
                    int ip = r % 768;
                    int bhh = r / 768;
                    size_t addr = (((size_t)bhh << 10) + 256 + ip) * 1024 + 256 + 4 * jq;
                    *reinterpret_cast<float4*>(out + addr) = make_float4(0.f, 0.f, 0.f, 0.f);
                }
            }
        }

        const int tn = t + gridDim.x;
        float4 pf;
        const bool havePf = (tn < ntiles) && (tid < 64);
        if (havePf) {
            int bn, rin, j0n, wn;
            decode_tile(tn, fastmode, bn, rin, j0n, wn);
            pf = load_meta(pos, etype, mw, bw, bn, rin, j0n + tid);
        }

        {
            float4 dm = *reinterpret_cast<float4*>(sm + OFF_DLM4 + cur * 256 + gm * 4);
            #pragma unroll
            for (int i = 0; i < 8; i++) {
                int kp = gkc * 8 + i;
                float2 mn = *reinterpret_cast<float2*>(sm + OFF_MEAN + 2 * kp);
                float2 is = *reinterpret_cast<float2*>(sm + OFF_ISTD + 2 * kp);
                float2 cf = *reinterpret_cast<float2*>(sm + OFF_COEF + 2 * kp);
                float2 w0 = *reinterpret_cast<float2*>(sm + OFF_VW1 + 2 * kp);
                float2 w1 = *reinterpret_cast<float2*>(sm + OFF_VW1 + 128 + 2 * kp);
                float2 w2 = *reinterpret_cast<float2*>(sm + OFF_VW1 + 256 + 2 * kp);
                float2 vb = *reinterpret_cast<float2*>(sm + OFF_VB1 + 2 * kp);
                float tx = (dm.w - mn.x) * is.x;
                float ty = (dm.w - mn.y) * is.y;
                float2 g = make_float2(__expf(-0.5f * tx * tx) * cf.x,
                                       __expf(-0.5f * ty * ty) * cf.y);
                float sx = dm.x * w0.x + dm.y * w1.x + dm.z * w2.x + vb.x;
                float sy = dm.x * w0.y + dm.y * w1.y + dm.z * w2.y + vb.y;
                float2 v1 = make_float2(fast_gelu(sx), fast_gelu(sy));
                *reinterpret_cast<float2*>(sm + OFF_GP  + kp * PP + 2 * gm) = g;
                *reinterpret_cast<float2*>(sm + OFF_VP1 + kp * PP + 2 * gm) = v1;
            }
        }
        if (havePf)
            *reinterpret_cast<float4*>(sm + OFF_DLM4 + (cur ^ 1) * 256 + tid * 4) = pf;
        __syncthreads();

        {
            ull acc[4][4];
            #pragma unroll
            for (int r = 0; r < 4; r++)
                #pragma unroll
                for (int j = 0; j < 4; j++) acc[r][j] = 0ull;
            const float* gpB = sm + OFF_GP + 2 * s1_mbase;
            const float* w1B = sm + OFF_OW1 + 2 * s1_cbase + 4 * s1_ng;
            #pragma unroll 4
            for (int kp = 0; kp < 64; kp++) {
                ulonglong2 g01 = *reinterpret_cast<const ulonglong2*>(gpB + kp * PP);
                ulonglong2 g23 = *reinterpret_cast<const ulonglong2*>(gpB + kp * PP + 4);
                ulonglong2 wA  = *reinterpret_cast<const ulonglong2*>(w1B + kp * 256);
                ulonglong2 wB  = *reinterpret_cast<const ulonglong2*>(w1B + kp * 256 + 32);
                acc[0][0] = ffma2(g01.x, wA.x, acc[0][0]);
                acc[0][1] = ffma2(g01.x, wA.y, acc[0][1]);
                acc[0][2] = ffma2(g01.x, wB.x, acc[0][2]);
                acc[0][3] = ffma2(g01.x, wB.y, acc[0][3]);
                acc[1][0] = ffma2(g01.y, wA.x, acc[1][0]);
                acc[1][1] = ffma2(g01.y, wA.y, acc[1][1]);
                acc[1][2] = ffma2(g01.y, wB.x, acc[1][2]);
                acc[1][3] = ffma2(g01.y, wB.y, acc[1][3]);
                acc[2][0] = ffma2(g23.x, wA.x, acc[2][0]);
                acc[2][1] = ffma2(g23.x, wA.y, acc[2][1]);
                acc[2][2] = ffma2(g23.x, wB.x, acc[2][2]);
                acc[2][3] = ffma2(g23.x, wB.y, acc[2][3]);
                acc[3][0] = ffma2(g23.y, wA.x, acc[3][0]);
                acc[3][1] = ffma2(g23.y, wA.y, acc[3][1]);
                acc[3][2] = ffma2(g23.y, wB.x, acc[3][2]);
                acc[3][3] = ffma2(g23.y, wB.y, acc[3][3]);
            }
            float2 obA = *reinterpret_cast<float2*>(sm + OFF_OB1 + s1_cbase + 2 * s1_ng);
            float2 obB = *reinterpret_cast<float2*>(sm + OFF_OB1 + s1_cbase + 2 * s1_ng + 16);
            #pragma unroll
            for (int r = 0; r < 4; r++) {
                int m = s1_mbase + r;
                float2 hA = make_float2(fast_gelu(hadd2(acc[r][0]) + obA.x),
                                        fast_gelu(hadd2(acc[r][1]) + obA.y));
                float2 hB = make_float2(fast_gelu(hadd2(acc[r][2]) + obB.x),
                                        fast_gelu(hadd2(acc[r][3]) + obB.y));
                *reinterpret_cast<float2*>(sm + OFF_H1P + s1_npA * PP + 2 * m) = hA;
                *reinterpret_cast<float2*>(sm + OFF_H1P + (s1_npA + 8) * PP + 2 * m) = hB;
            }
        }
        __syncthreads();

        float rowv[8];
        {
            const float* hB = sm + OFF_H1P + s2_kh * 32 * PP + 2 * s2_m;
            const float* vB = sm + OFF_VP1 + s2_kh * 32 * PP + 2 * s2_m;
            const float* oB = sm + OFF_OW2 + s2_kh * 2048 + 2 * s2_h0;
            const float* wB = sm + OFF_VW2 + s2_kh * 2048 + 2 * s2_h0;
            ull R[8];
            #pragma unroll
            for (int j = 0; j < 8; j++) R[j] = 0ull;
            #pragma unroll 4
            for (int i = 0; i < 32; i++) {
                ull hp = *reinterpret_cast<const ull*>(hB + i * PP);
                ull vp = *reinterpret_cast<const ull*>(vB + i * PP);
                ulonglong2 o01 = *reinterpret_cast<const ulonglong2*>(oB + i * 64);
                ulonglong2 o23 = *reinterpret_cast<const ulonglong2*>(oB + i * 64 + 4);
                ulonglong2 o45 = *reinterpret_cast<const ulonglong2*>(oB + i * 64 + 8);
                ulonglong2 o67 = *reinterpret_cast<const ulonglong2*>(oB + i * 64 + 12);
                R[0] = ffma2(hp, o01.x, R[0]); R[1] = ffma2(hp, o01.y, R[1]);
                R[2] = ffma2(hp, o23.x, R[2]); R[3] = ffma2(hp, o23.y, R[3]);
                R[4] = ffma2(hp, o45.x, R[4]); R[5] = ffma2(hp, o45.y, R[5]);
                R[6] = ffma2(hp, o67.x, R[6]); R[7] = ffma2(hp, o67.y, R[7]);
                ulonglong2 v01 = *reinterpret_cast<const ulonglong2*>(wB + i * 64);
                ulonglong2 v23 = *reinterpret_cast<const ulonglong2*>(wB + i * 64 + 4);
                ulonglong2 v45 = *reinterpret_cast<const ulonglong2*>(wB + i * 64 + 8);
                ulonglong2 v67 = *reinterpret_cast<const ulonglong2*>(wB + i * 64 + 12);
                R[0] = ffma2(vp, v01.x, R[0]); R[1] = ffma2(vp, v01.y, R[1]);
                R[2] = ffma2(vp, v23.x, R[2]); R[3] = ffma2(vp, v23.y, R[3]);
                R[4] = ffma2(vp, v45.x, R[4]); R[5] = ffma2(vp, v45.y, R[5]);
                R[6] = ffma2(vp, v67.x, R[6]); R[7] = ffma2(vp, v67.y, R[7]);
            }
            #pragma unroll
            for (int j = 0; j < 8; j++) rowv[j] = hadd2(R[j]);
        }
        float corr[8];
        if (wrM && vbzero && s2_kh == 0) {
            float4 dmv = *reinterpret_cast<float4*>(sm + OFF_DLM4 + cur * 256 + s2_m * 4);
            #pragma unroll
            for (int j = 0; j < 8; j++) {
                int h = s2_h0 + j;
                corr[j] = dmv.x * sm[OFF_TVV + h]
                        + dmv.y * sm[OFF_TVV + 32 + h]
                        + dmv.z * sm[OFF_TVV + 64 + h];
            }
        }
        if (s2_kh) {
            float* sc = sm + OFF_SCR + s2_m * SCP + s2_h0;
            *reinterpret_cast<float4*>(sc)     = make_float4(rowv[0], rowv[1], rowv[2], rowv[3]);
            *reinterpret_cast<float4*>(sc + 4) = make_float4(rowv[4], rowv[5], rowv[6], rowv[7]);
        }
        __syncthreads();
        if (s2_kh == 0) {
            const float* sc = sm + OFF_SCR + s2_m * SCP + s2_h0;
            float4 r0 = *reinterpret_cast<const float4*>(sc);
            float4 r1 = *reinterpret_cast<const float4*>(sc + 4);
            rowv[0] += r0.x; rowv[1] += r0.y; rowv[2] += r0.z; rowv[3] += r0.w;
            rowv[4] += r1.x; rowv[5] += r1.y; rowv[6] += r1.z; rowv[7] += r1.w;
            const size_t bh = (size_t)b * HDIM;
            #pragma unroll
            for (int j = 0; j < 8; j++) {
                int h = s2_h0 + j;
                float v = rowv[j] + sm[OFF_B2 + h];
                out[((bh + h) * NTOT + rowi) * NTOT + j0 + s2_m] = v;
                if (wrM && vbzero)
                    out[((bh + h) * NTOT + (j0 + s2_m)) * NTOT + rowi] = v - corr[j];
            }
        }

        if (wrM && !vbzero) {
            float dp[8];
            {
                float4 dmv = *reinterpret_cast<float4*>(sm + OFF_DLM4 + cur * 256 + s2_m * 4);
                const float* vB = sm + OFF_VP1 + s2_kh * 32 * PP + 2 * s2_m;
                const float* wB = sm + OFF_VW2 + s2_kh * 2048 + 2 * s2_h0;
                ull D[8];
                #pragma unroll
                for (int j = 0; j < 8; j++) D[j] = 0ull;
                for (int i = 0; i < 32; i++) {
                    int kp = s2_kh * 32 + i;
                    float2 w0 = *reinterpret_cast<float2*>(sm + OFF_VW1 + 2 * kp);
                    float2 w1 = *reinterpret_cast<float2*>(sm + OFF_VW1 + 128 + 2 * kp);
                    float2 w2 = *reinterpret_cast<float2*>(sm + OFF_VW1 + 256 + 2 * kp);
                    float2 vb = *reinterpret_cast<float2*>(sm + OFF_VB1 + 2 * kp);
                    float sx = dmv.x * w0.x + dmv.y * w1.x + dmv.z * w2.x + vb.x;
                    float sy = dmv.x * w0.y + dmv.y * w1.y + dmv.z * w2.y + vb.y;
                    float2 pv = u2f2(*reinterpret_cast<const ull*>(vB + i * PP));
                    ull dq = f2pack(fast_gelu(2.0f * vb.x - sx) - pv.x,
                                    fast_gelu(2.0f * vb.y - sy) - pv.y);
                    ulonglong2 v01 = *reinterpret_cast<const ulonglong2*>(wB + i * 64);
                    ulonglong2 v23 = *reinterpret_cast<const ulonglong2*>(wB + i * 64 + 4);
                    ulonglong2 v45 = *reinterpret_cast<const ulonglong2*>(wB + i * 64 + 8);
                    ulonglong2 v67 = *reinterpret_cast<const ulonglong2*>(wB + i * 64 + 12);
                    D[0] = ffma2(dq, v01.x, D[0]); D[1] = ffma2(dq, v01.y, D[1]);
                    D[2] = ffma2(dq, v23.x, D[2]); D[3] = ffma2(dq, v23.y, D[3]);
                    D[4] = ffma2(dq, v45.x, D[4]); D[5] = ffma2(dq, v45.y, D[5]);
                    D[6] = ffma2(dq, v67.x, D[6]); D[7] = ffma2(dq, v67.y, D[7]);
                }
                #pragma unroll
                for (int j = 0; j < 8; j++) dp[j] = hadd2(D[j]);
            }
            __syncthreads();
            if (s2_kh) {
                float* sc = sm + OFF_SCR + s2_m * SCP + s2_h0;
                *reinterpret_cast<float4*>(sc)     = make_float4(dp[0], dp[1], dp[2], dp[3]);
                *reinterpret_cast<float4*>(sc + 4) = make_float4(dp[4], dp[5], dp[6], dp[7]);
            }
            __syncthreads();
            if (s2_kh == 0) {
                const float* sc = sm + OFF_SCR + s2_m * SCP + s2_h0;
                float4 r0 = *reinterpret_cast<const float4*>(sc);
                float4 r1 = *reinterpret_cast<const float4*>(sc + 4);
                dp[0] += r0.x; dp[1] += r0.y; dp[2] += r0.z; dp[3] += r0.w;
                dp[4] += r1.x; dp[5] += r1.y; dp[6] += r1.z; dp[7] += r1.w;
                const size_t bh = (size_t)b * HDIM;
                #pragma unroll
                for (int j = 0; j < 8; j++) {
                    int h = s2_h0 + j;
                    float v = rowv[j] + dp[j] + sm[OFF_B2 + h];
                    out[((bh + h) * NTOT + (j0 + s2_m)) * NTOT + rowi] = v;
                }
            }
        }
        cur ^= 1;
    }
}

extern "C" void kernel_launch(void* const* d_in, const int* in_sizes, int n_in,
                              void* d_out, int out_size) {
    const float* pos    = (const float*)d_in[0];
    const int*   etype  = (const int*)d_in[1];
    const float* means  = (const float*)d_in[3];
    const float* stds   = (const float*)d_in[4];
    const float* mul_w  = (const float*)d_in[5];
    const float* bias_w = (const float*)d_in[6];
    const float* ow1    = (const float*)d_in[7];
    const float* ob1    = (const float*)d_in[8];
    const float* ow2    = (const float*)d_in[9];
    const float* ob2    = (const float*)d_in[10];
    const float* vw1    = (const float*)d_in[11];
    const float* vb1    = (const float*)d_in[12];
    const float* vw2    = (const float*)d_in[13];
    const float* vb2    = (const float*)d_in[14];
    float* out = (float*)d_out;
    int nE = in_sizes[5];

    cudaFuncSetAttribute(build_tab_kernel,
                         cudaFuncAttributeMaxDynamicSharedMemorySize, SMEM_BYTES);
    cudaFuncSetAttribute(fast_tab_kernel,
                         cudaFuncAttributeMaxDynamicSharedMemorySize, FSMEM_BYTES);
    cudaFuncSetAttribute(fused_distbias_kernel,
                         cudaFuncAttributeMaxDynamicSharedMemorySize, SMEM_BYTES);

    build_tab_kernel<<<GRIDX, 512, SMEM_BYTES>>>(
        mul_w, bias_w, means, stds, ow1, ob1, ow2, vb1, vw1, vw2, nE);

    fast_tab_kernel<<<GRIDF, 512, FSMEM_BYTES>>>(
        pos, mul_w, bias_w, ob2, vw1, vw2, vb2, out);

    mirror_transpose_kernel<<<NTT_TOTAL, 256>>>(pos, out);

    fused_distbias_kernel<<<GRIDX, 512, SMEM_BYTES>>>(
        pos, etype, mul_w, bias_w, means, stds,
        ow1, ob1, ow2, ob2, vw1, vb1, vw2, vb2, out);
}